// round 1
// baseline (speedup 1.0000x reference)
#include <cuda_runtime.h>
#include <cuda_bf16.h>
#include <math.h>

// ---------------- problem constants ----------------
#define N_USER 50000
#define N_REPO 100000
#define NE     1000000
#define NEP    200000
#define D_IN   256
#define D_EMB  125
#define D_HID  96
#define D_OUT  64

// ---------------- scratch (device globals; no runtime alloc) ----------------
__device__ float g_h_user[N_USER * D_EMB];      // 25 MB
__device__ float g_h_repo[N_REPO * D_EMB];      // 50 MB
__device__ float g_feat_r[N_REPO * D_HID];      // 38.4 MB (layer2 reuse @64)
__device__ float g_feat_u[N_USER * D_HID];      // 19.2 MB
__device__ float g_agg_u [N_USER * D_HID];      // 19.2 MB (layer2 reuse @64)
__device__ float g_agg_r [N_REPO * D_HID];      // 38.4 MB
__device__ float g_out_user[N_USER * D_HID];    // 19.2 MB
__device__ float g_out_repo[N_REPO * D_HID];    // 38.4 MB
__device__ float g_new_user[N_USER * D_OUT];    // 12.8 MB
__device__ float g_new_repo[N_REPO * D_OUT];    // 25.6 MB

__device__ int   g_cnt_u_out[N_USER];   // out-deg of user in e_ur
__device__ int   g_cnt_u_in [N_USER];   // in-deg of user in e_ru
__device__ int   g_cnt_r_out[N_REPO];   // out-deg of repo in e_ru
__device__ int   g_cnt_r_in [N_REPO];   // in-deg of repo in e_ur
__device__ float g_rs_u_out[N_USER], g_rs_u_in[N_USER];
__device__ float g_rs_r_out[N_REPO], g_rs_r_in[N_REPO];

__device__ int g_rowptr_ur[N_REPO + 1]; // CSR by dst=repo (edges e_ur)
__device__ int g_rowptr_ru[N_USER + 1]; // CSR by dst=user (edges e_ru)
__device__ int g_cursor_ur[N_REPO];
__device__ int g_cursor_ru[N_USER];
__device__ int g_col_ur[NE];            // src user ids
__device__ int g_col_ru[NE];            // src repo ids

__device__ float g_invn_u[N_USER];
__device__ float g_invn_r[N_REPO];

// ---------------- small utility kernels ----------------
__global__ void k_zero_int(int* p, int n) {
    int i = blockIdx.x * blockDim.x + threadIdx.x;
    for (; i < n; i += gridDim.x * blockDim.x) p[i] = 0;
}

__global__ void k_count_deg(const int* __restrict__ src, const int* __restrict__ dst,
                            int* cnt_src, int* cnt_dst, int n) {
    int i = blockIdx.x * blockDim.x + threadIdx.x;
    if (i < n) {
        atomicAdd(&cnt_src[src[i]], 1);
        atomicAdd(&cnt_dst[dst[i]], 1);
    }
}

__global__ void k_rsqrt_deg(const int* __restrict__ cnt, float* rs, int n) {
    int i = blockIdx.x * blockDim.x + threadIdx.x;
    if (i < n) rs[i] = rsqrtf(fmaxf((float)cnt[i], 1.0f));
}

// single-block exclusive-scan producing rowptr (rowptr[0]=0, rowptr[i+1]=incl[i])
__global__ void k_scan(const int* __restrict__ cnt, int* rowptr, int n) {
    __shared__ int sh[1024];
    __shared__ int carry;
    int t = threadIdx.x;
    if (t == 0) carry = 0;
    __syncthreads();
    for (int base = 0; base < n; base += 1024) {
        int v = (base + t < n) ? cnt[base + t] : 0;
        sh[t] = v;
        __syncthreads();
        for (int off = 1; off < 1024; off <<= 1) {
            int x = (t >= off) ? sh[t - off] : 0;
            __syncthreads();
            sh[t] += x;
            __syncthreads();
        }
        if (base + t < n) rowptr[base + t + 1] = carry + sh[t];
        __syncthreads();
        if (t == 1023) carry += sh[1023];
        __syncthreads();
    }
    if (t == 0) rowptr[0] = 0;
}

__global__ void k_copy_int(const int* __restrict__ a, int* b, int n) {
    int i = blockIdx.x * blockDim.x + threadIdx.x;
    if (i < n) b[i] = a[i];
}

__global__ void k_csr_fill(const int* __restrict__ src, const int* __restrict__ dst,
                           int* cursor, int* col, int n) {
    int i = blockIdx.x * blockDim.x + threadIdx.x;
    if (i < n) {
        int p = atomicAdd(&cursor[dst[i]], 1);
        col[p] = src[i];
    }
}

// ---------------- GEMM: C = [relu]( (A ∘ scaleA) @ W + bias1 + bias2 + addMat ∘ addScale ) ----------------
#define TM 64
#define TN 64
#define TKK 16
__global__ __launch_bounds__(256) void k_gemm(
    const float* __restrict__ A, const float* __restrict__ W, float* __restrict__ C,
    int M, int N, int K,
    const float* __restrict__ scaleA,   // [M] or null (row pre-scale of A)
    const float* __restrict__ bias1,    // [N] or null
    const float* __restrict__ bias2,    // [N] or null
    const float* __restrict__ addMat,   // [M,N] or null
    const float* __restrict__ addScale, // [M] or null (row scale of addMat)
    int relu)
{
    __shared__ float As[TKK][TM + 4];
    __shared__ float Ws[TKK][TN];
    const int m0 = blockIdx.y * TM;
    const int n0 = blockIdx.x * TN;
    const int tid = threadIdx.x;
    const int tx = tid & 15, ty = tid >> 4;
    float acc[4][4] = {};

    for (int k0 = 0; k0 < K; k0 += TKK) {
        // load A tile (coalesced along K)
        #pragma unroll
        for (int i = 0; i < 4; i++) {
            int idx = tid + 256 * i;
            int kk = idx & 15, mm = idx >> 4;
            int m = m0 + mm, k = k0 + kk;
            float v = 0.f;
            if (m < M && k < K) {
                v = A[(long)m * K + k];
                if (scaleA) v *= scaleA[m];
            }
            As[kk][mm] = v;
        }
        // load W tile (coalesced along N)
        #pragma unroll
        for (int i = 0; i < 4; i++) {
            int idx = tid + 256 * i;
            int nn = idx & 63, kk = idx >> 6;
            int k = k0 + kk, n = n0 + nn;
            Ws[kk][nn] = (k < K && n < N) ? W[(long)k * N + n] : 0.f;
        }
        __syncthreads();
        #pragma unroll
        for (int kk = 0; kk < TKK; kk++) {
            float a[4], b[4];
            #pragma unroll
            for (int i = 0; i < 4; i++) a[i] = As[kk][ty * 4 + i];
            #pragma unroll
            for (int j = 0; j < 4; j++) b[j] = Ws[kk][tx * 4 + j];
            #pragma unroll
            for (int i = 0; i < 4; i++)
                #pragma unroll
                for (int j = 0; j < 4; j++)
                    acc[i][j] += a[i] * b[j];
        }
        __syncthreads();
    }

    #pragma unroll
    for (int i = 0; i < 4; i++) {
        int m = m0 + ty * 4 + i;
        if (m >= M) continue;
        float asc = addScale ? addScale[m] : 1.f;
        #pragma unroll
        for (int j = 0; j < 4; j++) {
            int n = n0 + tx * 4 + j;
            if (n >= N) continue;
            float v = acc[i][j];
            if (bias1) v += bias1[n];
            if (bias2) v += bias2[n];
            if (addMat) v += addMat[(long)m * N + n] * asc;
            if (relu)  v = fmaxf(v, 0.f);
            C[(long)m * N + n] = v;
        }
    }
}

// ---------------- SpMM: out[r,:] = sum_{e in row r} feat[col[e],:]  (warp per row) ----------------
__global__ void k_spmm(const float* __restrict__ feat, const int* __restrict__ rowptr,
                       const int* __restrict__ col, float* __restrict__ out,
                       int n_rows, int D)
{
    int warp = (blockIdx.x * blockDim.x + threadIdx.x) >> 5;
    int lane = threadIdx.x & 31;
    if (warp >= n_rows) return;
    int s = rowptr[warp], e = rowptr[warp + 1];
    float a0 = 0.f, a1 = 0.f, a2 = 0.f;
    for (int i = s; i < e; i++) {
        int src = col[i];
        const float* f = feat + (long)src * D;
        a0 += f[lane];
        if (D > 32) a1 += f[lane + 32];
        if (D > 64) a2 += f[lane + 64];
    }
    float* o = out + (long)warp * D;
    o[lane] = a0;
    if (D > 32) o[lane + 32] = a1;
    if (D > 64) o[lane + 64] = a2;
}

// ---------------- normalize + score ----------------
__global__ void k_invnorm(const float* __restrict__ x, float* invn, int n) {
    int warp = (blockIdx.x * blockDim.x + threadIdx.x) >> 5;
    int lane = threadIdx.x & 31;
    if (warp >= n) return;
    const float* h = x + (long)warp * D_OUT;
    float v0 = h[lane], v1 = h[lane + 32];
    float s = v0 * v0 + v1 * v1;
    #pragma unroll
    for (int off = 16; off; off >>= 1) s += __shfl_xor_sync(0xffffffffu, s, off);
    if (lane == 0) invn[warp] = 1.0f / fmaxf(sqrtf(s), 1e-12f);
}

__global__ void k_score(const float* __restrict__ hu, const float* __restrict__ hr,
                        const float* __restrict__ invn_u, const float* __restrict__ invn_r,
                        const int* __restrict__ iu, const int* __restrict__ ir,
                        float* __restrict__ out, int n)
{
    int warp = (blockIdx.x * blockDim.x + threadIdx.x) >> 5;
    int lane = threadIdx.x & 31;
    if (warp >= n) return;
    int u = iu[warp], r = ir[warp];
    const float* a = hu + (long)u * D_OUT;
    const float* b = hr + (long)r * D_OUT;
    float s = a[lane] * b[lane] + a[lane + 32] * b[lane + 32];
    #pragma unroll
    for (int off = 16; off; off >>= 1) s += __shfl_xor_sync(0xffffffffu, s, off);
    if (lane == 0) out[warp] = s * invn_u[u] * invn_r[r];
}

// ---------------- host helpers ----------------
static inline void* sym(const void* s) {
    void* p = nullptr;
    cudaGetSymbolAddress(&p, s);
    return p;
}

extern "C" void kernel_launch(void* const* d_in, const int* in_sizes, int n_in,
                              void* d_out, int out_size) {
    // inputs in setup_inputs() order
    const float* user_feat = (const float*)d_in[0];
    const float* repo_feat = (const float*)d_in[1];
    const float* W_ue = (const float*)d_in[2];   const float* b_ue = (const float*)d_in[3];
    const float* W_re = (const float*)d_in[4];   const float* b_re = (const float*)d_in[5];
    const float* W_hid_ur = (const float*)d_in[6];  const float* b_hid_ur = (const float*)d_in[7];
    const float* W_hid_ru = (const float*)d_in[8];  const float* b_hid_ru = (const float*)d_in[9];
    const float* W_out_ur = (const float*)d_in[10]; const float* b_out_ur = (const float*)d_in[11];
    const float* W_out_ru = (const float*)d_in[12]; const float* b_out_ru = (const float*)d_in[13];
    const float* W_hcu = (const float*)d_in[14]; const float* b_hcu = (const float*)d_in[15];
    const float* W_hcr = (const float*)d_in[16]; const float* b_hcr = (const float*)d_in[17];
    const float* W_ocu = (const float*)d_in[18]; const float* b_ocu = (const float*)d_in[19];
    const float* W_ocr = (const float*)d_in[20]; const float* b_ocr = (const float*)d_in[21];
    const int* e_ur_src = (const int*)d_in[22];
    const int* e_ur_dst = (const int*)d_in[23];
    const int* e_ru_src = (const int*)d_in[24];
    const int* e_ru_dst = (const int*)d_in[25];
    const int* pos_u = (const int*)d_in[26];
    const int* pos_r = (const int*)d_in[27];
    const int* neg_u = (const int*)d_in[28];
    const int* neg_r = (const int*)d_in[29];
    float* out = (float*)d_out;

    // scratch addresses
    float* h_user = (float*)sym(g_h_user);
    float* h_repo = (float*)sym(g_h_repo);
    float* feat_r = (float*)sym(g_feat_r);
    float* feat_u = (float*)sym(g_feat_u);
    float* agg_u  = (float*)sym(g_agg_u);
    float* agg_r  = (float*)sym(g_agg_r);
    float* out_user = (float*)sym(g_out_user);
    float* out_repo = (float*)sym(g_out_repo);
    float* new_user = (float*)sym(g_new_user);
    float* new_repo = (float*)sym(g_new_repo);
    int* cnt_u_out = (int*)sym(g_cnt_u_out);
    int* cnt_u_in  = (int*)sym(g_cnt_u_in);
    int* cnt_r_out = (int*)sym(g_cnt_r_out);
    int* cnt_r_in  = (int*)sym(g_cnt_r_in);
    float* rs_u_out = (float*)sym(g_rs_u_out);
    float* rs_u_in  = (float*)sym(g_rs_u_in);
    float* rs_r_out = (float*)sym(g_rs_r_out);
    float* rs_r_in  = (float*)sym(g_rs_r_in);
    int* rowptr_ur = (int*)sym(g_rowptr_ur);
    int* rowptr_ru = (int*)sym(g_rowptr_ru);
    int* cursor_ur = (int*)sym(g_cursor_ur);
    int* cursor_ru = (int*)sym(g_cursor_ru);
    int* col_ur = (int*)sym(g_col_ur);
    int* col_ru = (int*)sym(g_col_ru);
    float* invn_u = (float*)sym(g_invn_u);
    float* invn_r = (float*)sym(g_invn_r);

    const int T = 256;
    auto blocks = [](int n, int t) { return (n + t - 1) / t; };

    // ---- graph structure (degrees + CSR) ----
    k_zero_int<<<blocks(N_USER, T), T>>>(cnt_u_out, N_USER);
    k_zero_int<<<blocks(N_USER, T), T>>>(cnt_u_in, N_USER);
    k_zero_int<<<blocks(N_REPO, T), T>>>(cnt_r_out, N_REPO);
    k_zero_int<<<blocks(N_REPO, T), T>>>(cnt_r_in, N_REPO);
    k_count_deg<<<blocks(NE, T), T>>>(e_ur_src, e_ur_dst, cnt_u_out, cnt_r_in, NE);
    k_count_deg<<<blocks(NE, T), T>>>(e_ru_src, e_ru_dst, cnt_r_out, cnt_u_in, NE);
    k_rsqrt_deg<<<blocks(N_USER, T), T>>>(cnt_u_out, rs_u_out, N_USER);
    k_rsqrt_deg<<<blocks(N_USER, T), T>>>(cnt_u_in, rs_u_in, N_USER);
    k_rsqrt_deg<<<blocks(N_REPO, T), T>>>(cnt_r_out, rs_r_out, N_REPO);
    k_rsqrt_deg<<<blocks(N_REPO, T), T>>>(cnt_r_in, rs_r_in, N_REPO);
    k_scan<<<1, 1024>>>(cnt_r_in, rowptr_ur, N_REPO);
    k_scan<<<1, 1024>>>(cnt_u_in, rowptr_ru, N_USER);
    k_copy_int<<<blocks(N_REPO, T), T>>>(rowptr_ur, cursor_ur, N_REPO);
    k_copy_int<<<blocks(N_USER, T), T>>>(rowptr_ru, cursor_ru, N_USER);
    k_csr_fill<<<blocks(NE, T), T>>>(e_ur_src, e_ur_dst, cursor_ur, col_ur, NE);
    k_csr_fill<<<blocks(NE, T), T>>>(e_ru_src, e_ru_dst, cursor_ru, col_ru, NE);

    dim3 tb(256);
    auto grid = [](int M, int N) { return dim3((N + TN - 1) / TN, (M + TM - 1) / TM); };

    // ---- embedding GEMMs ----
    k_gemm<<<grid(N_USER, D_EMB), tb>>>(user_feat, W_ue, h_user, N_USER, D_EMB, D_IN,
                                        nullptr, b_ue, nullptr, nullptr, nullptr, 0);
    k_gemm<<<grid(N_REPO, D_EMB), tb>>>(repo_feat, W_re, h_repo, N_REPO, D_EMB, D_IN,
                                        nullptr, b_re, nullptr, nullptr, nullptr, 0);

    // ---- layer 1: message features + aggregation ----
    k_gemm<<<grid(N_REPO, D_HID), tb>>>(h_repo, W_hid_ru, feat_r, N_REPO, D_HID, D_EMB,
                                        rs_r_out, nullptr, nullptr, nullptr, nullptr, 0);
    k_gemm<<<grid(N_USER, D_HID), tb>>>(h_user, W_hid_ur, feat_u, N_USER, D_HID, D_EMB,
                                        rs_u_out, nullptr, nullptr, nullptr, nullptr, 0);
    k_spmm<<<blocks(N_USER * 32, T), T>>>(feat_r, rowptr_ru, col_ru, agg_u, N_USER, D_HID);
    k_spmm<<<blocks(N_REPO * 32, T), T>>>(feat_u, rowptr_ur, col_ur, agg_r, N_REPO, D_HID);

    // out_user = relu(h_user@W_hcu + b_hcu + b_hid_ru + agg_u*rs_u_in)
    k_gemm<<<grid(N_USER, D_HID), tb>>>(h_user, W_hcu, out_user, N_USER, D_HID, D_EMB,
                                        nullptr, b_hcu, b_hid_ru, agg_u, rs_u_in, 1);
    k_gemm<<<grid(N_REPO, D_HID), tb>>>(h_repo, W_hcr, out_repo, N_REPO, D_HID, D_EMB,
                                        nullptr, b_hcr, b_hid_ur, agg_r, rs_r_in, 1);

    // ---- layer 2 (reuse feat/agg buffers at D=64) ----
    k_gemm<<<grid(N_REPO, D_OUT), tb>>>(out_repo, W_out_ru, feat_r, N_REPO, D_OUT, D_HID,
                                        rs_r_out, nullptr, nullptr, nullptr, nullptr, 0);
    k_gemm<<<grid(N_USER, D_OUT), tb>>>(out_user, W_out_ur, feat_u, N_USER, D_OUT, D_HID,
                                        rs_u_out, nullptr, nullptr, nullptr, nullptr, 0);
    k_spmm<<<blocks(N_USER * 32, T), T>>>(feat_r, rowptr_ru, col_ru, agg_u, N_USER, D_OUT);
    k_spmm<<<blocks(N_REPO * 32, T), T>>>(feat_u, rowptr_ur, col_ur, agg_r, N_REPO, D_OUT);

    k_gemm<<<grid(N_USER, D_OUT), tb>>>(out_user, W_ocu, new_user, N_USER, D_OUT, D_HID,
                                        nullptr, b_ocu, b_out_ru, agg_u, rs_u_in, 1);
    k_gemm<<<grid(N_REPO, D_OUT), tb>>>(out_repo, W_ocr, new_repo, N_REPO, D_OUT, D_HID,
                                        nullptr, b_ocr, b_out_ur, agg_r, rs_r_in, 1);

    // ---- cosine scores ----
    k_invnorm<<<blocks(N_USER * 32, T), T>>>(new_user, invn_u, N_USER);
    k_invnorm<<<blocks(N_REPO * 32, T), T>>>(new_repo, invn_r, N_REPO);
    k_score<<<blocks(NEP * 32, T), T>>>(new_user, new_repo, invn_u, invn_r,
                                        pos_u, pos_r, out, NEP);
    k_score<<<blocks(NEP * 32, T), T>>>(new_user, new_repo, invn_u, invn_r,
                                        neg_u, neg_r, out + NEP, NEP);
}

// round 2
// speedup vs baseline: 1.2899x; 1.2899x over previous
#include <cuda_runtime.h>
#include <cuda_bf16.h>
#include <math.h>

// ---------------- problem constants ----------------
#define N_USER 50000
#define N_REPO 100000
#define NE     1000000
#define NEP    200000
#define D_IN   256
#define D_EMB  125
#define D_HID  96
#define D_OUT  64

// ---------------- scratch (device globals; no runtime alloc) ----------------
__device__ float g_h_user[N_USER * D_EMB];
__device__ float g_h_repo[N_REPO * D_EMB];
__device__ float g_feat_r[N_REPO * D_HID];
__device__ float g_feat_u[N_USER * D_HID];
__device__ float g_agg_u [N_USER * D_HID];
__device__ float g_agg_r [N_REPO * D_HID];
__device__ float g_out_user[N_USER * D_HID];
__device__ float g_out_repo[N_REPO * D_HID];
__device__ float g_new_user[N_USER * D_OUT];
__device__ float g_new_repo[N_REPO * D_OUT];

__device__ int   g_cnt_u_out[N_USER];
__device__ int   g_cnt_u_in [N_USER];
__device__ int   g_cnt_r_out[N_REPO];
__device__ int   g_cnt_r_in [N_REPO];
__device__ float g_rs_u_out[N_USER], g_rs_u_in[N_USER];
__device__ float g_rs_r_out[N_REPO], g_rs_r_in[N_REPO];

__device__ int g_rowptr_ur[N_REPO + 1];
__device__ int g_rowptr_ru[N_USER + 1];
__device__ int g_cursor_ur[N_REPO];
__device__ int g_cursor_ru[N_USER];
__device__ int g_col_ur[NE];
__device__ int g_col_ru[NE];
__device__ int g_part[128];

__device__ float g_invn_u[N_USER];
__device__ float g_invn_r[N_REPO];

// ---------------- small utility kernels ----------------
__global__ void k_count_deg(const int* __restrict__ src, const int* __restrict__ dst,
                            int* cnt_src, int* cnt_dst, int n) {
    int i = blockIdx.x * blockDim.x + threadIdx.x;
    if (i < n) {
        atomicAdd(&cnt_src[src[i]], 1);
        atomicAdd(&cnt_dst[dst[i]], 1);
    }
}

__global__ void k_rsqrt_deg(const int* __restrict__ cnt, float* rs, int n) {
    int i = blockIdx.x * blockDim.x + threadIdx.x;
    if (i < n) rs[i] = rsqrtf(fmaxf((float)cnt[i], 1.0f));
}

// ---- 3-phase multi-block scan ----
__global__ void k_scan_block(const int* __restrict__ cnt, int* rowptr, int* partial, int n) {
    __shared__ int sh[1024];
    int b = blockIdx.x, t = threadIdx.x;
    int i = b * 1024 + t;
    int v = (i < n) ? cnt[i] : 0;
    sh[t] = v;
    __syncthreads();
    for (int off = 1; off < 1024; off <<= 1) {
        int x = (t >= off) ? sh[t - off] : 0;
        __syncthreads();
        sh[t] += x;
        __syncthreads();
    }
    if (i < n) rowptr[i + 1] = sh[t];
    if (t == 1023) partial[b] = sh[1023];
}

__global__ void k_scan_part(int* partial, int nb) {
    __shared__ int sh[128];
    int t = threadIdx.x;
    int v = (t < nb) ? partial[t] : 0;
    sh[t] = v;
    __syncthreads();
    for (int off = 1; off < 128; off <<= 1) {
        int x = (t >= off) ? sh[t - off] : 0;
        __syncthreads();
        sh[t] += x;
        __syncthreads();
    }
    if (t < nb) partial[t] = sh[t] - v;  // exclusive
}

__global__ void k_scan_add(int* rowptr, const int* __restrict__ partial, int n) {
    int i = blockIdx.x * blockDim.x + threadIdx.x;
    if (i == 0) rowptr[0] = 0;
    if (i < n) rowptr[i + 1] += partial[i >> 10];
}

__global__ void k_copy_int(const int* __restrict__ a, int* b, int n) {
    int i = blockIdx.x * blockDim.x + threadIdx.x;
    if (i < n) b[i] = a[i];
}

__global__ void k_csr_fill(const int* __restrict__ src, const int* __restrict__ dst,
                           int* cursor, int* col, int n) {
    int i = blockIdx.x * blockDim.x + threadIdx.x;
    if (i < n) {
        int p = atomicAdd(&cursor[dst[i]], 1);
        col[p] = src[i];
    }
}

// ---------------- tf32 tensor-core GEMM ----------------
// C = [relu]( (A ∘ scaleA) @ W + bias1 + bias2 + addMat ∘ addScale )
#define BM 128
#define BN 64
#define BK 32
#define ASTRIDE 136   // ≡ 8 (mod 32) → conflict-free fragment loads
#define WSTRIDE 72    // ≡ 8 (mod 32)

__device__ __forceinline__ float to_tf32(float x) {
    float y;
    asm("cvt.rna.tf32.f32 %0, %1;" : "=f"(y) : "f"(x));
    return y;
}

__device__ __forceinline__ void mma_tf32(float c[4],
                                         unsigned a0, unsigned a1, unsigned a2, unsigned a3,
                                         unsigned b0, unsigned b1) {
    asm volatile(
        "mma.sync.aligned.m16n8k8.row.col.f32.tf32.tf32.f32 "
        "{%0,%1,%2,%3}, {%4,%5,%6,%7}, {%8,%9}, {%0,%1,%2,%3};"
        : "+f"(c[0]), "+f"(c[1]), "+f"(c[2]), "+f"(c[3])
        : "r"(a0), "r"(a1), "r"(a2), "r"(a3), "r"(b0), "r"(b1));
}

__global__ __launch_bounds__(128) void k_gemm_tc(
    const float* __restrict__ A, const float* __restrict__ W, float* __restrict__ C,
    int M, int N, int K,
    const float* __restrict__ scaleA,
    const float* __restrict__ bias1,
    const float* __restrict__ bias2,
    const float* __restrict__ addMat,
    const float* __restrict__ addScale,
    int relu)
{
    __shared__ float As[BK][ASTRIDE];
    __shared__ float Ws[BK][WSTRIDE];

    const int tid = threadIdx.x;
    const int warp = tid >> 5, lane = tid & 31;
    const int wm = (warp >> 1) * 64;   // warp tile 64x32
    const int wn = (warp & 1) * 32;
    const int m0 = blockIdx.y * BM;
    const int n0 = blockIdx.x * BN;
    const int r = lane >> 2;       // group id 0..7
    const int kc = lane & 3;       // thread-in-group 0..3

    float acc[4][4][4];
    #pragma unroll
    for (int a = 0; a < 4; a++)
        #pragma unroll
        for (int b = 0; b < 4; b++)
            #pragma unroll
            for (int c = 0; c < 4; c++) acc[a][b][c] = 0.f;

    for (int k0 = 0; k0 < K; k0 += BK) {
        // ---- stage A tile: BM x BK ----
        #pragma unroll
        for (int p = 0; p < 8; p++) {
            int row = (tid >> 3) + p * 16;
            int m = m0 + row;
            float sA = 1.f;
            if (scaleA && m < M) sA = scaleA[m];
            #pragma unroll
            for (int j = 0; j < 4; j++) {
                int kk = ((tid & 7) << 2) + j;
                int k = k0 + kk;
                float v = 0.f;
                if (m < M && k < K) v = A[(size_t)m * K + k] * sA;
                As[kk][row] = to_tf32(v);
            }
        }
        // ---- stage W tile: BK x BN ----
        #pragma unroll
        for (int p = 0; p < 4; p++) {
            int kk = (tid >> 4) + p * 8;
            int k = k0 + kk;
            #pragma unroll
            for (int j = 0; j < 4; j++) {
                int n = ((tid & 15) << 2) + j;
                float v = 0.f;
                if (k < K && (n0 + n) < N) v = W[(size_t)k * N + n0 + n];
                Ws[kk][n] = to_tf32(v);
            }
        }
        __syncthreads();

        #pragma unroll
        for (int ka = 0; ka < 4; ka++) {
            int k = ka * 8;
            unsigned af[4][4];
            #pragma unroll
            for (int mt = 0; mt < 4; mt++) {
                int m = wm + mt * 16 + r;
                af[mt][0] = __float_as_uint(As[k + kc][m]);
                af[mt][1] = __float_as_uint(As[k + kc][m + 8]);
                af[mt][2] = __float_as_uint(As[k + kc + 4][m]);
                af[mt][3] = __float_as_uint(As[k + kc + 4][m + 8]);
            }
            unsigned bf[4][2];
            #pragma unroll
            for (int nt = 0; nt < 4; nt++) {
                int n = wn + nt * 8 + r;
                bf[nt][0] = __float_as_uint(Ws[k + kc][n]);
                bf[nt][1] = __float_as_uint(Ws[k + kc + 4][n]);
            }
            #pragma unroll
            for (int mt = 0; mt < 4; mt++)
                #pragma unroll
                for (int nt = 0; nt < 4; nt++)
                    mma_tf32(acc[mt][nt], af[mt][0], af[mt][1], af[mt][2], af[mt][3],
                             bf[nt][0], bf[nt][1]);
        }
        __syncthreads();
    }

    // ---- epilogue ----
    #pragma unroll
    for (int mt = 0; mt < 4; mt++) {
        #pragma unroll
        for (int i2 = 0; i2 < 2; i2++) {
            int m = m0 + wm + mt * 16 + r + i2 * 8;
            if (m >= M) continue;
            float asc = addScale ? addScale[m] : 1.f;
            #pragma unroll
            for (int nt = 0; nt < 4; nt++) {
                #pragma unroll
                for (int jj = 0; jj < 2; jj++) {
                    int n = n0 + wn + nt * 8 + kc * 2 + jj;
                    if (n >= N) continue;
                    float v = acc[mt][nt][i2 * 2 + jj];
                    if (bias1) v += bias1[n];
                    if (bias2) v += bias2[n];
                    if (addMat) v += addMat[(size_t)m * N + n] * asc;
                    if (relu)  v = fmaxf(v, 0.f);
                    C[(size_t)m * N + n] = v;
                }
            }
        }
    }
}

// ---------------- SpMM: warp per destination row ----------------
__global__ void k_spmm(const float* __restrict__ feat, const int* __restrict__ rowptr,
                       const int* __restrict__ col, float* __restrict__ out,
                       int n_rows, int D)
{
    int warp = (blockIdx.x * blockDim.x + threadIdx.x) >> 5;
    int lane = threadIdx.x & 31;
    if (warp >= n_rows) return;
    int s = rowptr[warp], e = rowptr[warp + 1];
    float a0 = 0.f, a1 = 0.f, a2 = 0.f;
    for (int i = s; i < e; i++) {
        int src = col[i];
        const float* f = feat + (size_t)src * D;
        a0 += f[lane];
        if (D > 32) a1 += f[lane + 32];
        if (D > 64) a2 += f[lane + 64];
    }
    float* o = out + (size_t)warp * D;
    o[lane] = a0;
    if (D > 32) o[lane + 32] = a1;
    if (D > 64) o[lane + 64] = a2;
}

// ---------------- normalize + score ----------------
__global__ void k_invnorm(const float* __restrict__ x, float* invn, int n) {
    int warp = (blockIdx.x * blockDim.x + threadIdx.x) >> 5;
    int lane = threadIdx.x & 31;
    if (warp >= n) return;
    const float* h = x + (size_t)warp * D_OUT;
    float v0 = h[lane], v1 = h[lane + 32];
    float s = v0 * v0 + v1 * v1;
    #pragma unroll
    for (int off = 16; off; off >>= 1) s += __shfl_xor_sync(0xffffffffu, s, off);
    if (lane == 0) invn[warp] = 1.0f / fmaxf(sqrtf(s), 1e-12f);
}

__global__ void k_score(const float* __restrict__ hu, const float* __restrict__ hr,
                        const float* __restrict__ invn_u, const float* __restrict__ invn_r,
                        const int* __restrict__ iu, const int* __restrict__ ir,
                        float* __restrict__ out, int n)
{
    int warp = (blockIdx.x * blockDim.x + threadIdx.x) >> 5;
    int lane = threadIdx.x & 31;
    if (warp >= n) return;
    int u = iu[warp], r = ir[warp];
    const float* a = hu + (size_t)u * D_OUT;
    const float* b = hr + (size_t)r * D_OUT;
    float s = a[lane] * b[lane] + a[lane + 32] * b[lane + 32];
    #pragma unroll
    for (int off = 16; off; off >>= 1) s += __shfl_xor_sync(0xffffffffu, s, off);
    if (lane == 0) out[warp] = s * invn_u[u] * invn_r[r];
}

// ---------------- host ----------------
static inline void* sym(const void* s) {
    void* p = nullptr;
    cudaGetSymbolAddress(&p, s);
    return p;
}

extern "C" void kernel_launch(void* const* d_in, const int* in_sizes, int n_in,
                              void* d_out, int out_size) {
    const float* user_feat = (const float*)d_in[0];
    const float* repo_feat = (const float*)d_in[1];
    const float* W_ue = (const float*)d_in[2];   const float* b_ue = (const float*)d_in[3];
    const float* W_re = (const float*)d_in[4];   const float* b_re = (const float*)d_in[5];
    const float* W_hid_ur = (const float*)d_in[6];  const float* b_hid_ur = (const float*)d_in[7];
    const float* W_hid_ru = (const float*)d_in[8];  const float* b_hid_ru = (const float*)d_in[9];
    const float* W_out_ur = (const float*)d_in[10]; const float* b_out_ur = (const float*)d_in[11];
    const float* W_out_ru = (const float*)d_in[12]; const float* b_out_ru = (const float*)d_in[13];
    const float* W_hcu = (const float*)d_in[14]; const float* b_hcu = (const float*)d_in[15];
    const float* W_hcr = (const float*)d_in[16]; const float* b_hcr = (const float*)d_in[17];
    const float* W_ocu = (const float*)d_in[18]; const float* b_ocu = (const float*)d_in[19];
    const float* W_ocr = (const float*)d_in[20]; const float* b_ocr = (const float*)d_in[21];
    const int* e_ur_src = (const int*)d_in[22];
    const int* e_ur_dst = (const int*)d_in[23];
    const int* e_ru_src = (const int*)d_in[24];
    const int* e_ru_dst = (const int*)d_in[25];
    const int* pos_u = (const int*)d_in[26];
    const int* pos_r = (const int*)d_in[27];
    const int* neg_u = (const int*)d_in[28];
    const int* neg_r = (const int*)d_in[29];
    float* out = (float*)d_out;

    float* h_user = (float*)sym(g_h_user);
    float* h_repo = (float*)sym(g_h_repo);
    float* feat_r = (float*)sym(g_feat_r);
    float* feat_u = (float*)sym(g_feat_u);
    float* agg_u  = (float*)sym(g_agg_u);
    float* agg_r  = (float*)sym(g_agg_r);
    float* out_user = (float*)sym(g_out_user);
    float* out_repo = (float*)sym(g_out_repo);
    float* new_user = (float*)sym(g_new_user);
    float* new_repo = (float*)sym(g_new_repo);
    int* cnt_u_out = (int*)sym(g_cnt_u_out);
    int* cnt_u_in  = (int*)sym(g_cnt_u_in);
    int* cnt_r_out = (int*)sym(g_cnt_r_out);
    int* cnt_r_in  = (int*)sym(g_cnt_r_in);
    float* rs_u_out = (float*)sym(g_rs_u_out);
    float* rs_u_in  = (float*)sym(g_rs_u_in);
    float* rs_r_out = (float*)sym(g_rs_r_out);
    float* rs_r_in  = (float*)sym(g_rs_r_in);
    int* rowptr_ur = (int*)sym(g_rowptr_ur);
    int* rowptr_ru = (int*)sym(g_rowptr_ru);
    int* cursor_ur = (int*)sym(g_cursor_ur);
    int* cursor_ru = (int*)sym(g_cursor_ru);
    int* col_ur = (int*)sym(g_col_ur);
    int* col_ru = (int*)sym(g_col_ru);
    int* part   = (int*)sym(g_part);
    float* invn_u = (float*)sym(g_invn_u);
    float* invn_r = (float*)sym(g_invn_r);

    const int T = 256;
    auto blocks = [](int n, int t) { return (n + t - 1) / t; };

    // ---- graph structure (degrees + CSR) ----
    cudaMemsetAsync(cnt_u_out, 0, N_USER * sizeof(int), 0);
    cudaMemsetAsync(cnt_u_in,  0, N_USER * sizeof(int), 0);
    cudaMemsetAsync(cnt_r_out, 0, N_REPO * sizeof(int), 0);
    cudaMemsetAsync(cnt_r_in,  0, N_REPO * sizeof(int), 0);
    k_count_deg<<<blocks(NE, T), T>>>(e_ur_src, e_ur_dst, cnt_u_out, cnt_r_in, NE);
    k_count_deg<<<blocks(NE, T), T>>>(e_ru_src, e_ru_dst, cnt_r_out, cnt_u_in, NE);
    k_rsqrt_deg<<<blocks(N_USER, T), T>>>(cnt_u_out, rs_u_out, N_USER);
    k_rsqrt_deg<<<blocks(N_USER, T), T>>>(cnt_u_in, rs_u_in, N_USER);
    k_rsqrt_deg<<<blocks(N_REPO, T), T>>>(cnt_r_out, rs_r_out, N_REPO);
    k_rsqrt_deg<<<blocks(N_REPO, T), T>>>(cnt_r_in, rs_r_in, N_REPO);

    int nb_r = (N_REPO + 1023) / 1024;
    int nb_u = (N_USER + 1023) / 1024;
    k_scan_block<<<nb_r, 1024>>>(cnt_r_in, rowptr_ur, part, N_REPO);
    k_scan_part<<<1, 128>>>(part, nb_r);
    k_scan_add<<<blocks(N_REPO, T), T>>>(rowptr_ur, part, N_REPO);
    k_scan_block<<<nb_u, 1024>>>(cnt_u_in, rowptr_ru, part, N_USER);
    k_scan_part<<<1, 128>>>(part, nb_u);
    k_scan_add<<<blocks(N_USER, T), T>>>(rowptr_ru, part, N_USER);

    k_copy_int<<<blocks(N_REPO, T), T>>>(rowptr_ur, cursor_ur, N_REPO);
    k_copy_int<<<blocks(N_USER, T), T>>>(rowptr_ru, cursor_ru, N_USER);
    k_csr_fill<<<blocks(NE, T), T>>>(e_ur_src, e_ur_dst, cursor_ur, col_ur, NE);
    k_csr_fill<<<blocks(NE, T), T>>>(e_ru_src, e_ru_dst, cursor_ru, col_ru, NE);

    dim3 tb(128);
    auto grid = [](int M, int N) { return dim3((N + BN - 1) / BN, (M + BM - 1) / BM); };

    // ---- embedding GEMMs ----
    k_gemm_tc<<<grid(N_USER, D_EMB), tb>>>(user_feat, W_ue, h_user, N_USER, D_EMB, D_IN,
                                           nullptr, b_ue, nullptr, nullptr, nullptr, 0);
    k_gemm_tc<<<grid(N_REPO, D_EMB), tb>>>(repo_feat, W_re, h_repo, N_REPO, D_EMB, D_IN,
                                           nullptr, b_re, nullptr, nullptr, nullptr, 0);

    // ---- layer 1 ----
    k_gemm_tc<<<grid(N_REPO, D_HID), tb>>>(h_repo, W_hid_ru, feat_r, N_REPO, D_HID, D_EMB,
                                           rs_r_out, nullptr, nullptr, nullptr, nullptr, 0);
    k_gemm_tc<<<grid(N_USER, D_HID), tb>>>(h_user, W_hid_ur, feat_u, N_USER, D_HID, D_EMB,
                                           rs_u_out, nullptr, nullptr, nullptr, nullptr, 0);
    k_spmm<<<blocks(N_USER * 32, T), T>>>(feat_r, rowptr_ru, col_ru, agg_u, N_USER, D_HID);
    k_spmm<<<blocks(N_REPO * 32, T), T>>>(feat_u, rowptr_ur, col_ur, agg_r, N_REPO, D_HID);

    k_gemm_tc<<<grid(N_USER, D_HID), tb>>>(h_user, W_hcu, out_user, N_USER, D_HID, D_EMB,
                                           nullptr, b_hcu, b_hid_ru, agg_u, rs_u_in, 1);
    k_gemm_tc<<<grid(N_REPO, D_HID), tb>>>(h_repo, W_hcr, out_repo, N_REPO, D_HID, D_EMB,
                                           nullptr, b_hcr, b_hid_ur, agg_r, rs_r_in, 1);

    // ---- layer 2 ----
    k_gemm_tc<<<grid(N_REPO, D_OUT), tb>>>(out_repo, W_out_ru, feat_r, N_REPO, D_OUT, D_HID,
                                           rs_r_out, nullptr, nullptr, nullptr, nullptr, 0);
    k_gemm_tc<<<grid(N_USER, D_OUT), tb>>>(out_user, W_out_ur, feat_u, N_USER, D_OUT, D_HID,
                                           rs_u_out, nullptr, nullptr, nullptr, nullptr, 0);
    k_spmm<<<blocks(N_USER * 32, T), T>>>(feat_r, rowptr_ru, col_ru, agg_u, N_USER, D_OUT);
    k_spmm<<<blocks(N_REPO * 32, T), T>>>(feat_u, rowptr_ur, col_ur, agg_r, N_REPO, D_OUT);

    k_gemm_tc<<<grid(N_USER, D_OUT), tb>>>(out_user, W_ocu, new_user, N_USER, D_OUT, D_HID,
                                           nullptr, b_ocu, b_out_ru, agg_u, rs_u_in, 1);
    k_gemm_tc<<<grid(N_REPO, D_OUT), tb>>>(out_repo, W_ocr, new_repo, N_REPO, D_OUT, D_HID,
                                           nullptr, b_ocr, b_out_ur, agg_r, rs_r_in, 1);

    // ---- cosine scores ----
    k_invnorm<<<blocks(N_USER * 32, T), T>>>(new_user, invn_u, N_USER);
    k_invnorm<<<blocks(N_REPO * 32, T), T>>>(new_repo, invn_r, N_REPO);
    k_score<<<blocks(NEP * 32, T), T>>>(new_user, new_repo, invn_u, invn_r,
                                        pos_u, pos_r, out, NEP);
    k_score<<<blocks(NEP * 32, T), T>>>(new_user, new_repo, invn_u, invn_r,
                                        neg_u, neg_r, out + NEP, NEP);
}

// round 3
// speedup vs baseline: 2.0084x; 1.5571x over previous
#include <cuda_runtime.h>
#include <cuda_bf16.h>
#include <math.h>

// ---------------- problem constants ----------------
#define N_USER 50000
#define N_REPO 100000
#define NE     1000000
#define NEP    200000
#define D_IN   256
#define D_EMB  125
#define D_EMBP 128   // padded
#define D_HID  96
#define D_OUT  64

// ---------------- scratch (device globals) ----------------
__device__ float g_h_user[N_USER * D_EMBP];
__device__ float g_h_repo[N_REPO * D_EMBP];
__device__ float g_feat_u[N_USER * D_HID];   // reused at D_OUT in layer 2
__device__ float g_feat_r[N_REPO * D_HID];
__device__ float g_raw_u [N_USER * D_HID];
__device__ float g_raw_r [N_REPO * D_HID];
__device__ float g_agg_u [N_USER * D_HID];
__device__ float g_agg_r [N_REPO * D_HID];
__device__ float g_out_user[N_USER * D_HID];
__device__ float g_out_repo[N_REPO * D_HID];
__device__ float g_new_user[N_USER * D_OUT];
__device__ float g_new_repo[N_REPO * D_OUT];

__device__ int   g_cnt_u_out[N_USER];
__device__ int   g_cnt_u_in [N_USER];
__device__ int   g_cnt_r_out[N_REPO];
__device__ int   g_cnt_r_in [N_REPO];
__device__ float g_rs_u_out[N_USER], g_rs_u_in[N_USER];
__device__ float g_rs_r_out[N_REPO], g_rs_r_in[N_REPO];

__device__ int g_rowptr_ur[N_REPO + 1];
__device__ int g_rowptr_ru[N_USER + 1];
__device__ int g_cursor_ur[N_REPO];
__device__ int g_cursor_ru[N_USER];
__device__ int g_col_ur[NE];
__device__ int g_col_ru[NE];
__device__ int g_part[128];

__device__ float g_invn_u[N_USER];
__device__ float g_invn_r[N_REPO];

// packed/padded weights
__device__ float g_wp_ue[D_IN * D_EMBP];
__device__ float g_wp_re[D_IN * D_EMBP];
__device__ float g_bp_ue[D_EMBP];
__device__ float g_bp_re[D_EMBP];
__device__ float g_wc_u1[D_EMBP * 192];   // [128][ W_hid_ur | W_hcu ]
__device__ float g_wc_r1[D_EMBP * 192];   // [128][ W_hid_ru | W_hcr ]
__device__ float g_wc_u2[D_HID * 128];    // [96][ W_out_ur | W_ocu ]
__device__ float g_wc_r2[D_HID * 128];    // [96][ W_out_ru | W_ocr ]

// ---------------- utility kernels ----------------
__global__ void k_count_deg(const int* __restrict__ src, const int* __restrict__ dst,
                            int* cnt_src, int* cnt_dst, int n) {
    int i = blockIdx.x * blockDim.x + threadIdx.x;
    if (i < n) {
        atomicAdd(&cnt_src[src[i]], 1);
        atomicAdd(&cnt_dst[dst[i]], 1);
    }
}

__global__ void k_rsqrt_deg(const int* __restrict__ cnt, float* rs, int n) {
    int i = blockIdx.x * blockDim.x + threadIdx.x;
    if (i < n) rs[i] = rsqrtf(fmaxf((float)cnt[i], 1.0f));
}

__global__ void k_scan_block(const int* __restrict__ cnt, int* rowptr, int* partial, int n) {
    __shared__ int sh[1024];
    int b = blockIdx.x, t = threadIdx.x;
    int i = b * 1024 + t;
    int v = (i < n) ? cnt[i] : 0;
    sh[t] = v;
    __syncthreads();
    for (int off = 1; off < 1024; off <<= 1) {
        int x = (t >= off) ? sh[t - off] : 0;
        __syncthreads();
        sh[t] += x;
        __syncthreads();
    }
    if (i < n) rowptr[i + 1] = sh[t];
    if (t == 1023) partial[b] = sh[1023];
}

__global__ void k_scan_part(int* partial, int nb) {
    __shared__ int sh[128];
    int t = threadIdx.x;
    int v = (t < nb) ? partial[t] : 0;
    sh[t] = v;
    __syncthreads();
    for (int off = 1; off < 128; off <<= 1) {
        int x = (t >= off) ? sh[t - off] : 0;
        __syncthreads();
        sh[t] += x;
        __syncthreads();
    }
    if (t < nb) partial[t] = sh[t] - v;
}

__global__ void k_scan_add(int* rowptr, const int* __restrict__ partial, int n) {
    int i = blockIdx.x * blockDim.x + threadIdx.x;
    if (i == 0) rowptr[0] = 0;
    if (i < n) rowptr[i + 1] += partial[i >> 10];
}

__global__ void k_copy_int(const int* __restrict__ a, int* b, int n) {
    int i = blockIdx.x * blockDim.x + threadIdx.x;
    if (i < n) b[i] = a[i];
}

__global__ void k_csr_fill(const int* __restrict__ src, const int* __restrict__ dst,
                           int* cursor, int* col, int n) {
    int i = blockIdx.x * blockDim.x + threadIdx.x;
    if (i < n) {
        int p = atomicAdd(&cursor[dst[i]], 1);
        col[p] = src[i];
    }
}

// pad/concat copy: dst[k*ldd + coloff + n] = src[k*Ns + n]; padded rows pre-zeroed by memset
__global__ void k_pack(float* dst, int ldd, int coloff, const float* __restrict__ src,
                       int Ks, int Ns) {
    int i = blockIdx.x * blockDim.x + threadIdx.x;
    if (i >= Ks * Ns) return;
    int k = i / Ns, n = i % Ns;
    dst[k * ldd + coloff + n] = src[i];
}

// ---------------- tf32 tensor-core GEMM ----------------
// C1[m, n]            = acc * outScale[m] + bias[n]   for n <  nsplit
// C2[m, n - nsplit]   = acc                           for n >= nsplit
#define BM 128
#define BN 64
#define BK 32
#define AS 40
#define WS 40

__device__ __forceinline__ float to_tf32(float x) {
    float y;
    asm("cvt.rna.tf32.f32 %0, %1;" : "=f"(y) : "f"(x));
    return y;
}

__device__ __forceinline__ void mma_tf32(float c[4],
                                         unsigned a0, unsigned a1, unsigned a2, unsigned a3,
                                         unsigned b0, unsigned b1) {
    asm volatile(
        "mma.sync.aligned.m16n8k8.row.col.f32.tf32.tf32.f32 "
        "{%0,%1,%2,%3}, {%4,%5,%6,%7}, {%8,%9}, {%0,%1,%2,%3};"
        : "+f"(c[0]), "+f"(c[1]), "+f"(c[2]), "+f"(c[3])
        : "r"(a0), "r"(a1), "r"(a2), "r"(a3), "r"(b0), "r"(b1));
}

__global__ __launch_bounds__(128) void k_gemm_tc(
    const float* __restrict__ A, const float* __restrict__ W,
    float* __restrict__ C1, int ld1, float* __restrict__ C2, int ld2, int nsplit,
    int M, int N, int K,
    const float* __restrict__ outScale, const float* __restrict__ bias)
{
    __shared__ float As_s[BM * AS];
    __shared__ float Ws_s[BN * WS];

    const int tid = threadIdx.x;
    const int warp = tid >> 5, lane = tid & 31;
    const int wm = (warp >> 1) * 64;
    const int wn = (warp & 1) * 32;
    const int m0 = blockIdx.y * BM;
    const int n0 = blockIdx.x * BN;
    const int r = lane >> 2, kc = lane & 3;

    float acc[4][4][4];
    #pragma unroll
    for (int a = 0; a < 4; a++)
        #pragma unroll
        for (int b = 0; b < 4; b++)
            #pragma unroll
            for (int c = 0; c < 4; c++) acc[a][b][c] = 0.f;

    float4 a4[8];
    float  wreg[16];

    const int am = m0 + tid;                 // this thread stages A row am
    const bool ag = am < M;
    const float* Arow = A + (size_t)am * K;

    // W staging mapping (per it in 0..3): idx = tid + it*128
    //   n = idx & 63, h = idx >> 6, p = h >> 1, hi = h & 1
    //   k offsets: {p*8+2hi, p*8+2hi+4, p*8+2hi+1, p*8+2hi+5}

    // ---- prologue: load tile 0 ----
    {
        #pragma unroll
        for (int j = 0; j < 8; j++)
            a4[j] = ag ? *(const float4*)(Arow + j * 4) : make_float4(0.f, 0.f, 0.f, 0.f);
        #pragma unroll
        for (int it = 0; it < 4; it++) {
            int idx = tid + it * 128;
            int n = idx & 63, h = idx >> 6;
            int p = h >> 1, hi = h & 1;
            const float* Wb = W + (size_t)(p * 8 + 2 * hi) * N + n0 + n;
            wreg[it * 4 + 0] = Wb[0];
            wreg[it * 4 + 1] = Wb[4 * N];
            wreg[it * 4 + 2] = Wb[1 * N];
            wreg[it * 4 + 3] = Wb[5 * N];
        }
    }

    const int T = K / BK;
    for (int t = 0; t < T; t++) {
        // ---- STS staged regs (tf32-converted, permuted layout) ----
        #pragma unroll
        for (int p = 0; p < 4; p++) {
            float4 lo = a4[2 * p], hi = a4[2 * p + 1];
            float4 q0 = make_float4(to_tf32(lo.x), to_tf32(hi.x), to_tf32(lo.y), to_tf32(hi.y));
            float4 q1 = make_float4(to_tf32(lo.z), to_tf32(hi.z), to_tf32(lo.w), to_tf32(hi.w));
            *(float4*)(As_s + tid * AS + p * 8)     = q0;
            *(float4*)(As_s + tid * AS + p * 8 + 4) = q1;
        }
        #pragma unroll
        for (int it = 0; it < 4; it++) {
            int idx = tid + it * 128;
            int n = idx & 63, h = idx >> 6;
            int p = h >> 1, hi = h & 1;
            float4 q = make_float4(to_tf32(wreg[it * 4 + 0]), to_tf32(wreg[it * 4 + 1]),
                                   to_tf32(wreg[it * 4 + 2]), to_tf32(wreg[it * 4 + 3]));
            *(float4*)(Ws_s + n * WS + p * 8 + hi * 4) = q;
        }
        __syncthreads();

        // ---- prefetch next tile into regs (overlaps with compute) ----
        if (t + 1 < T) {
            int k0 = (t + 1) * BK;
            #pragma unroll
            for (int j = 0; j < 8; j++)
                a4[j] = ag ? *(const float4*)(Arow + k0 + j * 4) : make_float4(0.f, 0.f, 0.f, 0.f);
            #pragma unroll
            for (int it = 0; it < 4; it++) {
                int idx = tid + it * 128;
                int n = idx & 63, h = idx >> 6;
                int p = h >> 1, hi = h & 1;
                const float* Wb = W + (size_t)(k0 + p * 8 + 2 * hi) * N + n0 + n;
                wreg[it * 4 + 0] = Wb[0];
                wreg[it * 4 + 1] = Wb[4 * N];
                wreg[it * 4 + 2] = Wb[1 * N];
                wreg[it * 4 + 3] = Wb[5 * N];
            }
        }

        // ---- compute: 4 ka-steps of m16n8k8 ----
        #pragma unroll
        for (int ka = 0; ka < 4; ka++) {
            int kb = ka * 8 + 2 * kc;
            unsigned af[4][4], bf[4][2];
            #pragma unroll
            for (int mt = 0; mt < 4; mt++) {
                float2 lo = *(const float2*)(As_s + (wm + mt * 16 + r) * AS + kb);
                float2 hi = *(const float2*)(As_s + (wm + mt * 16 + r + 8) * AS + kb);
                af[mt][0] = __float_as_uint(lo.x);
                af[mt][2] = __float_as_uint(lo.y);
                af[mt][1] = __float_as_uint(hi.x);
                af[mt][3] = __float_as_uint(hi.y);
            }
            #pragma unroll
            for (int nt = 0; nt < 4; nt++) {
                float2 b = *(const float2*)(Ws_s + (wn + nt * 8 + r) * WS + kb);
                bf[nt][0] = __float_as_uint(b.x);
                bf[nt][1] = __float_as_uint(b.y);
            }
            #pragma unroll
            for (int mt = 0; mt < 4; mt++)
                #pragma unroll
                for (int nt = 0; nt < 4; nt++)
                    mma_tf32(acc[mt][nt], af[mt][0], af[mt][1], af[mt][2], af[mt][3],
                             bf[nt][0], bf[nt][1]);
        }
        __syncthreads();
    }

    // ---- epilogue ----
    #pragma unroll
    for (int mt = 0; mt < 4; mt++) {
        #pragma unroll
        for (int i2 = 0; i2 < 2; i2++) {
            int m = m0 + wm + mt * 16 + r + i2 * 8;
            if (m >= M) continue;
            float sc = outScale ? outScale[m] : 1.f;
            #pragma unroll
            for (int nt = 0; nt < 4; nt++) {
                int n = n0 + wn + nt * 8 + kc * 2;
                float v0 = acc[mt][nt][i2 * 2 + 0];
                float v1 = acc[mt][nt][i2 * 2 + 1];
                if (n < nsplit) {
                    v0 = v0 * sc + (bias ? bias[n] : 0.f);
                    v1 = v1 * sc + (bias ? bias[n + 1] : 0.f);
                    float2 o = make_float2(v0, v1);
                    *(float2*)(C1 + (size_t)m * ld1 + n) = o;
                } else {
                    float2 o = make_float2(v0, v1);
                    *(float2*)(C2 + (size_t)m * ld2 + n - nsplit) = o;
                }
            }
        }
    }
}

// ---------------- residual epilogue: out = relu(raw + b1 + b2 + agg*rs) ----------------
__global__ void k_resid(float* __restrict__ out, const float* __restrict__ raw,
                        const float* __restrict__ agg, const float* __restrict__ rs,
                        const float* __restrict__ b1, const float* __restrict__ b2,
                        int M, int D) {
    int per = D >> 2;
    int i = blockIdx.x * blockDim.x + threadIdx.x;
    if (i >= M * per) return;
    int m = i / per, d = (i - m * per) * 4;
    float4 r4 = *(const float4*)(raw + (size_t)m * D + d);
    float4 a4 = *(const float4*)(agg + (size_t)m * D + d);
    float s = rs[m];
    float4 o;
    o.x = fmaxf(r4.x + b1[d + 0] + b2[d + 0] + a4.x * s, 0.f);
    o.y = fmaxf(r4.y + b1[d + 1] + b2[d + 1] + a4.y * s, 0.f);
    o.z = fmaxf(r4.z + b1[d + 2] + b2[d + 2] + a4.z * s, 0.f);
    o.w = fmaxf(r4.w + b1[d + 3] + b2[d + 3] + a4.w * s, 0.f);
    *(float4*)(out + (size_t)m * D + d) = o;
}

// ---------------- SpMM: warp per destination row, float4 gathers ----------------
__global__ void k_spmm96(const float* __restrict__ feat, const int* __restrict__ rowptr,
                         const int* __restrict__ col, float* __restrict__ out, int n_rows) {
    int w = (blockIdx.x * blockDim.x + threadIdx.x) >> 5;
    int lane = threadIdx.x & 31;
    if (w >= n_rows) return;
    int s = rowptr[w], e = rowptr[w + 1];
    bool act = lane < 24;
    int c4 = lane * 4;
    float4 a = make_float4(0.f, 0.f, 0.f, 0.f);
    for (int i = s; i < e; i++) {
        int src = col[i];
        if (act) {
            float4 f = *(const float4*)(feat + (size_t)src * 96 + c4);
            a.x += f.x; a.y += f.y; a.z += f.z; a.w += f.w;
        }
    }
    if (act) *(float4*)(out + (size_t)w * 96 + c4) = a;
}

__global__ void k_spmm64(const float* __restrict__ feat, const int* __restrict__ rowptr,
                         const int* __restrict__ col, float* __restrict__ out, int n_rows) {
    int w = (blockIdx.x * blockDim.x + threadIdx.x) >> 5;
    int lane = threadIdx.x & 31;
    if (w >= n_rows) return;
    int s = rowptr[w], e = rowptr[w + 1];
    bool act = lane < 16;
    int c4 = lane * 4;
    float4 a = make_float4(0.f, 0.f, 0.f, 0.f);
    for (int i = s; i < e; i++) {
        int src = col[i];
        if (act) {
            float4 f = *(const float4*)(feat + (size_t)src * 64 + c4);
            a.x += f.x; a.y += f.y; a.z += f.z; a.w += f.w;
        }
    }
    if (act) *(float4*)(out + (size_t)w * 64 + c4) = a;
}

// ---------------- normalize + score ----------------
__global__ void k_invnorm(const float* __restrict__ x, float* invn, int n) {
    int warp = (blockIdx.x * blockDim.x + threadIdx.x) >> 5;
    int lane = threadIdx.x & 31;
    if (warp >= n) return;
    const float* h = x + (size_t)warp * D_OUT;
    float v0 = h[lane], v1 = h[lane + 32];
    float s = v0 * v0 + v1 * v1;
    #pragma unroll
    for (int off = 16; off; off >>= 1) s += __shfl_xor_sync(0xffffffffu, s, off);
    if (lane == 0) invn[warp] = 1.0f / fmaxf(sqrtf(s), 1e-12f);
}

__global__ void k_score(const float* __restrict__ hu, const float* __restrict__ hr,
                        const float* __restrict__ invn_u, const float* __restrict__ invn_r,
                        const int* __restrict__ iu, const int* __restrict__ ir,
                        float* __restrict__ out, int n) {
    int warp = (blockIdx.x * blockDim.x + threadIdx.x) >> 5;
    int lane = threadIdx.x & 31;
    if (warp >= n) return;
    int u = iu[warp], r = ir[warp];
    const float* a = hu + (size_t)u * D_OUT;
    const float* b = hr + (size_t)r * D_OUT;
    float s = a[lane] * b[lane] + a[lane + 32] * b[lane + 32];
    #pragma unroll
    for (int off = 16; off; off >>= 1) s += __shfl_xor_sync(0xffffffffu, s, off);
    if (lane == 0) out[warp] = s * invn_u[u] * invn_r[r];
}

// ---------------- host ----------------
static inline void* sym(const void* s) {
    void* p = nullptr;
    cudaGetSymbolAddress(&p, s);
    return p;
}

extern "C" void kernel_launch(void* const* d_in, const int* in_sizes, int n_in,
                              void* d_out, int out_size) {
    const float* user_feat = (const float*)d_in[0];
    const float* repo_feat = (const float*)d_in[1];
    const float* W_ue = (const float*)d_in[2];   const float* b_ue = (const float*)d_in[3];
    const float* W_re = (const float*)d_in[4];   const float* b_re = (const float*)d_in[5];
    const float* W_hid_ur = (const float*)d_in[6];  const float* b_hid_ur = (const float*)d_in[7];
    const float* W_hid_ru = (const float*)d_in[8];  const float* b_hid_ru = (const float*)d_in[9];
    const float* W_out_ur = (const float*)d_in[10]; const float* b_out_ur = (const float*)d_in[11];
    const float* W_out_ru = (const float*)d_in[12]; const float* b_out_ru = (const float*)d_in[13];
    const float* W_hcu = (const float*)d_in[14]; const float* b_hcu = (const float*)d_in[15];
    const float* W_hcr = (const float*)d_in[16]; const float* b_hcr = (const float*)d_in[17];
    const float* W_ocu = (const float*)d_in[18]; const float* b_ocu = (const float*)d_in[19];
    const float* W_ocr = (const float*)d_in[20]; const float* b_ocr = (const float*)d_in[21];
    const int* e_ur_src = (const int*)d_in[22];
    const int* e_ur_dst = (const int*)d_in[23];
    const int* e_ru_src = (const int*)d_in[24];
    const int* e_ru_dst = (const int*)d_in[25];
    const int* pos_u = (const int*)d_in[26];
    const int* pos_r = (const int*)d_in[27];
    const int* neg_u = (const int*)d_in[28];
    const int* neg_r = (const int*)d_in[29];
    float* out = (float*)d_out;

    float* h_user = (float*)sym(g_h_user);
    float* h_repo = (float*)sym(g_h_repo);
    float* feat_u = (float*)sym(g_feat_u);
    float* feat_r = (float*)sym(g_feat_r);
    float* raw_u  = (float*)sym(g_raw_u);
    float* raw_r  = (float*)sym(g_raw_r);
    float* agg_u  = (float*)sym(g_agg_u);
    float* agg_r  = (float*)sym(g_agg_r);
    float* out_user = (float*)sym(g_out_user);
    float* out_repo = (float*)sym(g_out_repo);
    float* new_user = (float*)sym(g_new_user);
    float* new_repo = (float*)sym(g_new_repo);
    int* cnt_u_out = (int*)sym(g_cnt_u_out);
    int* cnt_u_in  = (int*)sym(g_cnt_u_in);
    int* cnt_r_out = (int*)sym(g_cnt_r_out);
    int* cnt_r_in  = (int*)sym(g_cnt_r_in);
    float* rs_u_out = (float*)sym(g_rs_u_out);
    float* rs_u_in  = (float*)sym(g_rs_u_in);
    float* rs_r_out = (float*)sym(g_rs_r_out);
    float* rs_r_in  = (float*)sym(g_rs_r_in);
    int* rowptr_ur = (int*)sym(g_rowptr_ur);
    int* rowptr_ru = (int*)sym(g_rowptr_ru);
    int* cursor_ur = (int*)sym(g_cursor_ur);
    int* cursor_ru = (int*)sym(g_cursor_ru);
    int* col_ur = (int*)sym(g_col_ur);
    int* col_ru = (int*)sym(g_col_ru);
    int* part   = (int*)sym(g_part);
    float* invn_u = (float*)sym(g_invn_u);
    float* invn_r = (float*)sym(g_invn_r);
    float* wp_ue = (float*)sym(g_wp_ue);
    float* wp_re = (float*)sym(g_wp_re);
    float* bp_ue = (float*)sym(g_bp_ue);
    float* bp_re = (float*)sym(g_bp_re);
    float* wc_u1 = (float*)sym(g_wc_u1);
    float* wc_r1 = (float*)sym(g_wc_r1);
    float* wc_u2 = (float*)sym(g_wc_u2);
    float* wc_r2 = (float*)sym(g_wc_r2);

    const int T = 256;
    auto blocks = [](long n, int t) { return (int)((n + t - 1) / t); };

    // ---- weight packing (zero-pad via memset, then copy) ----
    cudaMemsetAsync(wp_ue, 0, D_IN * D_EMBP * sizeof(float), 0);
    cudaMemsetAsync(wp_re, 0, D_IN * D_EMBP * sizeof(float), 0);
    cudaMemsetAsync(bp_ue, 0, D_EMBP * sizeof(float), 0);
    cudaMemsetAsync(bp_re, 0, D_EMBP * sizeof(float), 0);
    cudaMemsetAsync(wc_u1, 0, D_EMBP * 192 * sizeof(float), 0);
    cudaMemsetAsync(wc_r1, 0, D_EMBP * 192 * sizeof(float), 0);
    k_pack<<<blocks(D_IN * D_EMB, T), T>>>(wp_ue, D_EMBP, 0, W_ue, D_IN, D_EMB);
    k_pack<<<blocks(D_IN * D_EMB, T), T>>>(wp_re, D_EMBP, 0, W_re, D_IN, D_EMB);
    k_pack<<<1, D_EMB>>>(bp_ue, D_EMBP, 0, b_ue, 1, D_EMB);
    k_pack<<<1, D_EMB>>>(bp_re, D_EMBP, 0, b_re, 1, D_EMB);
    k_pack<<<blocks(D_EMB * D_HID, T), T>>>(wc_u1, 192, 0,  W_hid_ur, D_EMB, D_HID);
    k_pack<<<blocks(D_EMB * D_HID, T), T>>>(wc_u1, 192, 96, W_hcu,    D_EMB, D_HID);
    k_pack<<<blocks(D_EMB * D_HID, T), T>>>(wc_r1, 192, 0,  W_hid_ru, D_EMB, D_HID);
    k_pack<<<blocks(D_EMB * D_HID, T), T>>>(wc_r1, 192, 96, W_hcr,    D_EMB, D_HID);
    k_pack<<<blocks(D_HID * D_OUT, T), T>>>(wc_u2, 128, 0,  W_out_ur, D_HID, D_OUT);
    k_pack<<<blocks(D_HID * D_OUT, T), T>>>(wc_u2, 128, 64, W_ocu,    D_HID, D_OUT);
    k_pack<<<blocks(D_HID * D_OUT, T), T>>>(wc_r2, 128, 0,  W_out_ru, D_HID, D_OUT);
    k_pack<<<blocks(D_HID * D_OUT, T), T>>>(wc_r2, 128, 64, W_ocr,    D_HID, D_OUT);

    // ---- graph structure ----
    cudaMemsetAsync(cnt_u_out, 0, N_USER * sizeof(int), 0);
    cudaMemsetAsync(cnt_u_in,  0, N_USER * sizeof(int), 0);
    cudaMemsetAsync(cnt_r_out, 0, N_REPO * sizeof(int), 0);
    cudaMemsetAsync(cnt_r_in,  0, N_REPO * sizeof(int), 0);
    k_count_deg<<<blocks(NE, T), T>>>(e_ur_src, e_ur_dst, cnt_u_out, cnt_r_in, NE);
    k_count_deg<<<blocks(NE, T), T>>>(e_ru_src, e_ru_dst, cnt_r_out, cnt_u_in, NE);
    k_rsqrt_deg<<<blocks(N_USER, T), T>>>(cnt_u_out, rs_u_out, N_USER);
    k_rsqrt_deg<<<blocks(N_USER, T), T>>>(cnt_u_in, rs_u_in, N_USER);
    k_rsqrt_deg<<<blocks(N_REPO, T), T>>>(cnt_r_out, rs_r_out, N_REPO);
    k_rsqrt_deg<<<blocks(N_REPO, T), T>>>(cnt_r_in, rs_r_in, N_REPO);

    int nb_r = (N_REPO + 1023) / 1024;
    int nb_u = (N_USER + 1023) / 1024;
    k_scan_block<<<nb_r, 1024>>>(cnt_r_in, rowptr_ur, part, N_REPO);
    k_scan_part<<<1, 128>>>(part, nb_r);
    k_scan_add<<<blocks(N_REPO, T), T>>>(rowptr_ur, part, N_REPO);
    k_scan_block<<<nb_u, 1024>>>(cnt_u_in, rowptr_ru, part, N_USER);
    k_scan_part<<<1, 128>>>(part, nb_u);
    k_scan_add<<<blocks(N_USER, T), T>>>(rowptr_ru, part, N_USER);

    k_copy_int<<<blocks(N_REPO, T), T>>>(rowptr_ur, cursor_ur, N_REPO);
    k_copy_int<<<blocks(N_USER, T), T>>>(rowptr_ru, cursor_ru, N_USER);
    k_csr_fill<<<blocks(NE, T), T>>>(e_ur_src, e_ur_dst, cursor_ur, col_ur, NE);
    k_csr_fill<<<blocks(NE, T), T>>>(e_ru_src, e_ru_dst, cursor_ru, col_ru, NE);

    dim3 tb(128);
    auto grid = [](int M, int N) { return dim3(N / BN, (M + BM - 1) / BM); };

    // ---- embedding GEMMs: h = feat @ Wp + bp  (N=128, padded cols = 0) ----
    k_gemm_tc<<<grid(N_USER, D_EMBP), tb>>>(user_feat, wp_ue,
        h_user, D_EMBP, h_user, D_EMBP, D_EMBP, N_USER, D_EMBP, D_IN, nullptr, bp_ue);
    k_gemm_tc<<<grid(N_REPO, D_EMBP), tb>>>(repo_feat, wp_re,
        h_repo, D_EMBP, h_repo, D_EMBP, D_EMBP, N_REPO, D_EMBP, D_IN, nullptr, bp_re);

    // ---- layer 1: fused [feat | raw] GEMMs (K=128, N=192) ----
    k_gemm_tc<<<grid(N_REPO, 192), tb>>>(h_repo, wc_r1,
        feat_r, D_HID, raw_r, D_HID, D_HID, N_REPO, 192, D_EMBP, rs_r_out, nullptr);
    k_gemm_tc<<<grid(N_USER, 192), tb>>>(h_user, wc_u1,
        feat_u, D_HID, raw_u, D_HID, D_HID, N_USER, 192, D_EMBP, rs_u_out, nullptr);
    k_spmm96<<<blocks((long)N_USER * 32, T), T>>>(feat_r, rowptr_ru, col_ru, agg_u, N_USER);
    k_spmm96<<<blocks((long)N_REPO * 32, T), T>>>(feat_u, rowptr_ur, col_ur, agg_r, N_REPO);
    k_resid<<<blocks((long)N_USER * D_HID / 4, T), T>>>(out_user, raw_u, agg_u, rs_u_in,
                                                        b_hcu, b_hid_ru, N_USER, D_HID);
    k_resid<<<blocks((long)N_REPO * D_HID / 4, T), T>>>(out_repo, raw_r, agg_r, rs_r_in,
                                                        b_hcr, b_hid_ur, N_REPO, D_HID);

    // ---- layer 2: fused [feat | raw] GEMMs (K=96, N=128); reuse feat/raw/agg @64 ----
    k_gemm_tc<<<grid(N_REPO, 128), tb>>>(out_repo, wc_r2,
        feat_r, D_OUT, raw_r, D_OUT, D_OUT, N_REPO, 128, D_HID, rs_r_out, nullptr);
    k_gemm_tc<<<grid(N_USER, 128), tb>>>(out_user, wc_u2,
        feat_u, D_OUT, raw_u, D_OUT, D_OUT, N_USER, 128, D_HID, rs_u_out, nullptr);
    k_spmm64<<<blocks((long)N_USER * 32, T), T>>>(feat_r, rowptr_ru, col_ru, agg_u, N_USER);
    k_spmm64<<<blocks((long)N_REPO * 32, T), T>>>(feat_u, rowptr_ur, col_ur, agg_r, N_REPO);
    k_resid<<<blocks((long)N_USER * D_OUT / 4, T), T>>>(new_user, raw_u, agg_u, rs_u_in,
                                                        b_ocu, b_out_ru, N_USER, D_OUT);
    k_resid<<<blocks((long)N_REPO * D_OUT / 4, T), T>>>(new_repo, raw_r, agg_r, rs_r_in,
                                                        b_ocr, b_out_ur, N_REPO, D_OUT);

    // ---- cosine scores ----
    k_invnorm<<<blocks((long)N_USER * 32, T), T>>>(new_user, invn_u, N_USER);
    k_invnorm<<<blocks((long)N_REPO * 32, T), T>>>(new_repo, invn_r, N_REPO);
    k_score<<<blocks((long)NEP * 32, T), T>>>(new_user, new_repo, invn_u, invn_r,
                                              pos_u, pos_r, out, NEP);
    k_score<<<blocks((long)NEP * 32, T), T>>>(new_user, new_repo, invn_u, invn_r,
                                              neg_u, neg_r, out + NEP, NEP);
}

// round 4
// speedup vs baseline: 2.2475x; 1.1190x over previous
#include <cuda_runtime.h>
#include <cuda_fp16.h>
#include <math.h>

// ---------------- problem constants ----------------
#define N_USER 50000
#define N_REPO 100000
#define NE     1000000
#define NEP    200000
#define D_IN   256
#define D_EMB  125
#define D_EMBP 128
#define D_HID  96
#define D_OUT  64

// ---------------- scratch (device globals) ----------------
__device__ float  g_h_user[N_USER * D_EMBP];
__device__ float  g_h_repo[N_REPO * D_EMBP];
__device__ __half g_feat_u[N_USER * D_HID];   // fp16 messages (reused @64 in layer 2)
__device__ __half g_feat_r[N_REPO * D_HID];
__device__ float  g_raw_u [N_USER * D_HID];
__device__ float  g_raw_r [N_REPO * D_HID];
__device__ float  g_out_user[N_USER * D_HID];
__device__ float  g_out_repo[N_REPO * D_HID];
__device__ float  g_new_user[N_USER * D_OUT];
__device__ float  g_new_repo[N_REPO * D_OUT];

__device__ int   g_cnt_u_out[N_USER];
__device__ int   g_cnt_u_in [N_USER];
__device__ int   g_cnt_r_out[N_REPO];
__device__ int   g_cnt_r_in [N_REPO];
__device__ float g_rs_u_out[N_USER], g_rs_u_in[N_USER];
__device__ float g_rs_r_out[N_REPO], g_rs_r_in[N_REPO];

__device__ int g_rowptr_ur[N_REPO + 1];
__device__ int g_rowptr_ru[N_USER + 1];
__device__ int g_cursor_ur[N_REPO];
__device__ int g_cursor_ru[N_USER];
__device__ int g_col_ur[NE];
__device__ int g_col_ru[NE];
__device__ int g_part[128];

__device__ float g_invn_u[N_USER];
__device__ float g_invn_r[N_REPO];

// packed/padded weights
__device__ float g_wp_ue[D_IN * D_EMBP];
__device__ float g_wp_re[D_IN * D_EMBP];
__device__ float g_bp_ue[D_EMBP];
__device__ float g_bp_re[D_EMBP];
__device__ float g_wc_u1[D_EMBP * 192];   // [128][ W_hid_ur | W_hcu ]
__device__ float g_wc_r1[D_EMBP * 192];   // [128][ W_hid_ru | W_hcr ]
__device__ float g_wc_u2[D_HID * 128];    // [96][ W_out_ur | W_ocu ]
__device__ float g_wc_r2[D_HID * 128];    // [96][ W_out_ru | W_ocr ]

// ---------------- merged preprocessing ----------------
__global__ void k_pack_all(const float* __restrict__ W_ue, const float* __restrict__ W_re,
                           const float* __restrict__ b_ue, const float* __restrict__ b_re,
                           const float* __restrict__ W_hid_ur, const float* __restrict__ W_hcu,
                           const float* __restrict__ W_hid_ru, const float* __restrict__ W_hcr,
                           const float* __restrict__ W_out_ur, const float* __restrict__ W_ocu,
                           const float* __restrict__ W_out_ru, const float* __restrict__ W_ocr) {
    int i = blockIdx.x * blockDim.x + threadIdx.x;
    // seg 0/1: 256x125 -> wp (ld 128)
    if (i < 32000) { int k = i / 125, n = i % 125; g_wp_ue[k * 128 + n] = W_ue[i]; return; }
    i -= 32000;
    if (i < 32000) { int k = i / 125, n = i % 125; g_wp_re[k * 128 + n] = W_re[i]; return; }
    i -= 32000;
    if (i < 125) { g_bp_ue[i] = b_ue[i]; return; }
    i -= 125;
    if (i < 125) { g_bp_re[i] = b_re[i]; return; }
    i -= 125;
    // segs: 125x96 -> wc1 (ld 192)
    if (i < 12000) { int k = i / 96, n = i % 96; g_wc_u1[k * 192 + n]      = W_hid_ur[i]; return; }
    i -= 12000;
    if (i < 12000) { int k = i / 96, n = i % 96; g_wc_u1[k * 192 + 96 + n] = W_hcu[i]; return; }
    i -= 12000;
    if (i < 12000) { int k = i / 96, n = i % 96; g_wc_r1[k * 192 + n]      = W_hid_ru[i]; return; }
    i -= 12000;
    if (i < 12000) { int k = i / 96, n = i % 96; g_wc_r1[k * 192 + 96 + n] = W_hcr[i]; return; }
    i -= 12000;
    // segs: 96x64 -> wc2 (ld 128)
    if (i < 6144) { int k = i / 64, n = i % 64; g_wc_u2[k * 128 + n]      = W_out_ur[i]; return; }
    i -= 6144;
    if (i < 6144) { int k = i / 64, n = i % 64; g_wc_u2[k * 128 + 64 + n] = W_ocu[i]; return; }
    i -= 6144;
    if (i < 6144) { int k = i / 64, n = i % 64; g_wc_r2[k * 128 + n]      = W_out_ru[i]; return; }
    i -= 6144;
    if (i < 6144) { int k = i / 64, n = i % 64; g_wc_r2[k * 128 + 64 + n] = W_ocr[i]; return; }
}
#define PACK_TOTAL (32000*2 + 125*2 + 12000*4 + 6144*4)

__global__ void k_count_all(const int* __restrict__ ur_src, const int* __restrict__ ur_dst,
                            const int* __restrict__ ru_src, const int* __restrict__ ru_dst) {
    int i = blockIdx.x * blockDim.x + threadIdx.x;
    if (i < NE) {
        atomicAdd(&g_cnt_u_out[ur_src[i]], 1);
        atomicAdd(&g_cnt_r_in[ur_dst[i]], 1);
    } else if (i < 2 * NE) {
        int j = i - NE;
        atomicAdd(&g_cnt_r_out[ru_src[j]], 1);
        atomicAdd(&g_cnt_u_in[ru_dst[j]], 1);
    }
}

__global__ void k_rsqrt_all() {
    int i = blockIdx.x * blockDim.x + threadIdx.x;
    if (i < N_USER) { g_rs_u_out[i] = rsqrtf(fmaxf((float)g_cnt_u_out[i], 1.f)); return; }
    i -= N_USER;
    if (i < N_USER) { g_rs_u_in[i] = rsqrtf(fmaxf((float)g_cnt_u_in[i], 1.f)); return; }
    i -= N_USER;
    if (i < N_REPO) { g_rs_r_out[i] = rsqrtf(fmaxf((float)g_cnt_r_out[i], 1.f)); return; }
    i -= N_REPO;
    if (i < N_REPO) { g_rs_r_in[i] = rsqrtf(fmaxf((float)g_cnt_r_in[i], 1.f)); return; }
}

__global__ void k_scan_block(const int* __restrict__ cnt, int* rowptr, int* partial, int n) {
    __shared__ int sh[1024];
    int b = blockIdx.x, t = threadIdx.x;
    int i = b * 1024 + t;
    int v = (i < n) ? cnt[i] : 0;
    sh[t] = v;
    __syncthreads();
    for (int off = 1; off < 1024; off <<= 1) {
        int x = (t >= off) ? sh[t - off] : 0;
        __syncthreads();
        sh[t] += x;
        __syncthreads();
    }
    if (i < n) rowptr[i + 1] = sh[t];
    if (t == 1023) partial[b] = sh[1023];
}

__global__ void k_scan_part(int* partial, int nb) {
    __shared__ int sh[128];
    int t = threadIdx.x;
    int v = (t < nb) ? partial[t] : 0;
    sh[t] = v;
    __syncthreads();
    for (int off = 1; off < 128; off <<= 1) {
        int x = (t >= off) ? sh[t - off] : 0;
        __syncthreads();
        sh[t] += x;
        __syncthreads();
    }
    if (t < nb) partial[t] = sh[t] - v;
}

// finalize rowptr and copy to cursor in one pass
__global__ void k_scan_add(int* rowptr, int* cursor, const int* __restrict__ partial, int n) {
    int i = blockIdx.x * blockDim.x + threadIdx.x;
    if (i == 0) { rowptr[0] = 0; cursor[0] = 0; }
    if (i < n) {
        int v = rowptr[i + 1] + partial[i >> 10];
        rowptr[i + 1] = v;
        if (i + 1 < n) cursor[i + 1] = v;
    }
}

__global__ void k_fill_all(const int* __restrict__ ur_src, const int* __restrict__ ur_dst,
                           const int* __restrict__ ru_src, const int* __restrict__ ru_dst) {
    int i = blockIdx.x * blockDim.x + threadIdx.x;
    if (i < NE) {
        int p = atomicAdd(&g_cursor_ur[ur_dst[i]], 1);
        g_col_ur[p] = ur_src[i];
    } else if (i < 2 * NE) {
        int j = i - NE;
        int p = atomicAdd(&g_cursor_ru[ru_dst[j]], 1);
        g_col_ru[p] = ru_src[j];
    }
}

// ---------------- tf32 tensor-core GEMM ----------------
// n <  nsplit: C1 = acc * outScale[m] (+ bias[n] fp32 path); fp16 path stores half2
// n >= nsplit: C2 = acc (fp32)
#define BM 128
#define BN 64
#define BK 32
#define AS 40
#define WS 40

__device__ __forceinline__ float to_tf32(float x) {
    float y;
    asm("cvt.rna.tf32.f32 %0, %1;" : "=f"(y) : "f"(x));
    return y;
}

__device__ __forceinline__ void mma_tf32(float c[4],
                                         unsigned a0, unsigned a1, unsigned a2, unsigned a3,
                                         unsigned b0, unsigned b1) {
    asm volatile(
        "mma.sync.aligned.m16n8k8.row.col.f32.tf32.tf32.f32 "
        "{%0,%1,%2,%3}, {%4,%5,%6,%7}, {%8,%9}, {%0,%1,%2,%3};"
        : "+f"(c[0]), "+f"(c[1]), "+f"(c[2]), "+f"(c[3])
        : "r"(a0), "r"(a1), "r"(a2), "r"(a3), "r"(b0), "r"(b1));
}

template <bool FEAT_HALF>
__global__ __launch_bounds__(128) void k_gemm_tc(
    const float* __restrict__ A, const float* __restrict__ W,
    float* __restrict__ C1f, __half* __restrict__ C1h, int ld1,
    float* __restrict__ C2, int ld2, int nsplit,
    int M, int N, int K,
    const float* __restrict__ outScale, const float* __restrict__ bias)
{
    __shared__ float As_s[BM * AS];
    __shared__ float Ws_s[BN * WS];

    const int tid = threadIdx.x;
    const int warp = tid >> 5, lane = tid & 31;
    const int wm = (warp >> 1) * 64;
    const int wn = (warp & 1) * 32;
    const int m0 = blockIdx.y * BM;
    const int n0 = blockIdx.x * BN;
    const int r = lane >> 2, kc = lane & 3;

    float acc[4][4][4];
    #pragma unroll
    for (int a = 0; a < 4; a++)
        #pragma unroll
        for (int b = 0; b < 4; b++)
            #pragma unroll
            for (int c = 0; c < 4; c++) acc[a][b][c] = 0.f;

    float4 a4[8];
    float  wreg[16];

    const int am = m0 + tid;
    const bool ag = am < M;
    const float* Arow = A + (size_t)am * K;

    {
        #pragma unroll
        for (int j = 0; j < 8; j++)
            a4[j] = ag ? *(const float4*)(Arow + j * 4) : make_float4(0.f, 0.f, 0.f, 0.f);
        #pragma unroll
        for (int it = 0; it < 4; it++) {
            int idx = tid + it * 128;
            int n = idx & 63, h = idx >> 6;
            int p = h >> 1, hi = h & 1;
            const float* Wb = W + (size_t)(p * 8 + 2 * hi) * N + n0 + n;
            wreg[it * 4 + 0] = Wb[0];
            wreg[it * 4 + 1] = Wb[4 * N];
            wreg[it * 4 + 2] = Wb[1 * N];
            wreg[it * 4 + 3] = Wb[5 * N];
        }
    }

    const int T = K / BK;
    for (int t = 0; t < T; t++) {
        #pragma unroll
        for (int p = 0; p < 4; p++) {
            float4 lo = a4[2 * p], hi = a4[2 * p + 1];
            float4 q0 = make_float4(to_tf32(lo.x), to_tf32(hi.x), to_tf32(lo.y), to_tf32(hi.y));
            float4 q1 = make_float4(to_tf32(lo.z), to_tf32(hi.z), to_tf32(lo.w), to_tf32(hi.w));
            *(float4*)(As_s + tid * AS + p * 8)     = q0;
            *(float4*)(As_s + tid * AS + p * 8 + 4) = q1;
        }
        #pragma unroll
        for (int it = 0; it < 4; it++) {
            int idx = tid + it * 128;
            int n = idx & 63, h = idx >> 6;
            int p = h >> 1, hi = h & 1;
            float4 q = make_float4(to_tf32(wreg[it * 4 + 0]), to_tf32(wreg[it * 4 + 1]),
                                   to_tf32(wreg[it * 4 + 2]), to_tf32(wreg[it * 4 + 3]));
            *(float4*)(Ws_s + n * WS + p * 8 + hi * 4) = q;
        }
        __syncthreads();

        if (t + 1 < T) {
            int k0 = (t + 1) * BK;
            #pragma unroll
            for (int j = 0; j < 8; j++)
                a4[j] = ag ? *(const float4*)(Arow + k0 + j * 4) : make_float4(0.f, 0.f, 0.f, 0.f);
            #pragma unroll
            for (int it = 0; it < 4; it++) {
                int idx = tid + it * 128;
                int n = idx & 63, h = idx >> 6;
                int p = h >> 1, hi = h & 1;
                const float* Wb = W + (size_t)(k0 + p * 8 + 2 * hi) * N + n0 + n;
                wreg[it * 4 + 0] = Wb[0];
                wreg[it * 4 + 1] = Wb[4 * N];
                wreg[it * 4 + 2] = Wb[1 * N];
                wreg[it * 4 + 3] = Wb[5 * N];
            }
        }

        #pragma unroll
        for (int ka = 0; ka < 4; ka++) {
            int kb = ka * 8 + 2 * kc;
            unsigned af[4][4], bf[4][2];
            #pragma unroll
            for (int mt = 0; mt < 4; mt++) {
                float2 lo = *(const float2*)(As_s + (wm + mt * 16 + r) * AS + kb);
                float2 hi = *(const float2*)(As_s + (wm + mt * 16 + r + 8) * AS + kb);
                af[mt][0] = __float_as_uint(lo.x);
                af[mt][2] = __float_as_uint(lo.y);
                af[mt][1] = __float_as_uint(hi.x);
                af[mt][3] = __float_as_uint(hi.y);
            }
            #pragma unroll
            for (int nt = 0; nt < 4; nt++) {
                float2 b = *(const float2*)(Ws_s + (wn + nt * 8 + r) * WS + kb);
                bf[nt][0] = __float_as_uint(b.x);
                bf[nt][1] = __float_as_uint(b.y);
            }
            #pragma unroll
            for (int mt = 0; mt < 4; mt++)
                #pragma unroll
                for (int nt = 0; nt < 4; nt++)
                    mma_tf32(acc[mt][nt], af[mt][0], af[mt][1], af[mt][2], af[mt][3],
                             bf[nt][0], bf[nt][1]);
        }
        __syncthreads();
    }

    #pragma unroll
    for (int mt = 0; mt < 4; mt++) {
        #pragma unroll
        for (int i2 = 0; i2 < 2; i2++) {
            int m = m0 + wm + mt * 16 + r + i2 * 8;
            if (m >= M) continue;
            float sc = outScale ? outScale[m] : 1.f;
            #pragma unroll
            for (int nt = 0; nt < 4; nt++) {
                int n = n0 + wn + nt * 8 + kc * 2;
                float v0 = acc[mt][nt][i2 * 2 + 0];
                float v1 = acc[mt][nt][i2 * 2 + 1];
                if (n < nsplit) {
                    if (FEAT_HALF) {
                        __half2 h = __floats2half2_rn(v0 * sc, v1 * sc);
                        *(__half2*)(C1h + (size_t)m * ld1 + n) = h;
                    } else {
                        v0 = v0 * sc + (bias ? bias[n] : 0.f);
                        v1 = v1 * sc + (bias ? bias[n + 1] : 0.f);
                        *(float2*)(C1f + (size_t)m * ld1 + n) = make_float2(v0, v1);
                    }
                } else {
                    *(float2*)(C2 + (size_t)m * ld2 + n - nsplit) = make_float2(v0, v1);
                }
            }
        }
    }
}

// ---------------- fused SpMM + residual epilogue ----------------
// out[w,:] = relu(raw[w,:] + b1 + b2 + rs_in[w] * sum_{e in row w} feat[col[e],:])
__global__ void k_spmm_out96(const __half* __restrict__ feat, const int* __restrict__ rowptr,
                             const int* __restrict__ col, const float* __restrict__ raw,
                             const float* __restrict__ rs_in,
                             const float* __restrict__ b1, const float* __restrict__ b2,
                             float* __restrict__ out, int n_rows) {
    int w = (blockIdx.x * blockDim.x + threadIdx.x) >> 5;
    int lane = threadIdx.x & 31;
    if (w >= n_rows) return;
    int s = rowptr[w], e = rowptr[w + 1];
    bool act = lane < 24;
    int d = lane * 4;
    float4 a0 = make_float4(0.f, 0.f, 0.f, 0.f);
    float4 a1 = make_float4(0.f, 0.f, 0.f, 0.f);
    int i = s;
    for (; i + 1 < e; i += 2) {
        int c0 = col[i], c1 = col[i + 1];
        if (act) {
            uint2 q0 = *(const uint2*)(feat + (size_t)c0 * 96 + d);
            uint2 q1 = *(const uint2*)(feat + (size_t)c1 * 96 + d);
            float2 f00 = __half22float2(*(__half2*)&q0.x);
            float2 f01 = __half22float2(*(__half2*)&q0.y);
            float2 f10 = __half22float2(*(__half2*)&q1.x);
            float2 f11 = __half22float2(*(__half2*)&q1.y);
            a0.x += f00.x; a0.y += f00.y; a0.z += f01.x; a0.w += f01.y;
            a1.x += f10.x; a1.y += f10.y; a1.z += f11.x; a1.w += f11.y;
        }
    }
    if (i < e && act) {
        int c0 = col[i];
        uint2 q0 = *(const uint2*)(feat + (size_t)c0 * 96 + d);
        float2 f00 = __half22float2(*(__half2*)&q0.x);
        float2 f01 = __half22float2(*(__half2*)&q0.y);
        a0.x += f00.x; a0.y += f00.y; a0.z += f01.x; a0.w += f01.y;
    }
    if (act) {
        float sc = rs_in[w];
        float4 r4 = *(const float4*)(raw + (size_t)w * 96 + d);
        float4 o;
        o.x = fmaxf(r4.x + b1[d + 0] + b2[d + 0] + (a0.x + a1.x) * sc, 0.f);
        o.y = fmaxf(r4.y + b1[d + 1] + b2[d + 1] + (a0.y + a1.y) * sc, 0.f);
        o.z = fmaxf(r4.z + b1[d + 2] + b2[d + 2] + (a0.z + a1.z) * sc, 0.f);
        o.w = fmaxf(r4.w + b1[d + 3] + b2[d + 3] + (a0.w + a1.w) * sc, 0.f);
        *(float4*)(out + (size_t)w * 96 + d) = o;
    }
}

// layer-2 variant (D=64) with fused inverse-norm computation
__global__ void k_spmm_out64_norm(const __half* __restrict__ feat, const int* __restrict__ rowptr,
                                  const int* __restrict__ col, const float* __restrict__ raw,
                                  const float* __restrict__ rs_in,
                                  const float* __restrict__ b1, const float* __restrict__ b2,
                                  float* __restrict__ out, float* __restrict__ invn, int n_rows) {
    int w = (blockIdx.x * blockDim.x + threadIdx.x) >> 5;
    int lane = threadIdx.x & 31;
    if (w >= n_rows) return;
    int s = rowptr[w], e = rowptr[w + 1];
    bool act = lane < 16;
    int d = lane * 4;
    float4 a0 = make_float4(0.f, 0.f, 0.f, 0.f);
    float4 a1 = make_float4(0.f, 0.f, 0.f, 0.f);
    int i = s;
    for (; i + 1 < e; i += 2) {
        int c0 = col[i], c1 = col[i + 1];
        if (act) {
            uint2 q0 = *(const uint2*)(feat + (size_t)c0 * 64 + d);
            uint2 q1 = *(const uint2*)(feat + (size_t)c1 * 64 + d);
            float2 f00 = __half22float2(*(__half2*)&q0.x);
            float2 f01 = __half22float2(*(__half2*)&q0.y);
            float2 f10 = __half22float2(*(__half2*)&q1.x);
            float2 f11 = __half22float2(*(__half2*)&q1.y);
            a0.x += f00.x; a0.y += f00.y; a0.z += f01.x; a0.w += f01.y;
            a1.x += f10.x; a1.y += f10.y; a1.z += f11.x; a1.w += f11.y;
        }
    }
    if (i < e && act) {
        int c0 = col[i];
        uint2 q0 = *(const uint2*)(feat + (size_t)c0 * 64 + d);
        float2 f00 = __half22float2(*(__half2*)&q0.x);
        float2 f01 = __half22float2(*(__half2*)&q0.y);
        a0.x += f00.x; a0.y += f00.y; a0.z += f01.x; a0.w += f01.y;
    }
    float sq = 0.f;
    if (act) {
        float sc = rs_in[w];
        float4 r4 = *(const float4*)(raw + (size_t)w * 64 + d);
        float4 o;
        o.x = fmaxf(r4.x + b1[d + 0] + b2[d + 0] + (a0.x + a1.x) * sc, 0.f);
        o.y = fmaxf(r4.y + b1[d + 1] + b2[d + 1] + (a0.y + a1.y) * sc, 0.f);
        o.z = fmaxf(r4.z + b1[d + 2] + b2[d + 2] + (a0.z + a1.z) * sc, 0.f);
        o.w = fmaxf(r4.w + b1[d + 3] + b2[d + 3] + (a0.w + a1.w) * sc, 0.f);
        *(float4*)(out + (size_t)w * 64 + d) = o;
        sq = o.x * o.x + o.y * o.y + o.z * o.z + o.w * o.w;
    }
    #pragma unroll
    for (int off = 16; off; off >>= 1) sq += __shfl_xor_sync(0xffffffffu, sq, off);
    if (lane == 0) invn[w] = 1.0f / fmaxf(sqrtf(sq), 1e-12f);
}

// ---------------- score (pos+neg in one launch) ----------------
__global__ void k_score_all(const float* __restrict__ hu, const float* __restrict__ hr,
                            const float* __restrict__ invn_u, const float* __restrict__ invn_r,
                            const int* __restrict__ pos_u, const int* __restrict__ pos_r,
                            const int* __restrict__ neg_u, const int* __restrict__ neg_r,
                            float* __restrict__ out) {
    int w = (blockIdx.x * blockDim.x + threadIdx.x) >> 5;
    int lane = threadIdx.x & 31;
    if (w >= 2 * NEP) return;
    int u, r;
    if (w < NEP) { u = pos_u[w]; r = pos_r[w]; }
    else         { u = neg_u[w - NEP]; r = neg_r[w - NEP]; }
    const float* a = hu + (size_t)u * D_OUT;
    const float* b = hr + (size_t)r * D_OUT;
    float s = a[lane] * b[lane] + a[lane + 32] * b[lane + 32];
    #pragma unroll
    for (int off = 16; off; off >>= 1) s += __shfl_xor_sync(0xffffffffu, s, off);
    if (lane == 0) out[w] = s * invn_u[u] * invn_r[r];
}

// ---------------- host ----------------
static inline void* sym(const void* s) {
    void* p = nullptr;
    cudaGetSymbolAddress(&p, s);
    return p;
}

extern "C" void kernel_launch(void* const* d_in, const int* in_sizes, int n_in,
                              void* d_out, int out_size) {
    const float* user_feat = (const float*)d_in[0];
    const float* repo_feat = (const float*)d_in[1];
    const float* W_ue = (const float*)d_in[2];   const float* b_ue = (const float*)d_in[3];
    const float* W_re = (const float*)d_in[4];   const float* b_re = (const float*)d_in[5];
    const float* W_hid_ur = (const float*)d_in[6];  const float* b_hid_ur = (const float*)d_in[7];
    const float* W_hid_ru = (const float*)d_in[8];  const float* b_hid_ru = (const float*)d_in[9];
    const float* W_out_ur = (const float*)d_in[10]; const float* b_out_ur = (const float*)d_in[11];
    const float* W_out_ru = (const float*)d_in[12]; const float* b_out_ru = (const float*)d_in[13];
    const float* W_hcu = (const float*)d_in[14]; const float* b_hcu = (const float*)d_in[15];
    const float* W_hcr = (const float*)d_in[16]; const float* b_hcr = (const float*)d_in[17];
    const float* W_ocu = (const float*)d_in[18]; const float* b_ocu = (const float*)d_in[19];
    const float* W_ocr = (const float*)d_in[20]; const float* b_ocr = (const float*)d_in[21];
    const int* e_ur_src = (const int*)d_in[22];
    const int* e_ur_dst = (const int*)d_in[23];
    const int* e_ru_src = (const int*)d_in[24];
    const int* e_ru_dst = (const int*)d_in[25];
    const int* pos_u = (const int*)d_in[26];
    const int* pos_r = (const int*)d_in[27];
    const int* neg_u = (const int*)d_in[28];
    const int* neg_r = (const int*)d_in[29];
    float* out = (float*)d_out;

    float*  h_user = (float*)sym(g_h_user);
    float*  h_repo = (float*)sym(g_h_repo);
    __half* feat_u = (__half*)sym(g_feat_u);
    __half* feat_r = (__half*)sym(g_feat_r);
    float*  raw_u  = (float*)sym(g_raw_u);
    float*  raw_r  = (float*)sym(g_raw_r);
    float*  out_user = (float*)sym(g_out_user);
    float*  out_repo = (float*)sym(g_out_repo);
    float*  new_user = (float*)sym(g_new_user);
    float*  new_repo = (float*)sym(g_new_repo);
    int* cnt_u_out = (int*)sym(g_cnt_u_out);
    int* cnt_u_in  = (int*)sym(g_cnt_u_in);
    int* cnt_r_out = (int*)sym(g_cnt_r_out);
    int* cnt_r_in  = (int*)sym(g_cnt_r_in);
    float* rs_u_out = (float*)sym(g_rs_u_out);
    float* rs_u_in  = (float*)sym(g_rs_u_in);
    float* rs_r_out = (float*)sym(g_rs_r_out);
    float* rs_r_in  = (float*)sym(g_rs_r_in);
    int* rowptr_ur = (int*)sym(g_rowptr_ur);
    int* rowptr_ru = (int*)sym(g_rowptr_ru);
    int* cursor_ur = (int*)sym(g_cursor_ur);
    int* cursor_ru = (int*)sym(g_cursor_ru);
    int* col_ur = (int*)sym(g_col_ur);
    int* col_ru = (int*)sym(g_col_ru);
    int* part   = (int*)sym(g_part);
    float* invn_u = (float*)sym(g_invn_u);
    float* invn_r = (float*)sym(g_invn_r);
    float* wp_ue = (float*)sym(g_wp_ue);
    float* wp_re = (float*)sym(g_wp_re);
    float* bp_ue = (float*)sym(g_bp_ue);
    float* bp_re = (float*)sym(g_bp_re);
    float* wc_u1 = (float*)sym(g_wc_u1);
    float* wc_r1 = (float*)sym(g_wc_r1);
    float* wc_u2 = (float*)sym(g_wc_u2);
    float* wc_r2 = (float*)sym(g_wc_r2);

    const int T = 256;
    auto blocks = [](long n, int t) { return (int)((n + t - 1) / t); };

    // ---- weight packing ----
    cudaMemsetAsync(wp_ue, 0, D_IN * D_EMBP * sizeof(float), 0);
    cudaMemsetAsync(wp_re, 0, D_IN * D_EMBP * sizeof(float), 0);
    cudaMemsetAsync(bp_ue, 0, D_EMBP * sizeof(float), 0);
    cudaMemsetAsync(bp_re, 0, D_EMBP * sizeof(float), 0);
    cudaMemsetAsync(wc_u1, 0, D_EMBP * 192 * sizeof(float), 0);
    cudaMemsetAsync(wc_r1, 0, D_EMBP * 192 * sizeof(float), 0);
    k_pack_all<<<blocks(PACK_TOTAL, T), T>>>(W_ue, W_re, b_ue, b_re,
                                             W_hid_ur, W_hcu, W_hid_ru, W_hcr,
                                             W_out_ur, W_ocu, W_out_ru, W_ocr);

    // ---- graph structure ----
    cudaMemsetAsync(cnt_u_out, 0, N_USER * sizeof(int), 0);
    cudaMemsetAsync(cnt_u_in,  0, N_USER * sizeof(int), 0);
    cudaMemsetAsync(cnt_r_out, 0, N_REPO * sizeof(int), 0);
    cudaMemsetAsync(cnt_r_in,  0, N_REPO * sizeof(int), 0);
    k_count_all<<<blocks(2L * NE, T), T>>>(e_ur_src, e_ur_dst, e_ru_src, e_ru_dst);
    k_rsqrt_all<<<blocks(2L * (N_USER + N_REPO), T), T>>>();

    int nb_r = (N_REPO + 1023) / 1024;
    int nb_u = (N_USER + 1023) / 1024;
    k_scan_block<<<nb_r, 1024>>>(cnt_r_in, rowptr_ur, part, N_REPO);
    k_scan_part<<<1, 128>>>(part, nb_r);
    k_scan_add<<<blocks(N_REPO, T), T>>>(rowptr_ur, cursor_ur, part, N_REPO);
    k_scan_block<<<nb_u, 1024>>>(cnt_u_in, rowptr_ru, part, N_USER);
    k_scan_part<<<1, 128>>>(part, nb_u);
    k_scan_add<<<blocks(N_USER, T), T>>>(rowptr_ru, cursor_ru, part, N_USER);
    k_fill_all<<<blocks(2L * NE, T), T>>>(e_ur_src, e_ur_dst, e_ru_src, e_ru_dst);

    dim3 tb(128);
    auto grid = [](int M, int N) { return dim3(N / BN, (M + BM - 1) / BM); };

    // ---- embedding GEMMs (fp32 out, bias) ----
    k_gemm_tc<false><<<grid(N_USER, D_EMBP), tb>>>(user_feat, wp_ue,
        h_user, nullptr, D_EMBP, h_user, D_EMBP, D_EMBP, N_USER, D_EMBP, D_IN, nullptr, bp_ue);
    k_gemm_tc<false><<<grid(N_REPO, D_EMBP), tb>>>(repo_feat, wp_re,
        h_repo, nullptr, D_EMBP, h_repo, D_EMBP, D_EMBP, N_REPO, D_EMBP, D_IN, nullptr, bp_re);

    // ---- layer 1: fused GEMMs -> [feat(fp16, scaled) | raw(fp32)] ----
    k_gemm_tc<true><<<grid(N_REPO, 192), tb>>>(h_repo, wc_r1,
        nullptr, feat_r, D_HID, raw_r, D_HID, D_HID, N_REPO, 192, D_EMBP, rs_r_out, nullptr);
    k_gemm_tc<true><<<grid(N_USER, 192), tb>>>(h_user, wc_u1,
        nullptr, feat_u, D_HID, raw_u, D_HID, D_HID, N_USER, 192, D_EMBP, rs_u_out, nullptr);
    k_spmm_out96<<<blocks(N_USER * 32L, T), T>>>(feat_r, rowptr_ru, col_ru, raw_u, rs_u_in,
                                                 b_hcu, b_hid_ru, out_user, N_USER);
    k_spmm_out96<<<blocks(N_REPO * 32L, T), T>>>(feat_u, rowptr_ur, col_ur, raw_r, rs_r_in,
                                                 b_hcr, b_hid_ur, out_repo, N_REPO);

    // ---- layer 2 ----
    k_gemm_tc<true><<<grid(N_REPO, 128), tb>>>(out_repo, wc_r2,
        nullptr, feat_r, D_OUT, raw_r, D_OUT, D_OUT, N_REPO, 128, D_HID, rs_r_out, nullptr);
    k_gemm_tc<true><<<grid(N_USER, 128), tb>>>(out_user, wc_u2,
        nullptr, feat_u, D_OUT, raw_u, D_OUT, D_OUT, N_USER, 128, D_HID, rs_u_out, nullptr);
    k_spmm_out64_norm<<<blocks(N_USER * 32L, T), T>>>(feat_r, rowptr_ru, col_ru, raw_u, rs_u_in,
                                                      b_ocu, b_out_ru, new_user, invn_u, N_USER);
    k_spmm_out64_norm<<<blocks(N_REPO * 32L, T), T>>>(feat_u, rowptr_ur, col_ur, raw_r, rs_r_in,
                                                      b_ocr, b_out_ur, new_repo, invn_r, N_REPO);

    // ---- cosine scores ----
    k_score_all<<<blocks(2L * NEP * 32, T), T>>>(new_user, new_repo, invn_u, invn_r,
                                                 pos_u, pos_r, neg_u, neg_r, out);
}

// round 5
// speedup vs baseline: 2.4638x; 1.0963x over previous
#include <cuda_runtime.h>
#include <cuda_fp16.h>
#include <math.h>

// ---------------- problem constants ----------------
#define N_USER 50000
#define N_REPO 100000
#define NE     1000000
#define NEP    200000
#define D_IN   256
#define D_EMB  125
#define D_HID  96
#define D_OUT  64

// ---------------- scratch (device globals) ----------------
__device__ __half g_feat_u[N_USER * D_HID];   // fp16 messages (reused @64 in layer 2)
__device__ __half g_feat_r[N_REPO * D_HID];
__device__ float  g_raw_u [N_USER * D_HID];
__device__ float  g_raw_r [N_REPO * D_HID];
__device__ float  g_out_user[N_USER * D_HID];
__device__ float  g_out_repo[N_REPO * D_HID];
__device__ float  g_new_user[N_USER * D_OUT];
__device__ float  g_new_repo[N_REPO * D_OUT];

__device__ int   g_cnt_u_out[N_USER];
__device__ int   g_cnt_u_in [N_USER];
__device__ int   g_cnt_r_out[N_REPO];
__device__ int   g_cnt_r_in [N_REPO];
__device__ float g_rs_u_out[N_USER], g_rs_u_in[N_USER];
__device__ float g_rs_r_out[N_REPO], g_rs_r_in[N_REPO];

__device__ int g_rowptr_ur[N_REPO + 1];
__device__ int g_rowptr_ru[N_USER + 1];
__device__ int g_cursor_ur[N_REPO];
__device__ int g_cursor_ru[N_USER];
__device__ int g_col_ur[NE];
__device__ int g_col_ru[NE];
__device__ int g_part[128];

__device__ float g_invn_u[N_USER];
__device__ float g_invn_r[N_REPO];

// folded layer-1 weights: WC = W_emb @ [W_msg | W_res]  (256 x 192), bc = b_emb @ [..]
__device__ float g_WC_u1[D_IN * 192];
__device__ float g_WC_r1[D_IN * 192];
__device__ float g_bc_u1[192];
__device__ float g_bc_r1[192];
// packed layer-2 weights: [96][ W_out | W_oc ]
__device__ float g_wc_u2[D_HID * 128];
__device__ float g_wc_r2[D_HID * 128];

// ---------------- preprocessing kernels ----------------
__global__ void k_pack2(const float* __restrict__ W_out_ur, const float* __restrict__ W_ocu,
                        const float* __restrict__ W_out_ru, const float* __restrict__ W_ocr) {
    int i = blockIdx.x * blockDim.x + threadIdx.x;
    if (i < 6144) { int k = i / 64, n = i % 64; g_wc_u2[k * 128 + n]      = W_out_ur[i]; return; }
    i -= 6144;
    if (i < 6144) { int k = i / 64, n = i % 64; g_wc_u2[k * 128 + 64 + n] = W_ocu[i]; return; }
    i -= 6144;
    if (i < 6144) { int k = i / 64, n = i % 64; g_wc_r2[k * 128 + n]      = W_out_ru[i]; return; }
    i -= 6144;
    if (i < 6144) { int k = i / 64, n = i % 64; g_wc_r2[k * 128 + 64 + n] = W_ocr[i]; return; }
}

// fold: WC[m][n] = sum_k W_e[m][k] * Wx[k][n'], bc[n] = sum_k b_e[k] * Wx[k][n']
__global__ void k_fold(const float* __restrict__ W_ue, const float* __restrict__ b_ue,
                       const float* __restrict__ W_hid_ur, const float* __restrict__ W_hcu,
                       const float* __restrict__ W_re, const float* __restrict__ b_re,
                       const float* __restrict__ W_hid_ru, const float* __restrict__ W_hcr) {
    const int PER = D_IN * 192;
    int i = blockIdx.x * blockDim.x + threadIdx.x;
    if (i < 2 * PER) {
        const float* We = (i < PER) ? W_ue : W_re;
        const float* Wm = (i < PER) ? W_hid_ur : W_hid_ru;
        const float* Wr = (i < PER) ? W_hcu : W_hcr;
        float* WC = (i < PER) ? g_WC_u1 : g_WC_r1;
        int j = (i < PER) ? i : i - PER;
        int m = j / 192, n = j % 192;
        const float* Wx = (n < 96) ? (Wm + n) : (Wr + n - 96);
        float a = 0.f;
        #pragma unroll 5
        for (int k = 0; k < D_EMB; k++) a += We[m * D_EMB + k] * Wx[k * 96];
        WC[m * 192 + n] = a;
        return;
    }
    i -= 2 * PER;
    if (i < 384) {
        const float* be = (i < 192) ? b_ue : b_re;
        const float* Wm = (i < 192) ? W_hid_ur : W_hid_ru;
        const float* Wr = (i < 192) ? W_hcu : W_hcr;
        float* bc = (i < 192) ? g_bc_u1 : g_bc_r1;
        int n = i % 192;
        const float* Wx = (n < 96) ? (Wm + n) : (Wr + n - 96);
        float a = 0.f;
        for (int k = 0; k < D_EMB; k++) a += be[k] * Wx[k * 96];
        bc[n] = a;
    }
}

__global__ void k_count_all(const int* __restrict__ ur_src, const int* __restrict__ ur_dst,
                            const int* __restrict__ ru_src, const int* __restrict__ ru_dst) {
    int i = blockIdx.x * blockDim.x + threadIdx.x;
    if (i < NE) {
        atomicAdd(&g_cnt_u_out[ur_src[i]], 1);
        atomicAdd(&g_cnt_r_in[ur_dst[i]], 1);
    } else if (i < 2 * NE) {
        int j = i - NE;
        atomicAdd(&g_cnt_r_out[ru_src[j]], 1);
        atomicAdd(&g_cnt_u_in[ru_dst[j]], 1);
    }
}

__global__ void k_rsqrt_all() {
    int i = blockIdx.x * blockDim.x + threadIdx.x;
    if (i < N_USER) { g_rs_u_out[i] = rsqrtf(fmaxf((float)g_cnt_u_out[i], 1.f)); return; }
    i -= N_USER;
    if (i < N_USER) { g_rs_u_in[i] = rsqrtf(fmaxf((float)g_cnt_u_in[i], 1.f)); return; }
    i -= N_USER;
    if (i < N_REPO) { g_rs_r_out[i] = rsqrtf(fmaxf((float)g_cnt_r_out[i], 1.f)); return; }
    i -= N_REPO;
    if (i < N_REPO) { g_rs_r_in[i] = rsqrtf(fmaxf((float)g_cnt_r_in[i], 1.f)); return; }
}

__global__ void k_scan_block(const int* __restrict__ cnt, int* rowptr, int* partial, int n) {
    __shared__ int sh[1024];
    int b = blockIdx.x, t = threadIdx.x;
    int i = b * 1024 + t;
    int v = (i < n) ? cnt[i] : 0;
    sh[t] = v;
    __syncthreads();
    for (int off = 1; off < 1024; off <<= 1) {
        int x = (t >= off) ? sh[t - off] : 0;
        __syncthreads();
        sh[t] += x;
        __syncthreads();
    }
    if (i < n) rowptr[i + 1] = sh[t];
    if (t == 1023) partial[b] = sh[1023];
}

__global__ void k_scan_part(int* partial, int nb) {
    __shared__ int sh[128];
    int t = threadIdx.x;
    int v = (t < nb) ? partial[t] : 0;
    sh[t] = v;
    __syncthreads();
    for (int off = 1; off < 128; off <<= 1) {
        int x = (t >= off) ? sh[t - off] : 0;
        __syncthreads();
        sh[t] += x;
        __syncthreads();
    }
    if (t < nb) partial[t] = sh[t] - v;
}

__global__ void k_scan_add(int* rowptr, int* cursor, const int* __restrict__ partial, int n) {
    int i = blockIdx.x * blockDim.x + threadIdx.x;
    if (i == 0) { rowptr[0] = 0; cursor[0] = 0; }
    if (i < n) {
        int v = rowptr[i + 1] + partial[i >> 10];
        rowptr[i + 1] = v;
        if (i + 1 < n) cursor[i + 1] = v;
    }
}

__global__ void k_fill_all(const int* __restrict__ ur_src, const int* __restrict__ ur_dst,
                           const int* __restrict__ ru_src, const int* __restrict__ ru_dst) {
    int i = blockIdx.x * blockDim.x + threadIdx.x;
    if (i < NE) {
        int p = atomicAdd(&g_cursor_ur[ur_dst[i]], 1);
        g_col_ur[p] = ur_src[i];
    } else if (i < 2 * NE) {
        int j = i - NE;
        int p = atomicAdd(&g_cursor_ru[ru_dst[j]], 1);
        g_col_ru[p] = ru_src[j];
    }
}

// ---------------- tf32 tensor-core GEMM ----------------
// acc = A @ W + bias;  n < nsplit -> C1h (fp16);  n >= nsplit -> C2 (fp32)
#define BM 128
#define BN 64
#define BK 32
#define AS 40
#define WS 40

__device__ __forceinline__ float to_tf32(float x) {
    float y;
    asm("cvt.rna.tf32.f32 %0, %1;" : "=f"(y) : "f"(x));
    return y;
}

__device__ __forceinline__ void mma_tf32(float c[4],
                                         unsigned a0, unsigned a1, unsigned a2, unsigned a3,
                                         unsigned b0, unsigned b1) {
    asm volatile(
        "mma.sync.aligned.m16n8k8.row.col.f32.tf32.tf32.f32 "
        "{%0,%1,%2,%3}, {%4,%5,%6,%7}, {%8,%9}, {%0,%1,%2,%3};"
        : "+f"(c[0]), "+f"(c[1]), "+f"(c[2]), "+f"(c[3])
        : "r"(a0), "r"(a1), "r"(a2), "r"(a3), "r"(b0), "r"(b1));
}

__global__ __launch_bounds__(128) void k_gemm_tc(
    const float* __restrict__ A, const float* __restrict__ W,
    __half* __restrict__ C1h, int ld1,
    float* __restrict__ C2, int ld2, int nsplit,
    int M, int N, int K,
    const float* __restrict__ bias)
{
    __shared__ float As_s[BM * AS];
    __shared__ float Ws_s[BN * WS];

    const int tid = threadIdx.x;
    const int warp = tid >> 5, lane = tid & 31;
    const int wm = (warp >> 1) * 64;
    const int wn = (warp & 1) * 32;
    const int m0 = blockIdx.y * BM;
    const int n0 = blockIdx.x * BN;
    const int r = lane >> 2, kc = lane & 3;

    float acc[4][4][4];
    #pragma unroll
    for (int a = 0; a < 4; a++)
        #pragma unroll
        for (int b = 0; b < 4; b++)
            #pragma unroll
            for (int c = 0; c < 4; c++) acc[a][b][c] = 0.f;

    float4 a4[8];
    float  wreg[16];

    const int am = m0 + tid;
    const bool ag = am < M;
    const float* Arow = A + (size_t)am * K;

    {
        #pragma unroll
        for (int j = 0; j < 8; j++)
            a4[j] = ag ? *(const float4*)(Arow + j * 4) : make_float4(0.f, 0.f, 0.f, 0.f);
        #pragma unroll
        for (int it = 0; it < 4; it++) {
            int idx = tid + it * 128;
            int n = idx & 63, h = idx >> 6;
            int p = h >> 1, hi = h & 1;
            const float* Wb = W + (size_t)(p * 8 + 2 * hi) * N + n0 + n;
            wreg[it * 4 + 0] = Wb[0];
            wreg[it * 4 + 1] = Wb[4 * N];
            wreg[it * 4 + 2] = Wb[1 * N];
            wreg[it * 4 + 3] = Wb[5 * N];
        }
    }

    const int T = K / BK;
    for (int t = 0; t < T; t++) {
        #pragma unroll
        for (int p = 0; p < 4; p++) {
            float4 lo = a4[2 * p], hi = a4[2 * p + 1];
            float4 q0 = make_float4(to_tf32(lo.x), to_tf32(hi.x), to_tf32(lo.y), to_tf32(hi.y));
            float4 q1 = make_float4(to_tf32(lo.z), to_tf32(hi.z), to_tf32(lo.w), to_tf32(hi.w));
            *(float4*)(As_s + tid * AS + p * 8)     = q0;
            *(float4*)(As_s + tid * AS + p * 8 + 4) = q1;
        }
        #pragma unroll
        for (int it = 0; it < 4; it++) {
            int idx = tid + it * 128;
            int n = idx & 63, h = idx >> 6;
            int p = h >> 1, hi = h & 1;
            float4 q = make_float4(to_tf32(wreg[it * 4 + 0]), to_tf32(wreg[it * 4 + 1]),
                                   to_tf32(wreg[it * 4 + 2]), to_tf32(wreg[it * 4 + 3]));
            *(float4*)(Ws_s + n * WS + p * 8 + hi * 4) = q;
        }
        __syncthreads();

        if (t + 1 < T) {
            int k0 = (t + 1) * BK;
            #pragma unroll
            for (int j = 0; j < 8; j++)
                a4[j] = ag ? *(const float4*)(Arow + k0 + j * 4) : make_float4(0.f, 0.f, 0.f, 0.f);
            #pragma unroll
            for (int it = 0; it < 4; it++) {
                int idx = tid + it * 128;
                int n = idx & 63, h = idx >> 6;
                int p = h >> 1, hi = h & 1;
                const float* Wb = W + (size_t)(k0 + p * 8 + 2 * hi) * N + n0 + n;
                wreg[it * 4 + 0] = Wb[0];
                wreg[it * 4 + 1] = Wb[4 * N];
                wreg[it * 4 + 2] = Wb[1 * N];
                wreg[it * 4 + 3] = Wb[5 * N];
            }
        }

        #pragma unroll
        for (int ka = 0; ka < 4; ka++) {
            int kb = ka * 8 + 2 * kc;
            unsigned af[4][4], bf[4][2];
            #pragma unroll
            for (int mt = 0; mt < 4; mt++) {
                float2 lo = *(const float2*)(As_s + (wm + mt * 16 + r) * AS + kb);
                float2 hi = *(const float2*)(As_s + (wm + mt * 16 + r + 8) * AS + kb);
                af[mt][0] = __float_as_uint(lo.x);
                af[mt][2] = __float_as_uint(lo.y);
                af[mt][1] = __float_as_uint(hi.x);
                af[mt][3] = __float_as_uint(hi.y);
            }
            #pragma unroll
            for (int nt = 0; nt < 4; nt++) {
                float2 b = *(const float2*)(Ws_s + (wn + nt * 8 + r) * WS + kb);
                bf[nt][0] = __float_as_uint(b.x);
                bf[nt][1] = __float_as_uint(b.y);
            }
            #pragma unroll
            for (int mt = 0; mt < 4; mt++)
                #pragma unroll
                for (int nt = 0; nt < 4; nt++)
                    mma_tf32(acc[mt][nt], af[mt][0], af[mt][1], af[mt][2], af[mt][3],
                             bf[nt][0], bf[nt][1]);
        }
        __syncthreads();
    }

    #pragma unroll
    for (int mt = 0; mt < 4; mt++) {
        #pragma unroll
        for (int i2 = 0; i2 < 2; i2++) {
            int m = m0 + wm + mt * 16 + r + i2 * 8;
            if (m >= M) continue;
            #pragma unroll
            for (int nt = 0; nt < 4; nt++) {
                int n = n0 + wn + nt * 8 + kc * 2;
                float v0 = acc[mt][nt][i2 * 2 + 0];
                float v1 = acc[mt][nt][i2 * 2 + 1];
                if (bias) { v0 += bias[n]; v1 += bias[n + 1]; }
                if (n < nsplit) {
                    __half2 h = __floats2half2_rn(v0, v1);
                    *(__half2*)(C1h + (size_t)m * ld1 + n) = h;
                } else {
                    *(float2*)(C2 + (size_t)m * ld2 + n - nsplit) = make_float2(v0, v1);
                }
            }
        }
    }
}

// ---------------- fused SpMM (per-edge src scale) + residual epilogue ----------------
// out[w,:] = relu(raw[w,:] + b1 + b2 + rs_in[w] * sum_e rs_src[col[e]] * feat[col[e],:])
__global__ void k_spmm_out96(const __half* __restrict__ feat, const int* __restrict__ rowptr,
                             const int* __restrict__ col, const float* __restrict__ rs_src,
                             const float* __restrict__ raw, const float* __restrict__ rs_in,
                             const float* __restrict__ b1, const float* __restrict__ b2,
                             float* __restrict__ out, int n_rows) {
    int w = (blockIdx.x * blockDim.x + threadIdx.x) >> 5;
    int lane = threadIdx.x & 31;
    if (w >= n_rows) return;
    int s = rowptr[w], e = rowptr[w + 1];
    bool act = lane < 24;
    int d = lane * 4;
    float4 a0 = make_float4(0.f, 0.f, 0.f, 0.f);
    float4 a1 = make_float4(0.f, 0.f, 0.f, 0.f);
    int i = s;
    for (; i + 1 < e; i += 2) {
        int c0 = col[i], c1 = col[i + 1];
        float s0 = rs_src[c0], s1 = rs_src[c1];
        if (act) {
            uint2 q0 = *(const uint2*)(feat + (size_t)c0 * 96 + d);
            uint2 q1 = *(const uint2*)(feat + (size_t)c1 * 96 + d);
            float2 f00 = __half22float2(*(__half2*)&q0.x);
            float2 f01 = __half22float2(*(__half2*)&q0.y);
            float2 f10 = __half22float2(*(__half2*)&q1.x);
            float2 f11 = __half22float2(*(__half2*)&q1.y);
            a0.x += f00.x * s0; a0.y += f00.y * s0; a0.z += f01.x * s0; a0.w += f01.y * s0;
            a1.x += f10.x * s1; a1.y += f10.y * s1; a1.z += f11.x * s1; a1.w += f11.y * s1;
        }
    }
    if (i < e) {
        int c0 = col[i];
        float s0 = rs_src[c0];
        if (act) {
            uint2 q0 = *(const uint2*)(feat + (size_t)c0 * 96 + d);
            float2 f00 = __half22float2(*(__half2*)&q0.x);
            float2 f01 = __half22float2(*(__half2*)&q0.y);
            a0.x += f00.x * s0; a0.y += f00.y * s0; a0.z += f01.x * s0; a0.w += f01.y * s0;
        }
    }
    if (act) {
        float sc = rs_in[w];
        float4 r4 = *(const float4*)(raw + (size_t)w * 96 + d);
        float4 o;
        o.x = fmaxf(r4.x + b1[d + 0] + b2[d + 0] + (a0.x + a1.x) * sc, 0.f);
        o.y = fmaxf(r4.y + b1[d + 1] + b2[d + 1] + (a0.y + a1.y) * sc, 0.f);
        o.z = fmaxf(r4.z + b1[d + 2] + b2[d + 2] + (a0.z + a1.z) * sc, 0.f);
        o.w = fmaxf(r4.w + b1[d + 3] + b2[d + 3] + (a0.w + a1.w) * sc, 0.f);
        *(float4*)(out + (size_t)w * 96 + d) = o;
    }
}

__global__ void k_spmm_out64_norm(const __half* __restrict__ feat, const int* __restrict__ rowptr,
                                  const int* __restrict__ col, const float* __restrict__ rs_src,
                                  const float* __restrict__ raw, const float* __restrict__ rs_in,
                                  const float* __restrict__ b1, const float* __restrict__ b2,
                                  float* __restrict__ out, float* __restrict__ invn, int n_rows) {
    int w = (blockIdx.x * blockDim.x + threadIdx.x) >> 5;
    int lane = threadIdx.x & 31;
    if (w >= n_rows) return;
    int s = rowptr[w], e = rowptr[w + 1];
    bool act = lane < 16;
    int d = lane * 4;
    float4 a0 = make_float4(0.f, 0.f, 0.f, 0.f);
    float4 a1 = make_float4(0.f, 0.f, 0.f, 0.f);
    int i = s;
    for (; i + 1 < e; i += 2) {
        int c0 = col[i], c1 = col[i + 1];
        float s0 = rs_src[c0], s1 = rs_src[c1];
        if (act) {
            uint2 q0 = *(const uint2*)(feat + (size_t)c0 * 64 + d);
            uint2 q1 = *(const uint2*)(feat + (size_t)c1 * 64 + d);
            float2 f00 = __half22float2(*(__half2*)&q0.x);
            float2 f01 = __half22float2(*(__half2*)&q0.y);
            float2 f10 = __half22float2(*(__half2*)&q1.x);
            float2 f11 = __half22float2(*(__half2*)&q1.y);
            a0.x += f00.x * s0; a0.y += f00.y * s0; a0.z += f01.x * s0; a0.w += f01.y * s0;
            a1.x += f10.x * s1; a1.y += f10.y * s1; a1.z += f11.x * s1; a1.w += f11.y * s1;
        }
    }
    if (i < e) {
        int c0 = col[i];
        float s0 = rs_src[c0];
        if (act) {
            uint2 q0 = *(const uint2*)(feat + (size_t)c0 * 64 + d);
            float2 f00 = __half22float2(*(__half2*)&q0.x);
            float2 f01 = __half22float2(*(__half2*)&q0.y);
            a0.x += f00.x * s0; a0.y += f00.y * s0; a0.z += f01.x * s0; a0.w += f01.y * s0;
        }
    }
    float sq = 0.f;
    if (act) {
        float sc = rs_in[w];
        float4 r4 = *(const float4*)(raw + (size_t)w * 64 + d);
        float4 o;
        o.x = fmaxf(r4.x + b1[d + 0] + b2[d + 0] + (a0.x + a1.x) * sc, 0.f);
        o.y = fmaxf(r4.y + b1[d + 1] + b2[d + 1] + (a0.y + a1.y) * sc, 0.f);
        o.z = fmaxf(r4.z + b1[d + 2] + b2[d + 2] + (a0.z + a1.z) * sc, 0.f);
        o.w = fmaxf(r4.w + b1[d + 3] + b2[d + 3] + (a0.w + a1.w) * sc, 0.f);
        *(float4*)(out + (size_t)w * 64 + d) = o;
        sq = o.x * o.x + o.y * o.y + o.z * o.z + o.w * o.w;
    }
    #pragma unroll
    for (int off = 16; off; off >>= 1) sq += __shfl_xor_sync(0xffffffffu, sq, off);
    if (lane == 0) invn[w] = 1.0f / fmaxf(sqrtf(sq), 1e-12f);
}

// ---------------- score (pos+neg in one launch) ----------------
__global__ void k_score_all(const float* __restrict__ hu, const float* __restrict__ hr,
                            const float* __restrict__ invn_u, const float* __restrict__ invn_r,
                            const int* __restrict__ pos_u, const int* __restrict__ pos_r,
                            const int* __restrict__ neg_u, const int* __restrict__ neg_r,
                            float* __restrict__ out) {
    int w = (blockIdx.x * blockDim.x + threadIdx.x) >> 5;
    int lane = threadIdx.x & 31;
    if (w >= 2 * NEP) return;
    int u, r;
    if (w < NEP) { u = pos_u[w]; r = pos_r[w]; }
    else         { u = neg_u[w - NEP]; r = neg_r[w - NEP]; }
    const float* a = hu + (size_t)u * D_OUT;
    const float* b = hr + (size_t)r * D_OUT;
    float s = a[lane] * b[lane] + a[lane + 32] * b[lane + 32];
    #pragma unroll
    for (int off = 16; off; off >>= 1) s += __shfl_xor_sync(0xffffffffu, s, off);
    if (lane == 0) out[w] = s * invn_u[u] * invn_r[r];
}

// ---------------- host ----------------
static inline void* sym(const void* s) {
    void* p = nullptr;
    cudaGetSymbolAddress(&p, s);
    return p;
}

extern "C" void kernel_launch(void* const* d_in, const int* in_sizes, int n_in,
                              void* d_out, int out_size) {
    const float* user_feat = (const float*)d_in[0];
    const float* repo_feat = (const float*)d_in[1];
    const float* W_ue = (const float*)d_in[2];   const float* b_ue = (const float*)d_in[3];
    const float* W_re = (const float*)d_in[4];   const float* b_re = (const float*)d_in[5];
    const float* W_hid_ur = (const float*)d_in[6];  const float* b_hid_ur = (const float*)d_in[7];
    const float* W_hid_ru = (const float*)d_in[8];  const float* b_hid_ru = (const float*)d_in[9];
    const float* W_out_ur = (const float*)d_in[10]; const float* b_out_ur = (const float*)d_in[11];
    const float* W_out_ru = (const float*)d_in[12]; const float* b_out_ru = (const float*)d_in[13];
    const float* W_hcu = (const float*)d_in[14]; const float* b_hcu = (const float*)d_in[15];
    const float* W_hcr = (const float*)d_in[16]; const float* b_hcr = (const float*)d_in[17];
    const float* W_ocu = (const float*)d_in[18]; const float* b_ocu = (const float*)d_in[19];
    const float* W_ocr = (const float*)d_in[20]; const float* b_ocr = (const float*)d_in[21];
    const int* e_ur_src = (const int*)d_in[22];
    const int* e_ur_dst = (const int*)d_in[23];
    const int* e_ru_src = (const int*)d_in[24];
    const int* e_ru_dst = (const int*)d_in[25];
    const int* pos_u = (const int*)d_in[26];
    const int* pos_r = (const int*)d_in[27];
    const int* neg_u = (const int*)d_in[28];
    const int* neg_r = (const int*)d_in[29];
    float* out = (float*)d_out;

    __half* feat_u = (__half*)sym(g_feat_u);
    __half* feat_r = (__half*)sym(g_feat_r);
    float*  raw_u  = (float*)sym(g_raw_u);
    float*  raw_r  = (float*)sym(g_raw_r);
    float*  out_user = (float*)sym(g_out_user);
    float*  out_repo = (float*)sym(g_out_repo);
    float*  new_user = (float*)sym(g_new_user);
    float*  new_repo = (float*)sym(g_new_repo);
    int* cnt_u_out = (int*)sym(g_cnt_u_out);
    int* cnt_u_in  = (int*)sym(g_cnt_u_in);
    int* cnt_r_out = (int*)sym(g_cnt_r_out);
    int* cnt_r_in  = (int*)sym(g_cnt_r_in);
    float* rs_u_out = (float*)sym(g_rs_u_out);
    float* rs_u_in  = (float*)sym(g_rs_u_in);
    float* rs_r_out = (float*)sym(g_rs_r_out);
    float* rs_r_in  = (float*)sym(g_rs_r_in);
    int* rowptr_ur = (int*)sym(g_rowptr_ur);
    int* rowptr_ru = (int*)sym(g_rowptr_ru);
    int* cursor_ur = (int*)sym(g_cursor_ur);
    int* cursor_ru = (int*)sym(g_cursor_ru);
    int* col_ur = (int*)sym(g_col_ur);
    int* col_ru = (int*)sym(g_col_ru);
    int* part   = (int*)sym(g_part);
    float* invn_u = (float*)sym(g_invn_u);
    float* invn_r = (float*)sym(g_invn_r);
    float* WC_u1 = (float*)sym(g_WC_u1);
    float* WC_r1 = (float*)sym(g_WC_r1);
    float* bc_u1 = (float*)sym(g_bc_u1);
    float* bc_r1 = (float*)sym(g_bc_r1);
    float* wc_u2 = (float*)sym(g_wc_u2);
    float* wc_r2 = (float*)sym(g_wc_r2);

    const int T = 256;
    auto blocks = [](long n, int t) { return (int)((n + t - 1) / t); };

    // ---- memsets (degree counters only) ----
    cudaMemsetAsync(cnt_u_out, 0, N_USER * sizeof(int), 0);
    cudaMemsetAsync(cnt_u_in,  0, N_USER * sizeof(int), 0);
    cudaMemsetAsync(cnt_r_out, 0, N_REPO * sizeof(int), 0);
    cudaMemsetAsync(cnt_r_in,  0, N_REPO * sizeof(int), 0);

    // (1) pack layer-2 weights
    k_pack2<<<blocks(4 * 6144, T), T>>>(W_out_ur, W_ocu, W_out_ru, W_ocr);
    // (2) fold layer-1 weights: WC = W_e @ [W_msg | W_res]
    k_fold<<<blocks(2L * D_IN * 192 + 384, T), T>>>(W_ue, b_ue, W_hid_ur, W_hcu,
                                                    W_re, b_re, W_hid_ru, W_hcr);
    // (3) degree counts
    k_count_all<<<blocks(2L * NE, T), T>>>(e_ur_src, e_ur_dst, e_ru_src, e_ru_dst);

    dim3 tb(128);
    auto grid = [](int M, int N) { return dim3(N / BN, (M + BM - 1) / BM); };

    // (4)(5)(6) layer-1 fused GEMMs: X @ WC + bc -> [feat fp16 | raw fp32]
    const int MR_HALF = 50048;  // 391 * 128
    k_gemm_tc<<<grid(MR_HALF, 192), tb>>>(repo_feat, WC_r1,
        feat_r, D_HID, raw_r, D_HID, D_HID, MR_HALF, 192, D_IN, bc_r1);
    k_gemm_tc<<<grid(N_REPO - MR_HALF, 192), tb>>>(repo_feat + (size_t)MR_HALF * D_IN, WC_r1,
        feat_r + (size_t)MR_HALF * D_HID, D_HID, raw_r + (size_t)MR_HALF * D_HID, D_HID, D_HID,
        N_REPO - MR_HALF, 192, D_IN, bc_r1);
    k_gemm_tc<<<grid(N_USER, 192), tb>>>(user_feat, WC_u1,
        feat_u, D_HID, raw_u, D_HID, D_HID, N_USER, 192, D_IN, bc_u1);

    // (7+) graph structure
    k_rsqrt_all<<<blocks(2L * (N_USER + N_REPO), T), T>>>();
    int nb_r = (N_REPO + 1023) / 1024;
    int nb_u = (N_USER + 1023) / 1024;
    k_scan_block<<<nb_r, 1024>>>(cnt_r_in, rowptr_ur, part, N_REPO);
    k_scan_part<<<1, 128>>>(part, nb_r);
    k_scan_add<<<blocks(N_REPO, T), T>>>(rowptr_ur, cursor_ur, part, N_REPO);
    k_scan_block<<<nb_u, 1024>>>(cnt_u_in, rowptr_ru, part, N_USER);
    k_scan_part<<<1, 128>>>(part, nb_u);
    k_scan_add<<<blocks(N_USER, T), T>>>(rowptr_ru, cursor_ru, part, N_USER);
    k_fill_all<<<blocks(2L * NE, T), T>>>(e_ur_src, e_ur_dst, e_ru_src, e_ru_dst);

    // layer-1 SpMM + residual
    k_spmm_out96<<<blocks(N_USER * 32L, T), T>>>(feat_r, rowptr_ru, col_ru, rs_r_out,
                                                 raw_u, rs_u_in, b_hcu, b_hid_ru,
                                                 out_user, N_USER);
    k_spmm_out96<<<blocks(N_REPO * 32L, T), T>>>(feat_u, rowptr_ur, col_ur, rs_u_out,
                                                 raw_r, rs_r_in, b_hcr, b_hid_ur,
                                                 out_repo, N_REPO);

    // layer-2 GEMMs
    k_gemm_tc<<<grid(N_REPO, 128), tb>>>(out_repo, wc_r2,
        feat_r, D_OUT, raw_r, D_OUT, D_OUT, N_REPO, 128, D_HID, nullptr);
    k_gemm_tc<<<grid(N_USER, 128), tb>>>(out_user, wc_u2,
        feat_u, D_OUT, raw_u, D_OUT, D_OUT, N_USER, 128, D_HID, nullptr);

    // layer-2 SpMM + residual + norm
    k_spmm_out64_norm<<<blocks(N_USER * 32L, T), T>>>(feat_r, rowptr_ru, col_ru, rs_r_out,
                                                      raw_u, rs_u_in, b_ocu, b_out_ru,
                                                      new_user, invn_u, N_USER);
    k_spmm_out64_norm<<<blocks(N_REPO * 32L, T), T>>>(feat_u, rowptr_ur, col_ur, rs_u_out,
                                                      raw_r, rs_r_in, b_ocr, b_out_ur,
                                                      new_repo, invn_r, N_REPO);

    // cosine scores
    k_score_all<<<blocks(2L * NEP * 32, T), T>>>(new_user, new_repo, invn_u, invn_r,
                                                 pos_u, pos_r, neg_u, neg_r, out);
}

// round 6
// speedup vs baseline: 2.7054x; 1.0980x over previous
#include <cuda_runtime.h>
#include <cuda_fp16.h>
#include <math.h>

// ---------------- problem constants ----------------
#define N_USER 50000
#define N_REPO 100000
#define NE     1000000
#define NEP    200000
#define D_IN   256
#define D_EMB  125
#define D_HID  96
#define D_OUT  64

// ---------------- scratch (device globals) ----------------
__device__ __half g_feat_u[N_USER * D_HID];   // fp16 messages (reused @64 in layer 2)
__device__ __half g_feat_r[N_REPO * D_HID];
__device__ float  g_raw_u [N_USER * D_HID];
__device__ float  g_raw_r [N_REPO * D_HID];
__device__ float  g_out_user[N_USER * D_HID];
__device__ float  g_out_repo[N_REPO * D_HID];
__device__ float  g_new_user[N_USER * D_OUT];
__device__ float  g_new_repo[N_REPO * D_OUT];

__device__ int   g_cnt_u_out[N_USER];
__device__ int   g_cnt_u_in [N_USER];
__device__ int   g_cnt_r_out[N_REPO];
__device__ int   g_cnt_r_in [N_REPO];
__device__ float g_rs_u_out[N_USER], g_rs_u_in[N_USER];
__device__ float g_rs_r_out[N_REPO], g_rs_r_in[N_REPO];

__device__ int g_rowptr_ur[N_REPO + 1];
__device__ int g_rowptr_ru[N_USER + 1];
__device__ int g_cursor_ur[N_REPO];
__device__ int g_cursor_ru[N_USER];
__device__ int g_col_ur[NE];
__device__ int g_col_ru[NE];
__device__ int g_part[128];

__device__ float g_invn_u[N_USER];
__device__ float g_invn_r[N_REPO];

// folded layer-1 weights: WC = W_emb @ [W_msg | W_res]  (256 x 192)
__device__ float g_WC_u1[D_IN * 192];
__device__ float g_WC_r1[D_IN * 192];
__device__ float g_bc_u1[192];
__device__ float g_bc_r1[192];
// packed layer-2 weights: [96][ W_out | W_oc ]
__device__ float g_wc_u2[D_HID * 128];
__device__ float g_wc_r2[D_HID * 128];

// ---------------- preprocessing kernels ----------------
__global__ void k_pack2(const float* __restrict__ W_out_ur, const float* __restrict__ W_ocu,
                        const float* __restrict__ W_out_ru, const float* __restrict__ W_ocr) {
    int i = blockIdx.x * blockDim.x + threadIdx.x;
    if (i < 6144) { int k = i / 64, n = i % 64; g_wc_u2[k * 128 + n]      = W_out_ur[i]; return; }
    i -= 6144;
    if (i < 6144) { int k = i / 64, n = i % 64; g_wc_u2[k * 128 + 64 + n] = W_ocu[i]; return; }
    i -= 6144;
    if (i < 6144) { int k = i / 64, n = i % 64; g_wc_r2[k * 128 + n]      = W_out_ru[i]; return; }
    i -= 6144;
    if (i < 6144) { int k = i / 64, n = i % 64; g_wc_r2[k * 128 + 64 + n] = W_ocr[i]; return; }
}

__global__ void k_fold(const float* __restrict__ W_ue, const float* __restrict__ b_ue,
                       const float* __restrict__ W_hid_ur, const float* __restrict__ W_hcu,
                       const float* __restrict__ W_re, const float* __restrict__ b_re,
                       const float* __restrict__ W_hid_ru, const float* __restrict__ W_hcr) {
    const int PER = D_IN * 192;
    int i = blockIdx.x * blockDim.x + threadIdx.x;
    if (i < 2 * PER) {
        const float* We = (i < PER) ? W_ue : W_re;
        const float* Wm = (i < PER) ? W_hid_ur : W_hid_ru;
        const float* Wr = (i < PER) ? W_hcu : W_hcr;
        float* WC = (i < PER) ? g_WC_u1 : g_WC_r1;
        int j = (i < PER) ? i : i - PER;
        int m = j / 192, n = j % 192;
        const float* Wx = (n < 96) ? (Wm + n) : (Wr + n - 96);
        float a = 0.f;
        #pragma unroll 5
        for (int k = 0; k < D_EMB; k++) a += We[m * D_EMB + k] * Wx[k * 96];
        WC[m * 192 + n] = a;
        return;
    }
    i -= 2 * PER;
    if (i < 384) {
        const float* be = (i < 192) ? b_ue : b_re;
        const float* Wm = (i < 192) ? W_hid_ur : W_hid_ru;
        const float* Wr = (i < 192) ? W_hcu : W_hcr;
        float* bc = (i < 192) ? g_bc_u1 : g_bc_r1;
        int n = i % 192;
        const float* Wx = (n < 96) ? (Wm + n) : (Wr + n - 96);
        float a = 0.f;
        for (int k = 0; k < D_EMB; k++) a += be[k] * Wx[k * 96];
        bc[n] = a;
    }
}

__global__ void k_count_all(const int* __restrict__ ur_src, const int* __restrict__ ur_dst,
                            const int* __restrict__ ru_src, const int* __restrict__ ru_dst) {
    int i = blockIdx.x * blockDim.x + threadIdx.x;
    if (i < NE) {
        atomicAdd(&g_cnt_u_out[ur_src[i]], 1);
        atomicAdd(&g_cnt_r_in[ur_dst[i]], 1);
    } else if (i < 2 * NE) {
        int j = i - NE;
        atomicAdd(&g_cnt_r_out[ru_src[j]], 1);
        atomicAdd(&g_cnt_u_in[ru_dst[j]], 1);
    }
}

__global__ void k_rsqrt_all() {
    int i = blockIdx.x * blockDim.x + threadIdx.x;
    if (i < N_USER) { g_rs_u_out[i] = rsqrtf(fmaxf((float)g_cnt_u_out[i], 1.f)); return; }
    i -= N_USER;
    if (i < N_USER) { g_rs_u_in[i] = rsqrtf(fmaxf((float)g_cnt_u_in[i], 1.f)); return; }
    i -= N_USER;
    if (i < N_REPO) { g_rs_r_out[i] = rsqrtf(fmaxf((float)g_cnt_r_out[i], 1.f)); return; }
    i -= N_REPO;
    if (i < N_REPO) { g_rs_r_in[i] = rsqrtf(fmaxf((float)g_cnt_r_in[i], 1.f)); return; }
}

__global__ void k_scan_block(const int* __restrict__ cnt, int* rowptr, int* partial, int n) {
    __shared__ int sh[1024];
    int b = blockIdx.x, t = threadIdx.x;
    int i = b * 1024 + t;
    int v = (i < n) ? cnt[i] : 0;
    sh[t] = v;
    __syncthreads();
    for (int off = 1; off < 1024; off <<= 1) {
        int x = (t >= off) ? sh[t - off] : 0;
        __syncthreads();
        sh[t] += x;
        __syncthreads();
    }
    if (i < n) rowptr[i + 1] = sh[t];
    if (t == 1023) partial[b] = sh[1023];
}

__global__ void k_scan_part(int* partial, int nb) {
    __shared__ int sh[128];
    int t = threadIdx.x;
    int v = (t < nb) ? partial[t] : 0;
    sh[t] = v;
    __syncthreads();
    for (int off = 1; off < 128; off <<= 1) {
        int x = (t >= off) ? sh[t - off] : 0;
        __syncthreads();
        sh[t] += x;
        __syncthreads();
    }
    if (t < nb) partial[t] = sh[t] - v;
}

__global__ void k_scan_add(int* rowptr, int* cursor, const int* __restrict__ partial, int n) {
    int i = blockIdx.x * blockDim.x + threadIdx.x;
    if (i == 0) { rowptr[0] = 0; cursor[0] = 0; }
    if (i < n) {
        int v = rowptr[i + 1] + partial[i >> 10];
        rowptr[i + 1] = v;
        if (i + 1 < n) cursor[i + 1] = v;
    }
}

__global__ void k_fill_all(const int* __restrict__ ur_src, const int* __restrict__ ur_dst,
                           const int* __restrict__ ru_src, const int* __restrict__ ru_dst) {
    int i = blockIdx.x * blockDim.x + threadIdx.x;
    if (i < NE) {
        int p = atomicAdd(&g_cursor_ur[ur_dst[i]], 1);
        g_col_ur[p] = ur_src[i];
    } else if (i < 2 * NE) {
        int j = i - NE;
        int p = atomicAdd(&g_cursor_ru[ru_dst[j]], 1);
        g_col_ru[p] = ru_src[j];
    }
}

// ---------------- fp16 tensor-core GEMM (m16n8k16 + ldmatrix) ----------------
// acc = A @ W + bias;  n < nsplit -> C1h (fp16);  n >= nsplit -> C2 (fp32)
#define BM 128
#define BN 64
#define BK 32
#define APITCH 40   // halves per A row (80 B) -> conflict-free ldmatrix/STS
#define BPITCH 40

__device__ __forceinline__ void mma_f16(float c[4],
                                        unsigned a0, unsigned a1, unsigned a2, unsigned a3,
                                        unsigned b0, unsigned b1) {
    asm volatile(
        "mma.sync.aligned.m16n8k16.row.col.f32.f16.f16.f32 "
        "{%0,%1,%2,%3}, {%4,%5,%6,%7}, {%8,%9}, {%0,%1,%2,%3};"
        : "+f"(c[0]), "+f"(c[1]), "+f"(c[2]), "+f"(c[3])
        : "r"(a0), "r"(a1), "r"(a2), "r"(a3), "r"(b0), "r"(b1));
}

__device__ __forceinline__ void ldsm_x4(unsigned& r0, unsigned& r1, unsigned& r2, unsigned& r3,
                                        unsigned addr) {
    asm volatile("ldmatrix.sync.aligned.m8n8.x4.shared.b16 {%0,%1,%2,%3}, [%4];"
                 : "=r"(r0), "=r"(r1), "=r"(r2), "=r"(r3) : "r"(addr));
}

__global__ __launch_bounds__(128) void k_gemm_tc(
    const float* __restrict__ A, const float* __restrict__ W,
    __half* __restrict__ C1h, int ld1,
    float* __restrict__ C2, int ld2, int nsplit,
    int M, int N, int K,
    const float* __restrict__ bias)
{
    __shared__ __half As_s[BM * APITCH];
    __shared__ __half Bs_s[BN * BPITCH];

    const int tid = threadIdx.x;
    const int warp = tid >> 5, lane = tid & 31;
    const int wm = (warp >> 1) * 64;   // warp tile 64x32
    const int wn = (warp & 1) * 32;
    const int m0 = blockIdx.y * BM;
    const int n0 = blockIdx.x * BN;
    const int r = lane >> 2, kc = lane & 3;

    float acc[4][4][4];
    #pragma unroll
    for (int a = 0; a < 4; a++)
        #pragma unroll
        for (int b = 0; b < 4; b++)
            #pragma unroll
            for (int c = 0; c < 4; c++) acc[a][b][c] = 0.f;

    float4 a4[8];
    float  wreg[16];

    // A staging: thread <-> row m0+tid
    const int am = m0 + tid;
    const bool ag = am < M;
    const float* Arow = A + (size_t)am * K;
    // W staging: thread covers n = tid&63, k-range (tid>>6)*16 .. +15
    const int wn_idx = tid & 63;
    const int wkb = (tid >> 6) * 16;
    const float* Wcol = W + n0 + wn_idx;

    // ldmatrix per-thread address bases
    const unsigned as_base = (unsigned)__cvta_generic_to_shared(As_s);
    const unsigned bs_base = (unsigned)__cvta_generic_to_shared(Bs_s);
    const int q = lane >> 3, lr = lane & 7;
    const unsigned a_lm = as_base + (((wm + (q & 1) * 8 + lr) * APITCH + (q >> 1) * 8) << 1);
    const unsigned b_lm = bs_base + (((wn + (q >> 1) * 8 + lr) * BPITCH + (q & 1) * 8) << 1);

    // ---- prologue: load tile 0 ----
    #pragma unroll
    for (int j = 0; j < 8; j++)
        a4[j] = ag ? *(const float4*)(Arow + j * 4) : make_float4(0.f, 0.f, 0.f, 0.f);
    #pragma unroll
    for (int j = 0; j < 16; j++)
        wreg[j] = Wcol[(size_t)(wkb + j) * N];

    const int T = K / BK;
    for (int t = 0; t < T; t++) {
        // ---- STS A: 4 chunks of 8 halves (16B) per row ----
        #pragma unroll
        for (int c = 0; c < 4; c++) {
            float4 lo = a4[2 * c], hi = a4[2 * c + 1];
            __half2 hh[4];
            hh[0] = __floats2half2_rn(lo.x, lo.y);
            hh[1] = __floats2half2_rn(lo.z, lo.w);
            hh[2] = __floats2half2_rn(hi.x, hi.y);
            hh[3] = __floats2half2_rn(hi.z, hi.w);
            *(uint4*)&As_s[tid * APITCH + c * 8] = *(uint4*)hh;
        }
        // ---- STS B: 16 halves contiguous along k ----
        {
            __half2 hh[8];
            #pragma unroll
            for (int p = 0; p < 8; p++)
                hh[p] = __floats2half2_rn(wreg[2 * p], wreg[2 * p + 1]);
            *(uint4*)&Bs_s[wn_idx * BPITCH + wkb]     = *(uint4*)&hh[0];
            *(uint4*)&Bs_s[wn_idx * BPITCH + wkb + 8] = *(uint4*)&hh[4];
        }
        __syncthreads();

        // ---- prefetch next tile ----
        if (t + 1 < T) {
            int k0 = (t + 1) * BK;
            #pragma unroll
            for (int j = 0; j < 8; j++)
                a4[j] = ag ? *(const float4*)(Arow + k0 + j * 4) : make_float4(0.f, 0.f, 0.f, 0.f);
            #pragma unroll
            for (int j = 0; j < 16; j++)
                wreg[j] = Wcol[(size_t)(k0 + wkb + j) * N];
        }

        // ---- compute: 2 k16-groups ----
        #pragma unroll
        for (int g = 0; g < 2; g++) {
            unsigned af[4][4], bf[4][2];
            #pragma unroll
            for (int mt = 0; mt < 4; mt++)
                ldsm_x4(af[mt][0], af[mt][1], af[mt][2], af[mt][3],
                        a_lm + ((mt * 16 * APITCH + g * 16) << 1));
            #pragma unroll
            for (int np = 0; np < 2; np++) {
                unsigned r0, r1, r2, r3;
                ldsm_x4(r0, r1, r2, r3, b_lm + ((np * 16 * BPITCH + g * 16) << 1));
                bf[2 * np][0] = r0;  bf[2 * np][1] = r1;
                bf[2 * np + 1][0] = r2;  bf[2 * np + 1][1] = r3;
            }
            #pragma unroll
            for (int mt = 0; mt < 4; mt++)
                #pragma unroll
                for (int nt = 0; nt < 4; nt++)
                    mma_f16(acc[mt][nt], af[mt][0], af[mt][1], af[mt][2], af[mt][3],
                            bf[nt][0], bf[nt][1]);
        }
        __syncthreads();
    }

    // ---- epilogue ----
    #pragma unroll
    for (int mt = 0; mt < 4; mt++) {
        #pragma unroll
        for (int i2 = 0; i2 < 2; i2++) {
            int m = m0 + wm + mt * 16 + r + i2 * 8;
            if (m >= M) continue;
            #pragma unroll
            for (int nt = 0; nt < 4; nt++) {
                int n = n0 + wn + nt * 8 + kc * 2;
                float v0 = acc[mt][nt][i2 * 2 + 0];
                float v1 = acc[mt][nt][i2 * 2 + 1];
                if (bias) { v0 += bias[n]; v1 += bias[n + 1]; }
                if (n < nsplit) {
                    __half2 h = __floats2half2_rn(v0, v1);
                    *(__half2*)(C1h + (size_t)m * ld1 + n) = h;
                } else {
                    *(float2*)(C2 + (size_t)m * ld2 + n - nsplit) = make_float2(v0, v1);
                }
            }
        }
    }
}

// ---------------- fused SpMM (per-edge src scale) + residual epilogue ----------------
__global__ void k_spmm_out96(const __half* __restrict__ feat, const int* __restrict__ rowptr,
                             const int* __restrict__ col, const float* __restrict__ rs_src,
                             const float* __restrict__ raw, const float* __restrict__ rs_in,
                             const float* __restrict__ b1, const float* __restrict__ b2,
                             float* __restrict__ out, int n_rows) {
    int w = (blockIdx.x * blockDim.x + threadIdx.x) >> 5;
    int lane = threadIdx.x & 31;
    if (w >= n_rows) return;
    int s = rowptr[w], e = rowptr[w + 1];
    bool act = lane < 24;
    int d = lane * 4;
    float4 a0 = make_float4(0.f, 0.f, 0.f, 0.f);
    float4 a1 = make_float4(0.f, 0.f, 0.f, 0.f);
    int i = s;
    for (; i + 3 < e; i += 4) {
        int c0 = col[i], c1 = col[i + 1], c2 = col[i + 2], c3 = col[i + 3];
        float s0 = rs_src[c0], s1 = rs_src[c1], s2 = rs_src[c2], s3 = rs_src[c3];
        if (act) {
            uint2 q0 = *(const uint2*)(feat + (size_t)c0 * 96 + d);
            uint2 q1 = *(const uint2*)(feat + (size_t)c1 * 96 + d);
            uint2 q2 = *(const uint2*)(feat + (size_t)c2 * 96 + d);
            uint2 q3 = *(const uint2*)(feat + (size_t)c3 * 96 + d);
            float2 f;
            f = __half22float2(*(__half2*)&q0.x); a0.x += f.x * s0; a0.y += f.y * s0;
            f = __half22float2(*(__half2*)&q0.y); a0.z += f.x * s0; a0.w += f.y * s0;
            f = __half22float2(*(__half2*)&q1.x); a1.x += f.x * s1; a1.y += f.y * s1;
            f = __half22float2(*(__half2*)&q1.y); a1.z += f.x * s1; a1.w += f.y * s1;
            f = __half22float2(*(__half2*)&q2.x); a0.x += f.x * s2; a0.y += f.y * s2;
            f = __half22float2(*(__half2*)&q2.y); a0.z += f.x * s2; a0.w += f.y * s2;
            f = __half22float2(*(__half2*)&q3.x); a1.x += f.x * s3; a1.y += f.y * s3;
            f = __half22float2(*(__half2*)&q3.y); a1.z += f.x * s3; a1.w += f.y * s3;
        }
    }
    for (; i < e; i++) {
        int c0 = col[i];
        float s0 = rs_src[c0];
        if (act) {
            uint2 q0 = *(const uint2*)(feat + (size_t)c0 * 96 + d);
            float2 f;
            f = __half22float2(*(__half2*)&q0.x); a0.x += f.x * s0; a0.y += f.y * s0;
            f = __half22float2(*(__half2*)&q0.y); a0.z += f.x * s0; a0.w += f.y * s0;
        }
    }
    if (act) {
        float sc = rs_in[w];
        float4 r4 = *(const float4*)(raw + (size_t)w * 96 + d);
        float4 o;
        o.x = fmaxf(r4.x + b1[d + 0] + b2[d + 0] + (a0.x + a1.x) * sc, 0.f);
        o.y = fmaxf(r4.y + b1[d + 1] + b2[d + 1] + (a0.y + a1.y) * sc, 0.f);
        o.z = fmaxf(r4.z + b1[d + 2] + b2[d + 2] + (a0.z + a1.z) * sc, 0.f);
        o.w = fmaxf(r4.w + b1[d + 3] + b2[d + 3] + (a0.w + a1.w) * sc, 0.f);
        *(float4*)(out + (size_t)w * 96 + d) = o;
    }
}

__global__ void k_spmm_out64_norm(const __half* __restrict__ feat, const int* __restrict__ rowptr,
                                  const int* __restrict__ col, const float* __restrict__ rs_src,
                                  const float* __restrict__ raw, const float* __restrict__ rs_in,
                                  const float* __restrict__ b1, const float* __restrict__ b2,
                                  float* __restrict__ out, float* __restrict__ invn, int n_rows) {
    int w = (blockIdx.x * blockDim.x + threadIdx.x) >> 5;
    int lane = threadIdx.x & 31;
    if (w >= n_rows) return;
    int s = rowptr[w], e = rowptr[w + 1];
    bool act = lane < 16;
    int d = lane * 4;
    float4 a0 = make_float4(0.f, 0.f, 0.f, 0.f);
    float4 a1 = make_float4(0.f, 0.f, 0.f, 0.f);
    int i = s;
    for (; i + 3 < e; i += 4) {
        int c0 = col[i], c1 = col[i + 1], c2 = col[i + 2], c3 = col[i + 3];
        float s0 = rs_src[c0], s1 = rs_src[c1], s2 = rs_src[c2], s3 = rs_src[c3];
        if (act) {
            uint2 q0 = *(const uint2*)(feat + (size_t)c0 * 64 + d);
            uint2 q1 = *(const uint2*)(feat + (size_t)c1 * 64 + d);
            uint2 q2 = *(const uint2*)(feat + (size_t)c2 * 64 + d);
            uint2 q3 = *(const uint2*)(feat + (size_t)c3 * 64 + d);
            float2 f;
            f = __half22float2(*(__half2*)&q0.x); a0.x += f.x * s0; a0.y += f.y * s0;
            f = __half22float2(*(__half2*)&q0.y); a0.z += f.x * s0; a0.w += f.y * s0;
            f = __half22float2(*(__half2*)&q1.x); a1.x += f.x * s1; a1.y += f.y * s1;
            f = __half22float2(*(__half2*)&q1.y); a1.z += f.x * s1; a1.w += f.y * s1;
            f = __half22float2(*(__half2*)&q2.x); a0.x += f.x * s2; a0.y += f.y * s2;
            f = __half22float2(*(__half2*)&q2.y); a0.z += f.x * s2; a0.w += f.y * s2;
            f = __half22float2(*(__half2*)&q3.x); a1.x += f.x * s3; a1.y += f.y * s3;
            f = __half22float2(*(__half2*)&q3.y); a1.z += f.x * s3; a1.w += f.y * s3;
        }
    }
    for (; i < e; i++) {
        int c0 = col[i];
        float s0 = rs_src[c0];
        if (act) {
            uint2 q0 = *(const uint2*)(feat + (size_t)c0 * 64 + d);
            float2 f;
            f = __half22float2(*(__half2*)&q0.x); a0.x += f.x * s0; a0.y += f.y * s0;
            f = __half22float2(*(__half2*)&q0.y); a0.z += f.x * s0; a0.w += f.y * s0;
        }
    }
    float sq = 0.f;
    if (act) {
        float sc = rs_in[w];
        float4 r4 = *(const float4*)(raw + (size_t)w * 64 + d);
        float4 o;
        o.x = fmaxf(r4.x + b1[d + 0] + b2[d + 0] + (a0.x + a1.x) * sc, 0.f);
        o.y = fmaxf(r4.y + b1[d + 1] + b2[d + 1] + (a0.y + a1.y) * sc, 0.f);
        o.z = fmaxf(r4.z + b1[d + 2] + b2[d + 2] + (a0.z + a1.z) * sc, 0.f);
        o.w = fmaxf(r4.w + b1[d + 3] + b2[d + 3] + (a0.w + a1.w) * sc, 0.f);
        *(float4*)(out + (size_t)w * 64 + d) = o;
        sq = o.x * o.x + o.y * o.y + o.z * o.z + o.w * o.w;
    }
    #pragma unroll
    for (int off = 16; off; off >>= 1) sq += __shfl_xor_sync(0xffffffffu, sq, off);
    if (lane == 0) invn[w] = 1.0f / fmaxf(sqrtf(sq), 1e-12f);
}

// ---------------- score (pos+neg in one launch) ----------------
__global__ void k_score_all(const float* __restrict__ hu, const float* __restrict__ hr,
                            const float* __restrict__ invn_u, const float* __restrict__ invn_r,
                            const int* __restrict__ pos_u, const int* __restrict__ pos_r,
                            const int* __restrict__ neg_u, const int* __restrict__ neg_r,
                            float* __restrict__ out) {
    int w = (blockIdx.x * blockDim.x + threadIdx.x) >> 5;
    int lane = threadIdx.x & 31;
    if (w >= 2 * NEP) return;
    int u, r;
    if (w < NEP) { u = pos_u[w]; r = pos_r[w]; }
    else         { u = neg_u[w - NEP]; r = neg_r[w - NEP]; }
    const float* a = hu + (size_t)u * D_OUT;
    const float* b = hr + (size_t)r * D_OUT;
    float s = a[lane] * b[lane] + a[lane + 32] * b[lane + 32];
    #pragma unroll
    for (int off = 16; off; off >>= 1) s += __shfl_xor_sync(0xffffffffu, s, off);
    if (lane == 0) out[w] = s * invn_u[u] * invn_r[r];
}

// ---------------- host ----------------
static inline void* sym(const void* s) {
    void* p = nullptr;
    cudaGetSymbolAddress(&p, s);
    return p;
}

extern "C" void kernel_launch(void* const* d_in, const int* in_sizes, int n_in,
                              void* d_out, int out_size) {
    const float* user_feat = (const float*)d_in[0];
    const float* repo_feat = (const float*)d_in[1];
    const float* W_ue = (const float*)d_in[2];   const float* b_ue = (const float*)d_in[3];
    const float* W_re = (const float*)d_in[4];   const float* b_re = (const float*)d_in[5];
    const float* W_hid_ur = (const float*)d_in[6];  const float* b_hid_ur = (const float*)d_in[7];
    const float* W_hid_ru = (const float*)d_in[8];  const float* b_hid_ru = (const float*)d_in[9];
    const float* W_out_ur = (const float*)d_in[10]; const float* b_out_ur = (const float*)d_in[11];
    const float* W_out_ru = (const float*)d_in[12]; const float* b_out_ru = (const float*)d_in[13];
    const float* W_hcu = (const float*)d_in[14]; const float* b_hcu = (const float*)d_in[15];
    const float* W_hcr = (const float*)d_in[16]; const float* b_hcr = (const float*)d_in[17];
    const float* W_ocu = (const float*)d_in[18]; const float* b_ocu = (const float*)d_in[19];
    const float* W_ocr = (const float*)d_in[20]; const float* b_ocr = (const float*)d_in[21];
    const int* e_ur_src = (const int*)d_in[22];
    const int* e_ur_dst = (const int*)d_in[23];
    const int* e_ru_src = (const int*)d_in[24];
    const int* e_ru_dst = (const int*)d_in[25];
    const int* pos_u = (const int*)d_in[26];
    const int* pos_r = (const int*)d_in[27];
    const int* neg_u = (const int*)d_in[28];
    const int* neg_r = (const int*)d_in[29];
    float* out = (float*)d_out;

    __half* feat_u = (__half*)sym(g_feat_u);
    __half* feat_r = (__half*)sym(g_feat_r);
    float*  raw_u  = (float*)sym(g_raw_u);
    float*  raw_r  = (float*)sym(g_raw_r);
    float*  out_user = (float*)sym(g_out_user);
    float*  out_repo = (float*)sym(g_out_repo);
    float*  new_user = (float*)sym(g_new_user);
    float*  new_repo = (float*)sym(g_new_repo);
    int* cnt_u_out = (int*)sym(g_cnt_u_out);
    int* cnt_u_in  = (int*)sym(g_cnt_u_in);
    int* cnt_r_out = (int*)sym(g_cnt_r_out);
    int* cnt_r_in  = (int*)sym(g_cnt_r_in);
    float* rs_u_out = (float*)sym(g_rs_u_out);
    float* rs_u_in  = (float*)sym(g_rs_u_in);
    float* rs_r_out = (float*)sym(g_rs_r_out);
    float* rs_r_in  = (float*)sym(g_rs_r_in);
    int* rowptr_ur = (int*)sym(g_rowptr_ur);
    int* rowptr_ru = (int*)sym(g_rowptr_ru);
    int* cursor_ur = (int*)sym(g_cursor_ur);
    int* cursor_ru = (int*)sym(g_cursor_ru);
    int* col_ur = (int*)sym(g_col_ur);
    int* col_ru = (int*)sym(g_col_ru);
    int* part   = (int*)sym(g_part);
    float* invn_u = (float*)sym(g_invn_u);
    float* invn_r = (float*)sym(g_invn_r);
    float* WC_u1 = (float*)sym(g_WC_u1);
    float* WC_r1 = (float*)sym(g_WC_r1);
    float* bc_u1 = (float*)sym(g_bc_u1);
    float* bc_r1 = (float*)sym(g_bc_r1);
    float* wc_u2 = (float*)sym(g_wc_u2);
    float* wc_r2 = (float*)sym(g_wc_r2);

    const int T = 256;
    auto blocks = [](long n, int t) { return (int)((n + t - 1) / t); };

    cudaMemsetAsync(cnt_u_out, 0, N_USER * sizeof(int), 0);
    cudaMemsetAsync(cnt_u_in,  0, N_USER * sizeof(int), 0);
    cudaMemsetAsync(cnt_r_out, 0, N_REPO * sizeof(int), 0);
    cudaMemsetAsync(cnt_r_in,  0, N_REPO * sizeof(int), 0);

    k_pack2<<<blocks(4 * 6144, T), T>>>(W_out_ur, W_ocu, W_out_ru, W_ocr);
    k_fold<<<blocks(2L * D_IN * 192 + 384, T), T>>>(W_ue, b_ue, W_hid_ur, W_hcu,
                                                    W_re, b_re, W_hid_ru, W_hcr);
    k_count_all<<<blocks(2L * NE, T), T>>>(e_ur_src, e_ur_dst, e_ru_src, e_ru_dst);

    dim3 tb(128);
    auto grid = [](int M, int N) { return dim3(N / BN, (M + BM - 1) / BM); };

    // layer-1 fused GEMMs: X @ WC + bc -> [feat fp16 | raw fp32]
    const int MR_HALF = 50048;  // 391 * 128
    k_gemm_tc<<<grid(MR_HALF, 192), tb>>>(repo_feat, WC_r1,
        feat_r, D_HID, raw_r, D_HID, D_HID, MR_HALF, 192, D_IN, bc_r1);
    k_gemm_tc<<<grid(N_REPO - MR_HALF, 192), tb>>>(repo_feat + (size_t)MR_HALF * D_IN, WC_r1,
        feat_r + (size_t)MR_HALF * D_HID, D_HID, raw_r + (size_t)MR_HALF * D_HID, D_HID, D_HID,
        N_REPO - MR_HALF, 192, D_IN, bc_r1);
    k_gemm_tc<<<grid(N_USER, 192), tb>>>(user_feat, WC_u1,
        feat_u, D_HID, raw_u, D_HID, D_HID, N_USER, 192, D_IN, bc_u1);

    // graph structure
    k_rsqrt_all<<<blocks(2L * (N_USER + N_REPO), T), T>>>();
    int nb_r = (N_REPO + 1023) / 1024;
    int nb_u = (N_USER + 1023) / 1024;
    k_scan_block<<<nb_r, 1024>>>(cnt_r_in, rowptr_ur, part, N_REPO);
    k_scan_part<<<1, 128>>>(part, nb_r);
    k_scan_add<<<blocks(N_REPO, T), T>>>(rowptr_ur, cursor_ur, part, N_REPO);
    k_scan_block<<<nb_u, 1024>>>(cnt_u_in, rowptr_ru, part, N_USER);
    k_scan_part<<<1, 128>>>(part, nb_u);
    k_scan_add<<<blocks(N_USER, T), T>>>(rowptr_ru, cursor_ru, part, N_USER);
    k_fill_all<<<blocks(2L * NE, T), T>>>(e_ur_src, e_ur_dst, e_ru_src, e_ru_dst);

    // layer-1 SpMM + residual
    k_spmm_out96<<<blocks(N_USER * 32L, T), T>>>(feat_r, rowptr_ru, col_ru, rs_r_out,
                                                 raw_u, rs_u_in, b_hcu, b_hid_ru,
                                                 out_user, N_USER);
    k_spmm_out96<<<blocks(N_REPO * 32L, T), T>>>(feat_u, rowptr_ur, col_ur, rs_u_out,
                                                 raw_r, rs_r_in, b_hcr, b_hid_ur,
                                                 out_repo, N_REPO);

    // layer-2 GEMMs
    k_gemm_tc<<<grid(N_REPO, 128), tb>>>(out_repo, wc_r2,
        feat_r, D_OUT, raw_r, D_OUT, D_OUT, N_REPO, 128, D_HID, nullptr);
    k_gemm_tc<<<grid(N_USER, 128), tb>>>(out_user, wc_u2,
        feat_u, D_OUT, raw_u, D_OUT, D_OUT, N_USER, 128, D_HID, nullptr);

    // layer-2 SpMM + residual + norm
    k_spmm_out64_norm<<<blocks(N_USER * 32L, T), T>>>(feat_r, rowptr_ru, col_ru, rs_r_out,
                                                      raw_u, rs_u_in, b_ocu, b_out_ru,
                                                      new_user, invn_u, N_USER);
    k_spmm_out64_norm<<<blocks(N_REPO * 32L, T), T>>>(feat_u, rowptr_ur, col_ur, rs_u_out,
                                                      raw_r, rs_r_in, b_ocr, b_out_ur,
                                                      new_repo, invn_r, N_REPO);

    // cosine scores
    k_score_all<<<blocks(2L * NEP * 32, T), T>>>(new_user, new_repo, invn_u, invn_r,
                                                 pos_u, pos_r, neg_u, neg_r, out);
}

// round 7
// speedup vs baseline: 3.2733x; 1.2099x over previous
#include <cuda_runtime.h>
#include <cuda_fp16.h>
#include <math.h>

// ---------------- problem constants ----------------
#define N_USER 50000
#define N_REPO 100000
#define NE     1000000
#define NEP    200000
#define D_IN   256
#define D_EMB  125
#define D_HID  96
#define D_OUT  64

// ---------------- scratch (device globals) ----------------
__device__ __align__(16) __half g_a_user[N_USER * D_IN];   // fp16 input feats
__device__ __align__(16) __half g_a_repo[N_REPO * D_IN];
__device__ __align__(16) __half g_feat_u[N_USER * D_HID];  // fp16 messages (reused @64 L2)
__device__ __align__(16) __half g_feat_r[N_REPO * D_HID];
__device__ float  g_raw_u [N_USER * D_HID];
__device__ float  g_raw_r [N_REPO * D_HID];
__device__ __align__(16) __half g_out_user[N_USER * D_HID]; // fp16 layer-1 output (= layer-2 A)
__device__ __align__(16) __half g_out_repo[N_REPO * D_HID];
__device__ float  g_new_user[N_USER * D_OUT];
__device__ float  g_new_repo[N_REPO * D_OUT];

__device__ int   g_cnt_u_out[N_USER];
__device__ int   g_cnt_u_in [N_USER];
__device__ int   g_cnt_r_out[N_REPO];
__device__ int   g_cnt_r_in [N_REPO];
__device__ float g_rs_u_out[N_USER], g_rs_u_in[N_USER];
__device__ float g_rs_r_out[N_REPO], g_rs_r_in[N_REPO];

__device__ int g_rowptr_ur[N_REPO + 1];
__device__ int g_rowptr_ru[N_USER + 1];
__device__ int g_cursor_ur[N_REPO];
__device__ int g_cursor_ru[N_USER];
__device__ int g_col_ur[NE];
__device__ int g_col_ru[NE];
__device__ int g_part[128];

__device__ float g_invn_u[N_USER];
__device__ float g_invn_r[N_REPO];

// folded layer-1 weights TRANSPOSED fp16: WCt[n][k], n<192, k<256
__device__ __align__(16) __half g_WCt_u1[192 * D_IN];
__device__ __align__(16) __half g_WCt_r1[192 * D_IN];
__device__ float g_bc_u1[192];
__device__ float g_bc_r1[192];
// packed layer-2 weights TRANSPOSED fp16: [n<128][k<96]
__device__ __align__(16) __half g_wc2t_u[128 * D_HID];
__device__ __align__(16) __half g_wc2t_r[128 * D_HID];

// ---------------- preprocessing kernels ----------------
__global__ void k_pack2(const float* __restrict__ W_out_ur, const float* __restrict__ W_ocu,
                        const float* __restrict__ W_out_ru, const float* __restrict__ W_ocr) {
    int i = blockIdx.x * blockDim.x + threadIdx.x;   // 2 * 128 * 96
    if (i >= 2 * 128 * 96) return;
    int half_sel = i / (128 * 96);
    int j = i - half_sel * (128 * 96);
    int n = j / 96, k = j % 96;
    const float* Wa = half_sel ? W_out_ru : W_out_ur;
    const float* Wb = half_sel ? W_ocr    : W_ocu;
    float v = (n < 64) ? Wa[k * 64 + n] : Wb[k * 64 + (n - 64)];
    __half* dst = half_sel ? g_wc2t_r : g_wc2t_u;
    dst[n * 96 + k] = __float2half_rn(v);
}

// fold: WCt[n][m] = sum_k W_e[m][k] * Wx[k][n'];  bc[n] = sum_k b_e[k] * Wx[k][n']
__global__ void k_fold(const float* __restrict__ W_ue, const float* __restrict__ b_ue,
                       const float* __restrict__ W_hid_ur, const float* __restrict__ W_hcu,
                       const float* __restrict__ W_re, const float* __restrict__ b_re,
                       const float* __restrict__ W_hid_ru, const float* __restrict__ W_hcr) {
    const int PER = D_IN * 192;
    int i = blockIdx.x * blockDim.x + threadIdx.x;
    if (i < 2 * PER) {
        const float* We = (i < PER) ? W_ue : W_re;
        const float* Wm = (i < PER) ? W_hid_ur : W_hid_ru;
        const float* Wr = (i < PER) ? W_hcu : W_hcr;
        __half* WCt = (i < PER) ? g_WCt_u1 : g_WCt_r1;
        int j = (i < PER) ? i : i - PER;
        int n = j / D_IN, m = j % D_IN;
        const float* Wx = (n < 96) ? (Wm + n) : (Wr + n - 96);
        float a = 0.f;
        #pragma unroll 5
        for (int k = 0; k < D_EMB; k++) a += We[m * D_EMB + k] * Wx[k * 96];
        WCt[n * D_IN + m] = __float2half_rn(a);
        return;
    }
    i -= 2 * PER;
    if (i < 384) {
        const float* be = (i < 192) ? b_ue : b_re;
        const float* Wm = (i < 192) ? W_hid_ur : W_hid_ru;
        const float* Wr = (i < 192) ? W_hcu : W_hcr;
        float* bc = (i < 192) ? g_bc_u1 : g_bc_r1;
        int n = i % 192;
        const float* Wx = (n < 96) ? (Wm + n) : (Wr + n - 96);
        float a = 0.f;
        for (int k = 0; k < D_EMB; k++) a += be[k] * Wx[k * 96];
        bc[n] = a;
    }
}

// convert input features fp32 -> fp16 (vectorized)
#define NU4 (N_USER * (D_IN / 4))
#define NR4 (N_REPO * (D_IN / 4))
__global__ void k_tofp16(const float* __restrict__ u, const float* __restrict__ r) {
    long i = blockIdx.x * (long)blockDim.x + threadIdx.x;
    if (i < NU4) {
        float4 v = ((const float4*)u)[i];
        union { __half2 h[2]; uint2 q; } cv;
        cv.h[0] = __floats2half2_rn(v.x, v.y);
        cv.h[1] = __floats2half2_rn(v.z, v.w);
        ((uint2*)g_a_user)[i] = cv.q;
    } else if (i < NU4 + NR4) {
        long j = i - NU4;
        float4 v = ((const float4*)r)[j];
        union { __half2 h[2]; uint2 q; } cv;
        cv.h[0] = __floats2half2_rn(v.x, v.y);
        cv.h[1] = __floats2half2_rn(v.z, v.w);
        ((uint2*)g_a_repo)[j] = cv.q;
    }
}

__global__ void k_count_all(const int* __restrict__ ur_src, const int* __restrict__ ur_dst,
                            const int* __restrict__ ru_src, const int* __restrict__ ru_dst) {
    int i = blockIdx.x * blockDim.x + threadIdx.x;
    if (i < NE) {
        atomicAdd(&g_cnt_u_out[ur_src[i]], 1);
        atomicAdd(&g_cnt_r_in[ur_dst[i]], 1);
    } else if (i < 2 * NE) {
        int j = i - NE;
        atomicAdd(&g_cnt_r_out[ru_src[j]], 1);
        atomicAdd(&g_cnt_u_in[ru_dst[j]], 1);
    }
}

__global__ void k_rsqrt_all() {
    int i = blockIdx.x * blockDim.x + threadIdx.x;
    if (i < N_USER) { g_rs_u_out[i] = rsqrtf(fmaxf((float)g_cnt_u_out[i], 1.f)); return; }
    i -= N_USER;
    if (i < N_USER) { g_rs_u_in[i] = rsqrtf(fmaxf((float)g_cnt_u_in[i], 1.f)); return; }
    i -= N_USER;
    if (i < N_REPO) { g_rs_r_out[i] = rsqrtf(fmaxf((float)g_cnt_r_out[i], 1.f)); return; }
    i -= N_REPO;
    if (i < N_REPO) { g_rs_r_in[i] = rsqrtf(fmaxf((float)g_cnt_r_in[i], 1.f)); return; }
}

__global__ void k_scan_block(const int* __restrict__ cnt, int* rowptr, int* partial, int n) {
    __shared__ int sh[1024];
    int b = blockIdx.x, t = threadIdx.x;
    int i = b * 1024 + t;
    int v = (i < n) ? cnt[i] : 0;
    sh[t] = v;
    __syncthreads();
    for (int off = 1; off < 1024; off <<= 1) {
        int x = (t >= off) ? sh[t - off] : 0;
        __syncthreads();
        sh[t] += x;
        __syncthreads();
    }
    if (i < n) rowptr[i + 1] = sh[t];
    if (t == 1023) partial[b] = sh[1023];
}

__global__ void k_scan_part(int* partial, int nb) {
    __shared__ int sh[128];
    int t = threadIdx.x;
    int v = (t < nb) ? partial[t] : 0;
    sh[t] = v;
    __syncthreads();
    for (int off = 1; off < 128; off <<= 1) {
        int x = (t >= off) ? sh[t - off] : 0;
        __syncthreads();
        sh[t] += x;
        __syncthreads();
    }
    if (t < nb) partial[t] = sh[t] - v;
}

__global__ void k_scan_add(int* rowptr, int* cursor, const int* __restrict__ partial, int n) {
    int i = blockIdx.x * blockDim.x + threadIdx.x;
    if (i == 0) { rowptr[0] = 0; cursor[0] = 0; }
    if (i < n) {
        int v = rowptr[i + 1] + partial[i >> 10];
        rowptr[i + 1] = v;
        if (i + 1 < n) cursor[i + 1] = v;
    }
}

__global__ void k_fill_all(const int* __restrict__ ur_src, const int* __restrict__ ur_dst,
                           const int* __restrict__ ru_src, const int* __restrict__ ru_dst) {
    int i = blockIdx.x * blockDim.x + threadIdx.x;
    if (i < NE) {
        int p = atomicAdd(&g_cursor_ur[ur_dst[i]], 1);
        g_col_ur[p] = ur_src[i];
    } else if (i < 2 * NE) {
        int j = i - NE;
        int p = atomicAdd(&g_cursor_ru[ru_dst[j]], 1);
        g_col_ru[p] = ru_src[j];
    }
}

// ---------------- fp16 GEMM: cp.async double-buffer + ldmatrix + m16n8k16 ----------------
// acc = A @ Wt^T + bias;  n < nsplit -> C1h (fp16);  n >= nsplit -> C2 (fp32)
#define BM 128
#define BN 64
#define BK 32
#define APITCH 40   // halves per A smem row (80 B)
#define BPITCH 40
#define AHALVES (BM * APITCH)
#define BHALVES (BN * BPITCH)

__device__ __forceinline__ void mma_f16(float c[4],
                                        unsigned a0, unsigned a1, unsigned a2, unsigned a3,
                                        unsigned b0, unsigned b1) {
    asm volatile(
        "mma.sync.aligned.m16n8k16.row.col.f32.f16.f16.f32 "
        "{%0,%1,%2,%3}, {%4,%5,%6,%7}, {%8,%9}, {%0,%1,%2,%3};"
        : "+f"(c[0]), "+f"(c[1]), "+f"(c[2]), "+f"(c[3])
        : "r"(a0), "r"(a1), "r"(a2), "r"(a3), "r"(b0), "r"(b1));
}

__device__ __forceinline__ void ldsm_x4(unsigned& r0, unsigned& r1, unsigned& r2, unsigned& r3,
                                        unsigned addr) {
    asm volatile("ldmatrix.sync.aligned.m8n8.x4.shared.b16 {%0,%1,%2,%3}, [%4];"
                 : "=r"(r0), "=r"(r1), "=r"(r2), "=r"(r3) : "r"(addr));
}

__device__ __forceinline__ void cp_async16(unsigned dst, const void* src) {
    asm volatile("cp.async.cg.shared.global [%0], [%1], 16;" :: "r"(dst), "l"(src));
}
__device__ __forceinline__ void cp_commit() {
    asm volatile("cp.async.commit_group;");
}
__device__ __forceinline__ void cp_wait_all() {
    asm volatile("cp.async.wait_group 0;");
}

__global__ __launch_bounds__(128) void k_gemm_f16(
    const __half* __restrict__ A, const __half* __restrict__ Wt,  // Wt: [N][K] fp16
    __half* __restrict__ C1h, int ld1,
    float* __restrict__ C2, int ld2, int nsplit,
    int M, int N, int K,
    const float* __restrict__ bias)
{
    __shared__ __half As_s[2][AHALVES];
    __shared__ __half Bs_s[2][BHALVES];

    const int tid = threadIdx.x;
    const int warp = tid >> 5, lane = tid & 31;
    const int wm = (warp >> 1) * 64;
    const int wn = (warp & 1) * 32;
    const int m0 = blockIdx.y * BM;
    const int n0 = blockIdx.x * BN;
    const int r = lane >> 2, kc = lane & 3;

    float acc[4][4][4];
    #pragma unroll
    for (int a = 0; a < 4; a++)
        #pragma unroll
        for (int b = 0; b < 4; b++)
            #pragma unroll
            for (int c = 0; c < 4; c++) acc[a][b][c] = 0.f;

    const unsigned as0 = (unsigned)__cvta_generic_to_shared(&As_s[0][0]);
    const unsigned bs0 = (unsigned)__cvta_generic_to_shared(&Bs_s[0][0]);

    // ldmatrix per-thread base offsets (within one buffer)
    const int q = lane >> 3, lr = lane & 7;
    const unsigned a_lm = ((wm + (q & 1) * 8 + lr) * APITCH + (q >> 1) * 8) << 1;
    const unsigned b_lm = ((wn + (q >> 1) * 8 + lr) * BPITCH + (q & 1) * 8) << 1;

    // staging decomposition (16B chunks of 8 halves)
    const int a_row = tid >> 2, a_c = tid & 3;          // +32 rows per rep, 4 reps
    const int b_row = tid >> 2, b_c = tid & 3;          // +32 rows per rep, 2 reps

    const int T = K / BK;

    // ---- prologue: stage tile 0 into buffer 0 ----
    {
        const int k0 = 0;
        #pragma unroll
        for (int j = 0; j < 4; j++) {
            int row = a_row + j * 32;
            int m = m0 + row;
            if (m < M)
                cp_async16(as0 + ((row * APITCH + a_c * 8) << 1),
                           A + (size_t)m * K + k0 + a_c * 8);
        }
        #pragma unroll
        for (int j = 0; j < 2; j++) {
            int row = b_row + j * 32;
            cp_async16(bs0 + ((row * BPITCH + b_c * 8) << 1),
                       Wt + (size_t)(n0 + row) * K + k0 + b_c * 8);
        }
        cp_commit();
    }

    for (int t = 0; t < T; t++) {
        cp_wait_all();
        __syncthreads();

        // stage next tile into other buffer (overlaps with compute below)
        if (t + 1 < T) {
            const int k0 = (t + 1) * BK;
            const unsigned ab = as0 + ((t + 1) & 1) * (AHALVES * 2);
            const unsigned bb = bs0 + ((t + 1) & 1) * (BHALVES * 2);
            #pragma unroll
            for (int j = 0; j < 4; j++) {
                int row = a_row + j * 32;
                int m = m0 + row;
                if (m < M)
                    cp_async16(ab + ((row * APITCH + a_c * 8) << 1),
                               A + (size_t)m * K + k0 + a_c * 8);
            }
            #pragma unroll
            for (int j = 0; j < 2; j++) {
                int row = b_row + j * 32;
                cp_async16(bb + ((row * BPITCH + b_c * 8) << 1),
                           Wt + (size_t)(n0 + row) * K + k0 + b_c * 8);
            }
            cp_commit();
        }

        // compute on buffer t&1
        const unsigned abuf = as0 + (t & 1) * (AHALVES * 2) + a_lm;
        const unsigned bbuf = bs0 + (t & 1) * (BHALVES * 2) + b_lm;
        #pragma unroll
        for (int g = 0; g < 2; g++) {
            unsigned af[4][4], bf[4][2];
            #pragma unroll
            for (int mt = 0; mt < 4; mt++)
                ldsm_x4(af[mt][0], af[mt][1], af[mt][2], af[mt][3],
                        abuf + ((mt * 16 * APITCH + g * 16) << 1));
            #pragma unroll
            for (int np = 0; np < 2; np++) {
                unsigned r0, r1, r2, r3;
                ldsm_x4(r0, r1, r2, r3, bbuf + ((np * 16 * BPITCH + g * 16) << 1));
                bf[2 * np][0] = r0;  bf[2 * np][1] = r1;
                bf[2 * np + 1][0] = r2;  bf[2 * np + 1][1] = r3;
            }
            #pragma unroll
            for (int mt = 0; mt < 4; mt++)
                #pragma unroll
                for (int nt = 0; nt < 4; nt++)
                    mma_f16(acc[mt][nt], af[mt][0], af[mt][1], af[mt][2], af[mt][3],
                            bf[nt][0], bf[nt][1]);
        }
        __syncthreads();
    }

    // ---- epilogue ----
    #pragma unroll
    for (int mt = 0; mt < 4; mt++) {
        #pragma unroll
        for (int i2 = 0; i2 < 2; i2++) {
            int m = m0 + wm + mt * 16 + r + i2 * 8;
            if (m >= M) continue;
            #pragma unroll
            for (int nt = 0; nt < 4; nt++) {
                int n = n0 + wn + nt * 8 + kc * 2;
                float v0 = acc[mt][nt][i2 * 2 + 0];
                float v1 = acc[mt][nt][i2 * 2 + 1];
                if (bias) { v0 += bias[n]; v1 += bias[n + 1]; }
                if (n < nsplit) {
                    __half2 h = __floats2half2_rn(v0, v1);
                    *(__half2*)(C1h + (size_t)m * ld1 + n) = h;
                } else {
                    *(float2*)(C2 + (size_t)m * ld2 + n - nsplit) = make_float2(v0, v1);
                }
            }
        }
    }
}

// ---------------- fused SpMM + residual epilogue (layer 1: fp16 out) ----------------
__global__ void k_spmm_out96(const __half* __restrict__ feat, const int* __restrict__ rowptr,
                             const int* __restrict__ col, const float* __restrict__ rs_src,
                             const float* __restrict__ raw, const float* __restrict__ rs_in,
                             const float* __restrict__ b1, const float* __restrict__ b2,
                             __half* __restrict__ out, int n_rows) {
    int w = (blockIdx.x * blockDim.x + threadIdx.x) >> 5;
    int lane = threadIdx.x & 31;
    if (w >= n_rows) return;
    int s = rowptr[w], e = rowptr[w + 1];
    bool act = lane < 24;
    int d = lane * 4;
    float4 a0 = make_float4(0.f, 0.f, 0.f, 0.f);
    float4 a1 = make_float4(0.f, 0.f, 0.f, 0.f);
    int i = s;
    for (; i + 3 < e; i += 4) {
        int c0 = col[i], c1 = col[i + 1], c2 = col[i + 2], c3 = col[i + 3];
        float s0 = rs_src[c0], s1 = rs_src[c1], s2 = rs_src[c2], s3 = rs_src[c3];
        if (act) {
            uint2 q0 = *(const uint2*)(feat + (size_t)c0 * 96 + d);
            uint2 q1 = *(const uint2*)(feat + (size_t)c1 * 96 + d);
            uint2 q2 = *(const uint2*)(feat + (size_t)c2 * 96 + d);
            uint2 q3 = *(const uint2*)(feat + (size_t)c3 * 96 + d);
            float2 f;
            f = __half22float2(*(__half2*)&q0.x); a0.x += f.x * s0; a0.y += f.y * s0;
            f = __half22float2(*(__half2*)&q0.y); a0.z += f.x * s0; a0.w += f.y * s0;
            f = __half22float2(*(__half2*)&q1.x); a1.x += f.x * s1; a1.y += f.y * s1;
            f = __half22float2(*(__half2*)&q1.y); a1.z += f.x * s1; a1.w += f.y * s1;
            f = __half22float2(*(__half2*)&q2.x); a0.x += f.x * s2; a0.y += f.y * s2;
            f = __half22float2(*(__half2*)&q2.y); a0.z += f.x * s2; a0.w += f.y * s2;
            f = __half22float2(*(__half2*)&q3.x); a1.x += f.x * s3; a1.y += f.y * s3;
            f = __half22float2(*(__half2*)&q3.y); a1.z += f.x * s3; a1.w += f.y * s3;
        }
    }
    for (; i < e; i++) {
        int c0 = col[i];
        float s0 = rs_src[c0];
        if (act) {
            uint2 q0 = *(const uint2*)(feat + (size_t)c0 * 96 + d);
            float2 f;
            f = __half22float2(*(__half2*)&q0.x); a0.x += f.x * s0; a0.y += f.y * s0;
            f = __half22float2(*(__half2*)&q0.y); a0.z += f.x * s0; a0.w += f.y * s0;
        }
    }
    if (act) {
        float sc = rs_in[w];
        float4 r4 = *(const float4*)(raw + (size_t)w * 96 + d);
        float ox = fmaxf(r4.x + b1[d + 0] + b2[d + 0] + (a0.x + a1.x) * sc, 0.f);
        float oy = fmaxf(r4.y + b1[d + 1] + b2[d + 1] + (a0.y + a1.y) * sc, 0.f);
        float oz = fmaxf(r4.z + b1[d + 2] + b2[d + 2] + (a0.z + a1.z) * sc, 0.f);
        float ow = fmaxf(r4.w + b1[d + 3] + b2[d + 3] + (a0.w + a1.w) * sc, 0.f);
        union { __half2 h[2]; uint2 q; } cv;
        cv.h[0] = __floats2half2_rn(ox, oy);
        cv.h[1] = __floats2half2_rn(oz, ow);
        *(uint2*)(out + (size_t)w * 96 + d) = cv.q;
    }
}

// layer 2 (D=64): fp32 out + fused inverse-norm
__global__ void k_spmm_out64_norm(const __half* __restrict__ feat, const int* __restrict__ rowptr,
                                  const int* __restrict__ col, const float* __restrict__ rs_src,
                                  const float* __restrict__ raw, const float* __restrict__ rs_in,
                                  const float* __restrict__ b1, const float* __restrict__ b2,
                                  float* __restrict__ out, float* __restrict__ invn, int n_rows) {
    int w = (blockIdx.x * blockDim.x + threadIdx.x) >> 5;
    int lane = threadIdx.x & 31;
    if (w >= n_rows) return;
    int s = rowptr[w], e = rowptr[w + 1];
    bool act = lane < 16;
    int d = lane * 4;
    float4 a0 = make_float4(0.f, 0.f, 0.f, 0.f);
    float4 a1 = make_float4(0.f, 0.f, 0.f, 0.f);
    int i = s;
    for (; i + 3 < e; i += 4) {
        int c0 = col[i], c1 = col[i + 1], c2 = col[i + 2], c3 = col[i + 3];
        float s0 = rs_src[c0], s1 = rs_src[c1], s2 = rs_src[c2], s3 = rs_src[c3];
        if (act) {
            uint2 q0 = *(const uint2*)(feat + (size_t)c0 * 64 + d);
            uint2 q1 = *(const uint2*)(feat + (size_t)c1 * 64 + d);
            uint2 q2 = *(const uint2*)(feat + (size_t)c2 * 64 + d);
            uint2 q3 = *(const uint2*)(feat + (size_t)c3 * 64 + d);
            float2 f;
            f = __half22float2(*(__half2*)&q0.x); a0.x += f.x * s0; a0.y += f.y * s0;
            f = __half22float2(*(__half2*)&q0.y); a0.z += f.x * s0; a0.w += f.y * s0;
            f = __half22float2(*(__half2*)&q1.x); a1.x += f.x * s1; a1.y += f.y * s1;
            f = __half22float2(*(__half2*)&q1.y); a1.z += f.x * s1; a1.w += f.y * s1;
            f = __half22float2(*(__half2*)&q2.x); a0.x += f.x * s2; a0.y += f.y * s2;
            f = __half22float2(*(__half2*)&q2.y); a0.z += f.x * s2; a0.w += f.y * s2;
            f = __half22float2(*(__half2*)&q3.x); a1.x += f.x * s3; a1.y += f.y * s3;
            f = __half22float2(*(__half2*)&q3.y); a1.z += f.x * s3; a1.w += f.y * s3;
        }
    }
    for (; i < e; i++) {
        int c0 = col[i];
        float s0 = rs_src[c0];
        if (act) {
            uint2 q0 = *(const uint2*)(feat + (size_t)c0 * 64 + d);
            float2 f;
            f = __half22float2(*(__half2*)&q0.x); a0.x += f.x * s0; a0.y += f.y * s0;
            f = __half22float2(*(__half2*)&q0.y); a0.z += f.x * s0; a0.w += f.y * s0;
        }
    }
    float sq = 0.f;
    if (act) {
        float sc = rs_in[w];
        float4 r4 = *(const float4*)(raw + (size_t)w * 64 + d);
        float4 o;
        o.x = fmaxf(r4.x + b1[d + 0] + b2[d + 0] + (a0.x + a1.x) * sc, 0.f);
        o.y = fmaxf(r4.y + b1[d + 1] + b2[d + 1] + (a0.y + a1.y) * sc, 0.f);
        o.z = fmaxf(r4.z + b1[d + 2] + b2[d + 2] + (a0.z + a1.z) * sc, 0.f);
        o.w = fmaxf(r4.w + b1[d + 3] + b2[d + 3] + (a0.w + a1.w) * sc, 0.f);
        *(float4*)(out + (size_t)w * 64 + d) = o;
        sq = o.x * o.x + o.y * o.y + o.z * o.z + o.w * o.w;
    }
    #pragma unroll
    for (int off = 16; off; off >>= 1) sq += __shfl_xor_sync(0xffffffffu, sq, off);
    if (lane == 0) invn[w] = 1.0f / fmaxf(sqrtf(sq), 1e-12f);
}

// ---------------- score (pos+neg in one launch) ----------------
__global__ void k_score_all(const float* __restrict__ hu, const float* __restrict__ hr,
                            const float* __restrict__ invn_u, const float* __restrict__ invn_r,
                            const int* __restrict__ pos_u, const int* __restrict__ pos_r,
                            const int* __restrict__ neg_u, const int* __restrict__ neg_r,
                            float* __restrict__ out) {
    int w = (blockIdx.x * blockDim.x + threadIdx.x) >> 5;
    int lane = threadIdx.x & 31;
    if (w >= 2 * NEP) return;
    int u, r;
    if (w < NEP) { u = pos_u[w]; r = pos_r[w]; }
    else         { u = neg_u[w - NEP]; r = neg_r[w - NEP]; }
    const float* a = hu + (size_t)u * D_OUT;
    const float* b = hr + (size_t)r * D_OUT;
    float s = a[lane] * b[lane] + a[lane + 32] * b[lane + 32];
    #pragma unroll
    for (int off = 16; off; off >>= 1) s += __shfl_xor_sync(0xffffffffu, s, off);
    if (lane == 0) out[w] = s * invn_u[u] * invn_r[r];
}

// ---------------- host ----------------
static inline void* sym(const void* s) {
    void* p = nullptr;
    cudaGetSymbolAddress(&p, s);
    return p;
}

extern "C" void kernel_launch(void* const* d_in, const int* in_sizes, int n_in,
                              void* d_out, int out_size) {
    const float* user_feat = (const float*)d_in[0];
    const float* repo_feat = (const float*)d_in[1];
    const float* W_ue = (const float*)d_in[2];   const float* b_ue = (const float*)d_in[3];
    const float* W_re = (const float*)d_in[4];   const float* b_re = (const float*)d_in[5];
    const float* W_hid_ur = (const float*)d_in[6];  const float* b_hid_ur = (const float*)d_in[7];
    const float* W_hid_ru = (const float*)d_in[8];  const float* b_hid_ru = (const float*)d_in[9];
    const float* W_out_ur = (const float*)d_in[10]; const float* b_out_ur = (const float*)d_in[11];
    const float* W_out_ru = (const float*)d_in[12]; const float* b_out_ru = (const float*)d_in[13];
    const float* W_hcu = (const float*)d_in[14]; const float* b_hcu = (const float*)d_in[15];
    const float* W_hcr = (const float*)d_in[16]; const float* b_hcr = (const float*)d_in[17];
    const float* W_ocu = (const float*)d_in[18]; const float* b_ocu = (const float*)d_in[19];
    const float* W_ocr = (const float*)d_in[20]; const float* b_ocr = (const float*)d_in[21];
    const int* e_ur_src = (const int*)d_in[22];
    const int* e_ur_dst = (const int*)d_in[23];
    const int* e_ru_src = (const int*)d_in[24];
    const int* e_ru_dst = (const int*)d_in[25];
    const int* pos_u = (const int*)d_in[26];
    const int* pos_r = (const int*)d_in[27];
    const int* neg_u = (const int*)d_in[28];
    const int* neg_r = (const int*)d_in[29];
    float* out = (float*)d_out;

    __half* a_user = (__half*)sym(g_a_user);
    __half* a_repo = (__half*)sym(g_a_repo);
    __half* feat_u = (__half*)sym(g_feat_u);
    __half* feat_r = (__half*)sym(g_feat_r);
    float*  raw_u  = (float*)sym(g_raw_u);
    float*  raw_r  = (float*)sym(g_raw_r);
    __half* out_user = (__half*)sym(g_out_user);
    __half* out_repo = (__half*)sym(g_out_repo);
    float*  new_user = (float*)sym(g_new_user);
    float*  new_repo = (float*)sym(g_new_repo);
    int* cnt_u_out = (int*)sym(g_cnt_u_out);
    int* cnt_u_in  = (int*)sym(g_cnt_u_in);
    int* cnt_r_out = (int*)sym(g_cnt_r_out);
    int* cnt_r_in  = (int*)sym(g_cnt_r_in);
    float* rs_u_out = (float*)sym(g_rs_u_out);
    float* rs_u_in  = (float*)sym(g_rs_u_in);
    float* rs_r_out = (float*)sym(g_rs_r_out);
    float* rs_r_in  = (float*)sym(g_rs_r_in);
    int* rowptr_ur = (int*)sym(g_rowptr_ur);
    int* rowptr_ru = (int*)sym(g_rowptr_ru);
    int* cursor_ur = (int*)sym(g_cursor_ur);
    int* cursor_ru = (int*)sym(g_cursor_ru);
    int* col_ur = (int*)sym(g_col_ur);
    int* col_ru = (int*)sym(g_col_ru);
    int* part   = (int*)sym(g_part);
    float* invn_u = (float*)sym(g_invn_u);
    float* invn_r = (float*)sym(g_invn_r);
    __half* WCt_u1 = (__half*)sym(g_WCt_u1);
    __half* WCt_r1 = (__half*)sym(g_WCt_r1);
    float* bc_u1 = (float*)sym(g_bc_u1);
    float* bc_r1 = (float*)sym(g_bc_r1);
    __half* wc2t_u = (__half*)sym(g_wc2t_u);
    __half* wc2t_r = (__half*)sym(g_wc2t_r);

    const int T = 256;
    auto blocks = [](long n, int t) { return (int)((n + t - 1) / t); };

    cudaMemsetAsync(cnt_u_out, 0, N_USER * sizeof(int), 0);
    cudaMemsetAsync(cnt_u_in,  0, N_USER * sizeof(int), 0);
    cudaMemsetAsync(cnt_r_out, 0, N_REPO * sizeof(int), 0);
    cudaMemsetAsync(cnt_r_in,  0, N_REPO * sizeof(int), 0);

    k_pack2<<<blocks(2 * 128 * 96, T), T>>>(W_out_ur, W_ocu, W_out_ru, W_ocr);
    k_fold<<<blocks(2L * D_IN * 192 + 384, T), T>>>(W_ue, b_ue, W_hid_ur, W_hcu,
                                                    W_re, b_re, W_hid_ru, W_hcr);
    k_count_all<<<blocks(2L * NE, T), T>>>(e_ur_src, e_ur_dst, e_ru_src, e_ru_dst);
    k_tofp16<<<blocks((long)NU4 + NR4, T), T>>>(user_feat, repo_feat);

    dim3 tb(128);
    auto grid = [](int M, int N) { return dim3(N / BN, (M + BM - 1) / BM); };

    // layer-1 fused GEMMs: Xh @ WCt^T + bc -> [feat fp16 | raw fp32]
    const int MR_HALF = 50048;  // 391 * 128
    k_gemm_f16<<<grid(MR_HALF, 192), tb>>>(a_repo, WCt_r1,
        feat_r, D_HID, raw_r, D_HID, D_HID, MR_HALF, 192, D_IN, bc_r1);
    k_gemm_f16<<<grid(N_REPO - MR_HALF, 192), tb>>>(a_repo + (size_t)MR_HALF * D_IN, WCt_r1,
        feat_r + (size_t)MR_HALF * D_HID, D_HID, raw_r + (size_t)MR_HALF * D_HID, D_HID, D_HID,
        N_REPO - MR_HALF, 192, D_IN, bc_r1);
    k_gemm_f16<<<grid(N_USER, 192), tb>>>(a_user, WCt_u1,
        feat_u, D_HID, raw_u, D_HID, D_HID, N_USER, 192, D_IN, bc_u1);

    // graph structure
    k_rsqrt_all<<<blocks(2L * (N_USER + N_REPO), T), T>>>();
    int nb_r = (N_REPO + 1023) / 1024;
    int nb_u = (N_USER + 1023) / 1024;
    k_scan_block<<<nb_r, 1024>>>(cnt_r_in, rowptr_ur, part, N_REPO);
    k_scan_part<<<1, 128>>>(part, nb_r);
    k_scan_add<<<blocks(N_REPO, T), T>>>(rowptr_ur, cursor_ur, part, N_REPO);
    k_scan_block<<<nb_u, 1024>>>(cnt_u_in, rowptr_ru, part, N_USER);
    k_scan_part<<<1, 128>>>(part, nb_u);
    k_scan_add<<<blocks(N_USER, T), T>>>(rowptr_ru, cursor_ru, part, N_USER);
    k_fill_all<<<blocks(2L * NE, T), T>>>(e_ur_src, e_ur_dst, e_ru_src, e_ru_dst);

    // layer-1 SpMM + residual -> fp16 out
    k_spmm_out96<<<blocks(N_USER * 32L, T), T>>>(feat_r, rowptr_ru, col_ru, rs_r_out,
                                                 raw_u, rs_u_in, b_hcu, b_hid_ru,
                                                 out_user, N_USER);
    k_spmm_out96<<<blocks(N_REPO * 32L, T), T>>>(feat_u, rowptr_ur, col_ur, rs_u_out,
                                                 raw_r, rs_r_in, b_hcr, b_hid_ur,
                                                 out_repo, N_REPO);

    // layer-2 GEMMs (K=96)
    k_gemm_f16<<<grid(N_REPO, 128), tb>>>(out_repo, wc2t_r,
        feat_r, D_OUT, raw_r, D_OUT, D_OUT, N_REPO, 128, D_HID, nullptr);
    k_gemm_f16<<<grid(N_USER, 128), tb>>>(out_user, wc2t_u,
        feat_u, D_OUT, raw_u, D_OUT, D_OUT, N_USER, 128, D_HID, nullptr);

    // layer-2 SpMM + residual + norm
    k_spmm_out64_norm<<<blocks(N_USER * 32L, T), T>>>(feat_r, rowptr_ru, col_ru, rs_r_out,
                                                      raw_u, rs_u_in, b_ocu, b_out_ru,
                                                      new_user, invn_u, N_USER);
    k_spmm_out64_norm<<<blocks(N_REPO * 32L, T), T>>>(feat_u, rowptr_ur, col_ur, rs_u_out,
                                                      raw_r, rs_r_in, b_ocr, b_out_ur,
                                                      new_repo, invn_r, N_REPO);

    // cosine scores
    k_score_all<<<blocks(2L * NEP * 32, T), T>>>(new_user, new_repo, invn_u, invn_r,
                                                 pos_u, pos_r, neg_u, neg_r, out);
}